// round 1
// baseline (speedup 1.0000x reference)
#include <cuda_runtime.h>
#include <math.h>

#define NN 4096
#define NF 1024
#define NH 8
#define ND 128
#define NC 64
#define HD (NH*ND)      // 1024
#define NW (NN/32)      // 128 mask words per row
#define LALPHA 0.2f
#define JC 8            // j-split chunks for output attention layer

// ---------------- scratch (static device globals; no allocs) ----------------
__device__ unsigned g_mask[(size_t)NN*NW];        // 2 MB packed adjacency
__device__ float g_Wh[(size_t)NN*HD];             // 16 MB  [n][h*128+d]
__device__ float g_f1[NH*NN];
__device__ float g_f2[NH*NN];
__device__ float g_hcat[(size_t)NN*HD];           // 16 MB  elu(h) concat
__device__ float g_Who[(size_t)NN*NC];            // 1 MB
__device__ float g_g1[NN];
__device__ float g_g2[NN];
__device__ float g_part[(size_t)JC*NN*NC];        // 8 MB partial numerators
__device__ float g_dpart[JC*NN];                  // partial denominators

__device__ __forceinline__ float lrelu(float s) { return s > 0.f ? s : LALPHA * s; }

// ---------------- K1: pack adj -> bitmask ----------------
__global__ void k_pack(const int* __restrict__ adj) {
    int row = blockIdx.x;
    int warp = threadIdx.x >> 5, lane = threadIdx.x & 31;
    const int* ar = adj + (size_t)row * NN;
    for (int w = warp; w < NW; w += 4) {
        unsigned b = __ballot_sync(0xffffffffu, ar[w * 32 + lane] > 0);
        if (lane == 0) g_mask[(size_t)row * NW + w] = b;
    }
}

// ---------------- K2: Wh = x @ W  (fused over heads; C layout = concat) ----
// grid (32 row-tiles, 8 heads), 256 thr, BM=128 BN=128(=D) BK=16, TM=TN=8
#define ASTR 132
__global__ __launch_bounds__(256, 2) void k_wh(const float* __restrict__ x,
                                               const float* __restrict__ W) {
    __shared__ float As[16][ASTR];
    __shared__ float Bs[16][128];
    int h = blockIdx.y;
    int i0 = blockIdx.x * 128;
    int t = threadIdx.x;
    int ty = t >> 4, tx = t & 15;
    const float* Wh_ = W + (size_t)h * NF * ND;
    float acc[8][8];
#pragma unroll
    for (int u = 0; u < 8; u++)
#pragma unroll
        for (int v = 0; v < 8; v++) acc[u][v] = 0.f;

    for (int f0 = 0; f0 < NF; f0 += 16) {
#pragma unroll
        for (int p = 0; p < 2; p++) {
            int idx = p * 256 + t;
            int row = idx >> 2, k4 = (idx & 3) * 4;
            float4 v = *(const float4*)(x + (size_t)(i0 + row) * NF + f0 + k4);
            As[k4 + 0][row] = v.x; As[k4 + 1][row] = v.y;
            As[k4 + 2][row] = v.z; As[k4 + 3][row] = v.w;
        }
#pragma unroll
        for (int p = 0; p < 2; p++) {
            int idx = p * 256 + t;
            int kk = idx >> 5, d4 = (idx & 31) * 4;
            *(float4*)&Bs[kk][d4] = *(const float4*)(Wh_ + (size_t)(f0 + kk) * ND + d4);
        }
        __syncthreads();
#pragma unroll
        for (int k = 0; k < 16; k++) {
            float ra[8], rb[8];
            *(float4*)(ra)     = *(float4*)&As[k][ty * 8];
            *(float4*)(ra + 4) = *(float4*)&As[k][ty * 8 + 4];
            *(float4*)(rb)     = *(float4*)&Bs[k][tx * 8];
            *(float4*)(rb + 4) = *(float4*)&Bs[k][tx * 8 + 4];
#pragma unroll
            for (int u = 0; u < 8; u++)
#pragma unroll
                for (int v = 0; v < 8; v++) acc[u][v] = fmaf(ra[u], rb[v], acc[u][v]);
        }
        __syncthreads();
    }
#pragma unroll
    for (int u = 0; u < 8; u++) {
        int n = i0 + ty * 8 + u;
        size_t base = (size_t)n * HD + h * ND + tx * 8;
        *(float4*)(g_Wh + base)     = *(float4*)&acc[u][0];
        *(float4*)(g_Wh + base + 4) = *(float4*)&acc[u][4];
    }
}

// ---------------- K3: f1,f2 = Wh . a1/a2 ----------------
__global__ void k_f(const float* __restrict__ a1, const float* __restrict__ a2) {
    __shared__ float s1[HD], s2[HD];
    for (int i = threadIdx.x; i < HD; i += 256) { s1[i] = a1[i]; s2[i] = a2[i]; }
    __syncthreads();
    int warp = threadIdx.x >> 5, lane = threadIdx.x & 31;
    int n = blockIdx.x * 8 + warp;
    const float* wr = g_Wh + (size_t)n * HD;
    for (int h = 0; h < NH; h++) {
        float f1 = 0.f, f2 = 0.f;
#pragma unroll
        for (int d = lane; d < ND; d += 32) {
            float v = wr[h * ND + d];
            f1 = fmaf(v, s1[h * ND + d], f1);
            f2 = fmaf(v, s2[h * ND + d], f2);
        }
#pragma unroll
        for (int o = 16; o; o >>= 1) {
            f1 += __shfl_xor_sync(0xffffffffu, f1, o);
            f2 += __shfl_xor_sync(0xffffffffu, f2, o);
        }
        if (lane == 0) { g_f1[h * NN + n] = f1; g_f2[h * NN + n] = f2; }
    }
}

// ---------------- K4: fused masked-softmax aggregation, layer 1 ------------
// grid (32 row-tiles, 8 heads). Block computes 128 rows x 128 dims for one
// head; weight tile generated on the fly from f1/f2/bitmask; elu epilogue.
__global__ __launch_bounds__(256, 2) void k_attn1() {
    __shared__ float ws[32][128];      // weights [jj][r]
    __shared__ float whs[32][128];     // Wh tile [jj][d]
    __shared__ unsigned mrow[128];
    __shared__ float f2s[32];
    __shared__ float denomS[128];
    int h = blockIdx.y, i0 = blockIdx.x * 128;
    int t = threadIdx.x;
    int ty = t >> 4, tx = t & 15;
    int rgen = t >> 1, jh = (t & 1) * 16;
    float f1r = g_f1[h * NN + i0 + rgen];
    float dacc = 0.f;
    float acc[8][8];
#pragma unroll
    for (int u = 0; u < 8; u++)
#pragma unroll
        for (int v = 0; v < 8; v++) acc[u][v] = 0.f;

    for (int jt = 0; jt < NW; jt++) {
        int j0 = jt * 32;
        if (t < 32) f2s[t] = g_f2[h * NN + j0 + t];
        if (t < 128) mrow[t] = g_mask[(size_t)(i0 + t) * NW + jt];
#pragma unroll
        for (int p = 0; p < 4; p++) {
            int idx = p * 256 + t;
            int jj = idx >> 5, d4 = (idx & 31) * 4;
            *(float4*)&whs[jj][d4] = *(const float4*)(g_Wh + (size_t)(j0 + jj) * HD + h * ND + d4);
        }
        __syncthreads();
        unsigned m = mrow[rgen];
        float dloc = 0.f;
#pragma unroll
        for (int q = 0; q < 16; q++) {
            int jj = jh + q;
            float w = ((m >> jj) & 1u) ? __expf(lrelu(f1r + f2s[jj])) : 0.f;
            ws[jj][rgen] = w;
            dloc += w;
        }
        dloc += __shfl_xor_sync(0xffffffffu, dloc, 1);
        if (!(t & 1)) dacc += dloc;
        __syncthreads();
#pragma unroll
        for (int jj = 0; jj < 32; jj++) {
            float rw[8], rb[8];
            *(float4*)(rw)     = *(float4*)&ws[jj][ty * 8];
            *(float4*)(rw + 4) = *(float4*)&ws[jj][ty * 8 + 4];
            *(float4*)(rb)     = *(float4*)&whs[jj][tx * 8];
            *(float4*)(rb + 4) = *(float4*)&whs[jj][tx * 8 + 4];
#pragma unroll
            for (int u = 0; u < 8; u++)
#pragma unroll
                for (int v = 0; v < 8; v++) acc[u][v] = fmaf(rw[u], rb[v], acc[u][v]);
        }
        __syncthreads();
    }
    if (!(t & 1)) denomS[rgen] = dacc;
    __syncthreads();
#pragma unroll
    for (int u = 0; u < 8; u++) {
        int r = ty * 8 + u;
        float inv = 1.f / denomS[r];
        float o[8];
#pragma unroll
        for (int v = 0; v < 8; v++) {
            float z = acc[u][v] * inv;
            o[v] = z > 0.f ? z : (__expf(z) - 1.f);   // elu
        }
        size_t base = (size_t)(i0 + r) * HD + h * ND + tx * 8;
        *(float4*)(g_hcat + base)     = *(float4*)(o);
        *(float4*)(g_hcat + base + 4) = *(float4*)(o + 4);
    }
}

// ---------------- K5: Who = hcat @ Wo  (4096x1024x64) ----------------
// grid 128 blocks, block = 32 rows x 64 cols, 256 thr (TM=2, TN=4)
__global__ __launch_bounds__(256) void k_who(const float* __restrict__ Wo) {
    __shared__ float As[16][36];
    __shared__ float Bs[16][64];
    int i0 = blockIdx.x * 32;
    int t = threadIdx.x, ty = t >> 4, tx = t & 15;
    float acc[2][4];
#pragma unroll
    for (int u = 0; u < 2; u++)
#pragma unroll
        for (int v = 0; v < 4; v++) acc[u][v] = 0.f;
    for (int f0 = 0; f0 < HD; f0 += 16) {
        if (t < 128) {
            int row = t >> 2, k4 = (t & 3) * 4;
            float4 v = *(const float4*)(g_hcat + (size_t)(i0 + row) * HD + f0 + k4);
            As[k4 + 0][row] = v.x; As[k4 + 1][row] = v.y;
            As[k4 + 2][row] = v.z; As[k4 + 3][row] = v.w;
        }
        {
            int kk = t >> 4, d4 = (t & 15) * 4;
            *(float4*)&Bs[kk][d4] = *(const float4*)(Wo + (size_t)(f0 + kk) * NC + d4);
        }
        __syncthreads();
#pragma unroll
        for (int k = 0; k < 16; k++) {
            float ra0 = As[k][ty * 2], ra1 = As[k][ty * 2 + 1];
            float rb[4];
            *(float4*)rb = *(float4*)&Bs[k][tx * 4];
#pragma unroll
            for (int v = 0; v < 4; v++) {
                acc[0][v] = fmaf(ra0, rb[v], acc[0][v]);
                acc[1][v] = fmaf(ra1, rb[v], acc[1][v]);
            }
        }
        __syncthreads();
    }
#pragma unroll
    for (int u = 0; u < 2; u++)
        *(float4*)(g_Who + (size_t)(i0 + ty * 2 + u) * NC + tx * 4) = *(float4*)&acc[u][0];
}

// ---------------- K6: g1,g2 = Who . ao1/ao2 ----------------
__global__ void k_g(const float* __restrict__ ao1, const float* __restrict__ ao2) {
    int warp = threadIdx.x >> 5, lane = threadIdx.x & 31;
    int n = blockIdx.x * 8 + warp;
    const float* r = g_Who + (size_t)n * NC;
    float s1 = fmaf(r[lane], ao1[lane], r[lane + 32] * ao1[lane + 32]);
    float s2 = fmaf(r[lane], ao2[lane], r[lane + 32] * ao2[lane + 32]);
#pragma unroll
    for (int o = 16; o; o >>= 1) {
        s1 += __shfl_xor_sync(0xffffffffu, s1, o);
        s2 += __shfl_xor_sync(0xffffffffu, s2, o);
    }
    if (lane == 0) { g_g1[n] = s1; g_g2[n] = s2; }
}

// ---------------- K7: output attention, j-split partials ----------------
// grid (32 row-tiles, JC chunks). Partial numerator [128x64] + partial denom.
__global__ __launch_bounds__(256, 2) void k_attn2() {
    __shared__ float ws[32][128];
    __shared__ float whs[32][64];
    __shared__ unsigned mrow[128];
    __shared__ float g2s[32];
    int jc = blockIdx.y, i0 = blockIdx.x * 128;
    int t = threadIdx.x, ty = t >> 4, tx = t & 15;
    int rgen = t >> 1, jh = (t & 1) * 16;
    float g1r = g_g1[i0 + rgen];
    float dacc = 0.f;
    float acc[8][4];
#pragma unroll
    for (int u = 0; u < 8; u++)
#pragma unroll
        for (int v = 0; v < 4; v++) acc[u][v] = 0.f;

    int jt0 = jc * (NW / JC);
    for (int jt = jt0; jt < jt0 + NW / JC; jt++) {
        int j0 = jt * 32;
        if (t < 32) g2s[t] = g_g2[j0 + t];
        if (t < 128) mrow[t] = g_mask[(size_t)(i0 + t) * NW + jt];
#pragma unroll
        for (int p = 0; p < 2; p++) {
            int idx = p * 256 + t;
            int jj = idx >> 4, d4 = (idx & 15) * 4;
            *(float4*)&whs[jj][d4] = *(const float4*)(g_Who + (size_t)(j0 + jj) * NC + d4);
        }
        __syncthreads();
        unsigned m = mrow[rgen];
        float dloc = 0.f;
#pragma unroll
        for (int q = 0; q < 16; q++) {
            int jj = jh + q;
            float w = ((m >> jj) & 1u) ? __expf(lrelu(g1r + g2s[jj])) : 0.f;
            ws[jj][rgen] = w;
            dloc += w;
        }
        dloc += __shfl_xor_sync(0xffffffffu, dloc, 1);
        if (!(t & 1)) dacc += dloc;
        __syncthreads();
#pragma unroll
        for (int jj = 0; jj < 32; jj++) {
            float rw[8], rb[4];
            *(float4*)(rw)     = *(float4*)&ws[jj][ty * 8];
            *(float4*)(rw + 4) = *(float4*)&ws[jj][ty * 8 + 4];
            *(float4*)rb = *(float4*)&whs[jj][tx * 4];
#pragma unroll
            for (int u = 0; u < 8; u++)
#pragma unroll
                for (int v = 0; v < 4; v++) acc[u][v] = fmaf(rw[u], rb[v], acc[u][v]);
        }
        __syncthreads();
    }
#pragma unroll
    for (int u = 0; u < 8; u++) {
        int r = ty * 8 + u;
        size_t base = ((size_t)jc * NN + i0 + r) * NC + tx * 4;
        *(float4*)(g_part + base) = *(float4*)&acc[u][0];
    }
    if (!(t & 1)) g_dpart[jc * NN + i0 + rgen] = dacc;
}

// ---------------- K8: combine partials + elu + log_softmax ----------------
__global__ void k_final(float* __restrict__ out) {
    int warp = threadIdx.x >> 5, lane = threadIdx.x & 31;
    int n = blockIdx.x * 8 + warp;
    float den = 0.f;
#pragma unroll
    for (int jc = 0; jc < JC; jc++) den += g_dpart[jc * NN + n];
    float inv = 1.f / den;
    float v0 = 0.f, v1 = 0.f;
#pragma unroll
    for (int jc = 0; jc < JC; jc++) {
        size_t base = ((size_t)jc * NN + n) * NC;
        v0 += g_part[base + lane];
        v1 += g_part[base + lane + 32];
    }
    v0 *= inv; v1 *= inv;
    v0 = v0 > 0.f ? v0 : (expf(v0) - 1.f);
    v1 = v1 > 0.f ? v1 : (expf(v1) - 1.f);
    float m = fmaxf(v0, v1);
#pragma unroll
    for (int o = 16; o; o >>= 1) m = fmaxf(m, __shfl_xor_sync(0xffffffffu, m, o));
    float s = expf(v0 - m) + expf(v1 - m);
#pragma unroll
    for (int o = 16; o; o >>= 1) s += __shfl_xor_sync(0xffffffffu, s, o);
    float lse = m + logf(s);
    out[(size_t)n * NC + lane] = v0 - lse;
    out[(size_t)n * NC + lane + 32] = v1 - lse;
}

// ---------------- launch ----------------
extern "C" void kernel_launch(void* const* d_in, const int* in_sizes, int n_in,
                              void* d_out, int out_size) {
    const float* x   = (const float*)d_in[0];
    const int*   adj = (const int*)d_in[1];
    const float* W   = (const float*)d_in[2];
    const float* a1  = (const float*)d_in[3];
    const float* a2  = (const float*)d_in[4];
    const float* Wo  = (const float*)d_in[5];
    const float* ao1 = (const float*)d_in[6];
    const float* ao2 = (const float*)d_in[7];
    float* out = (float*)d_out;

    k_pack <<<NN, 128>>>(adj);
    k_wh   <<<dim3(NN / 128, NH), 256>>>(x, W);
    k_f    <<<NN / 8, 256>>>(a1, a2);
    k_attn1<<<dim3(NN / 128, NH), 256>>>();
    k_who  <<<NN / 32, 256>>>(Wo);
    k_g    <<<NN / 8, 256>>>(ao1, ao2);
    k_attn2<<<dim3(NN / 128, JC), 256>>>();
    k_final<<<NN / 8, 256>>>(out);
}

// round 4
// speedup vs baseline: 1.3780x; 1.3780x over previous
#include <cuda_runtime.h>
#include <cuda_bf16.h>
#include <math.h>
#include <stdint.h>

#define NN 4096
#define NF 1024
#define NH 8
#define ND 128
#define NC 64
#define HD (NH*ND)      // 1024
#define NW (NN/32)      // 128 mask words per row
#define LALPHA 0.2f
#define JC 8            // j-split chunks for output attention layer

// ---------------- scratch (static device globals; no allocs) ----------------
__device__ unsigned g_mask[(size_t)NN*NW];         // 2 MB packed adjacency
__device__ __nv_bfloat16 g_VhiT[(size_t)NH*ND*NN]; // 8 MB  Wh^T hi  [h][d][n]
__device__ __nv_bfloat16 g_VloT[(size_t)NH*ND*NN]; // 8 MB  Wh^T lo
__device__ float g_f1[NH*NN];
__device__ float g_f2[NH*NN];
__device__ float g_hcat[(size_t)NN*HD];            // 16 MB  elu(h) concat
__device__ float g_Who[(size_t)NN*NC];             // 1 MB
__device__ float g_g1[NN];
__device__ float g_g2[NN];
__device__ float g_part[(size_t)JC*NN*NC];         // 8 MB partial numerators
__device__ float g_dpart[JC*NN];                   // partial denominators

__device__ __forceinline__ float lrelu(float s) { return s > 0.f ? s : LALPHA * s; }

__device__ __forceinline__ uint32_t s2u(const void* p) {
    uint32_t a;
    asm("{ .reg .u64 t; cvta.to.shared.u64 t, %1; cvt.u32.u64 %0, t; }" : "=r"(a) : "l"(p));
    return a;
}

#define LDSM4(r, addr) \
    asm volatile("ldmatrix.sync.aligned.m8n8.x4.shared.b16 {%0,%1,%2,%3}, [%4];" \
        : "=r"((r)[0]), "=r"((r)[1]), "=r"((r)[2]), "=r"((r)[3]) : "r"(addr))

#define MMA_BF16(c, a, b0, b1) \
    asm volatile("mma.sync.aligned.m16n8k16.row.col.f32.bf16.bf16.f32 " \
        "{%0,%1,%2,%3}, {%4,%5,%6,%7}, {%8,%9}, {%0,%1,%2,%3};" \
        : "+f"((c)[0]), "+f"((c)[1]), "+f"((c)[2]), "+f"((c)[3]) \
        : "r"((a)[0]), "r"((a)[1]), "r"((a)[2]), "r"((a)[3]), "r"(b0), "r"(b1))

// ---------------- K1: pack adj -> bitmask ----------------
__global__ void k_pack(const int* __restrict__ adj) {
    int row = blockIdx.x;
    int warp = threadIdx.x >> 5, lane = threadIdx.x & 31;
    const int* ar = adj + (size_t)row * NN;
    for (int w = warp; w < NW; w += 4) {
        unsigned b = __ballot_sync(0xffffffffu, ar[w * 32 + lane] > 0);
        if (lane == 0) g_mask[(size_t)row * NW + w] = b;
    }
}

// ---------------- K2: Wh = x @ W ; epilogue: f1/f2 + transposed bf16 hi/lo --
#define ASTR 132
__global__ __launch_bounds__(256, 2) void k_wh(const float* __restrict__ x,
                                               const float* __restrict__ W,
                                               const float* __restrict__ a1,
                                               const float* __restrict__ a2) {
    __shared__ float As[16][ASTR];
    __shared__ float Bs[16][128];
    __shared__ float a1s[ND], a2s[ND];
    int h = blockIdx.y;
    int i0 = blockIdx.x * 128;
    int t = threadIdx.x;
    int ty = t >> 4, tx = t & 15;
    if (t < ND) { a1s[t] = a1[h * ND + t]; a2s[t] = a2[h * ND + t]; }
    const float* Wh_ = W + (size_t)h * NF * ND;
    float acc[8][8];
#pragma unroll
    for (int u = 0; u < 8; u++)
#pragma unroll
        for (int v = 0; v < 8; v++) acc[u][v] = 0.f;

    for (int f0 = 0; f0 < NF; f0 += 16) {
#pragma unroll
        for (int p = 0; p < 2; p++) {
            int idx = p * 256 + t;
            int row = idx >> 2, k4 = (idx & 3) * 4;
            float4 v = *(const float4*)(x + (size_t)(i0 + row) * NF + f0 + k4);
            As[k4 + 0][row] = v.x; As[k4 + 1][row] = v.y;
            As[k4 + 2][row] = v.z; As[k4 + 3][row] = v.w;
        }
#pragma unroll
        for (int p = 0; p < 2; p++) {
            int idx = p * 256 + t;
            int kk = idx >> 5, d4 = (idx & 31) * 4;
            *(float4*)&Bs[kk][d4] = *(const float4*)(Wh_ + (size_t)(f0 + kk) * ND + d4);
        }
        __syncthreads();
#pragma unroll
        for (int k = 0; k < 16; k++) {
            float ra[8], rb[8];
            *(float4*)(ra)     = *(float4*)&As[k][ty * 8];
            *(float4*)(ra + 4) = *(float4*)&As[k][ty * 8 + 4];
            *(float4*)(rb)     = *(float4*)&Bs[k][tx * 8];
            *(float4*)(rb + 4) = *(float4*)&Bs[k][tx * 8 + 4];
#pragma unroll
            for (int u = 0; u < 8; u++)
#pragma unroll
                for (int v = 0; v < 8; v++) acc[u][v] = fmaf(ra[u], rb[v], acc[u][v]);
        }
        __syncthreads();
    }
    // f1/f2: reduce acc[u][v]*a over d (tx dimension)
#pragma unroll
    for (int u = 0; u < 8; u++) {
        float p1 = 0.f, p2 = 0.f;
#pragma unroll
        for (int v = 0; v < 8; v++) {
            p1 = fmaf(acc[u][v], a1s[tx * 8 + v], p1);
            p2 = fmaf(acc[u][v], a2s[tx * 8 + v], p2);
        }
#pragma unroll
        for (int o = 8; o; o >>= 1) {
            p1 += __shfl_xor_sync(0xffffffffu, p1, o);
            p2 += __shfl_xor_sync(0xffffffffu, p2, o);
        }
        if (tx == 0) {
            g_f1[h * NN + i0 + ty * 8 + u] = p1;
            g_f2[h * NN + i0 + ty * 8 + u] = p2;
        }
    }
    // transposed bf16 hi/lo stores: [h][d][n], n contiguous
#pragma unroll
    for (int v = 0; v < 8; v++) {
        int d = tx * 8 + v;
        uint32_t hp[4], lp[4];
#pragma unroll
        for (int u = 0; u < 8; u += 2) {
            float w0 = acc[u][v], w1 = acc[u + 1][v];
            __nv_bfloat16 h0 = __float2bfloat16(w0), h1 = __float2bfloat16(w1);
            __nv_bfloat16 l0 = __float2bfloat16(w0 - __bfloat162float(h0));
            __nv_bfloat16 l1 = __float2bfloat16(w1 - __bfloat162float(h1));
            __nv_bfloat162 hh(h0, h1), ll(l0, l1);
            hp[u >> 1] = *(uint32_t*)&hh; lp[u >> 1] = *(uint32_t*)&ll;
        }
        size_t base = (size_t)(h * ND + d) * NN + i0 + ty * 8;
        *(uint4*)(g_VhiT + base) = *(uint4*)hp;
        *(uint4*)(g_VloT + base) = *(uint4*)lp;
    }
}

// ---------------- K4: HMMA masked-softmax aggregation, layer 1 -------------
// CTA = (128-row i-tile, head). 8 warps, warp = 32 rows x 64 cols fp32 acc.
// P generated on the fly as bf16 hi/lo in SMEM (272B row stride); V = staged
// bf16 hi/lo of Wh^T. 3 mma products per tile: Phi*Vhi + Phi*Vlo + Plo*Vhi.
// SMEM layout (bytes): f2s@0[512], mask@512[2048], dens@2560[512],
//   PHI@4096, PLO@38912, VHI@73728, VLO@108544; total 143360.
#define PSTR 272u            // bytes per smem row (136 bf16)
#define TILE_B 34816u        // 128 * 272
#define SMEM_TOT 143360
__global__ __launch_bounds__(256) void k_attn1() {
    extern __shared__ char smem[];
    uint32_t sb = s2u(smem);
    int t = threadIdx.x, lane = t & 31, wid = t >> 5;
    int h = blockIdx.y, i0 = blockIdx.x * 128;
    int wm = wid & 3, wn = wid >> 2;

    float* f2s = (float*)(smem);
    char* mw = smem + 512;
    float* dens = (float*)(smem + 2560);
    uint32_t PHI = sb + 4096, VHI = sb + 73728;

    int rgen = t >> 1, jh64 = (t & 1) * 64;
    float f1r = g_f1[h * NN + i0 + rgen];
    float dacc = 0.f;

    float acc[2][8][4];
#pragma unroll
    for (int mt = 0; mt < 2; mt++)
#pragma unroll
        for (int nt = 0; nt < 8; nt++)
#pragma unroll
            for (int q = 0; q < 4; q++) acc[mt][nt][q] = 0.f;

    // ldmatrix base addresses
    uint32_t aAddr0 = PHI + (uint32_t)(wm * 32 + (lane & 15)) * PSTR + (uint32_t)(lane >> 4) * 16u;
    int brow = ((lane >> 4) << 3) + (lane & 7);
    uint32_t bAddr0 = VHI + (uint32_t)(wn * 64 + brow) * PSTR + (uint32_t)((lane >> 3) & 1) * 16u;

    for (int jt = 0; jt < 32; jt++) {
        int j0 = jt * 128;
        __syncthreads();   // previous tile's ldmatrix reads done
        if (t < 128) f2s[t] = g_f2[h * NN + j0 + t];
        *(uint2*)(mw + rgen * 16 + (t & 1) * 8) =
            *(const uint2*)(g_mask + (size_t)(i0 + rgen) * NW + jt * 4 + (t & 1) * 2);
        // stage V hi/lo tiles [d 0..127][j0..j0+127]
#pragma unroll
        for (int c = 0; c < 8; c++) {
            int idx = c * 256 + t;
            int d = idx >> 4, jc = (idx & 15) * 8;
            uint32_t o = (uint32_t)d * PSTR + (uint32_t)jc * 2u;
            size_t g = (size_t)(h * ND + d) * NN + j0 + jc;
            *(float4*)(smem + 73728 + o)  = *(const float4*)(g_VhiT + g);
            *(float4*)(smem + 108544 + o) = *(const float4*)(g_VloT + g);
        }
        __syncthreads();
        // generate P hi/lo (row rgen, 64 cols from jh64)
        uint64_t m64 = *(const uint64_t*)(mw + rgen * 16 + (t & 1) * 8);
#pragma unroll
        for (int g = 0; g < 8; g++) {
            uint32_t ph[4], pl[4];
#pragma unroll
            for (int q = 0; q < 8; q += 2) {
                int b = g * 8 + q;
                float w0 = 0.f, w1 = 0.f;
                if ((m64 >> b) & 1)       { float s = f1r + f2s[jh64 + b];     w0 = __expf(lrelu(s)); }
                if ((m64 >> (b + 1)) & 1) { float s = f1r + f2s[jh64 + b + 1]; w1 = __expf(lrelu(s)); }
                dacc += w0 + w1;
                __nv_bfloat16 h0 = __float2bfloat16(w0), h1 = __float2bfloat16(w1);
                __nv_bfloat16 l0 = __float2bfloat16(w0 - __bfloat162float(h0));
                __nv_bfloat16 l1 = __float2bfloat16(w1 - __bfloat162float(h1));
                __nv_bfloat162 hh(h0, h1), ll(l0, l1);
                ph[q >> 1] = *(uint32_t*)&hh; pl[q >> 1] = *(uint32_t*)&ll;
            }
            uint32_t o = (uint32_t)rgen * PSTR + (uint32_t)(jh64 + g * 8) * 2u;
            *(uint4*)(smem + 4096 + o)  = *(uint4*)ph;
            *(uint4*)(smem + 38912 + o) = *(uint4*)pl;
        }
        __syncthreads();
        // HMMA over 8 k-steps of 16
#pragma unroll
        for (int ks = 0; ks < 8; ks++) {
            uint32_t ahi[2][4], alo[2][4];
#pragma unroll
            for (int mt = 0; mt < 2; mt++) {
                uint32_t ao = aAddr0 + (uint32_t)mt * (16u * PSTR) + (uint32_t)ks * 32u;
                LDSM4(ahi[mt], ao);
                LDSM4(alo[mt], ao + TILE_B);
            }
#pragma unroll
            for (int p = 0; p < 4; p++) {
                uint32_t bh[4], bl[4];
                uint32_t bo = bAddr0 + (uint32_t)p * (16u * PSTR) + (uint32_t)ks * 32u;
                LDSM4(bh, bo);
                LDSM4(bl, bo + TILE_B);
#pragma unroll
                for (int mt = 0; mt < 2; mt++) {
                    MMA_BF16(acc[mt][2 * p],     ahi[mt], bh[0], bh[1]);
                    MMA_BF16(acc[mt][2 * p],     ahi[mt], bl[0], bl[1]);
                    MMA_BF16(acc[mt][2 * p],     alo[mt], bh[0], bh[1]);
                    MMA_BF16(acc[mt][2 * p + 1], ahi[mt], bh[2], bh[3]);
                    MMA_BF16(acc[mt][2 * p + 1], ahi[mt], bl[2], bl[3]);
                    MMA_BF16(acc[mt][2 * p + 1], alo[mt], bh[2], bh[3]);
                }
            }
        }
    }
    // denominators
    dacc += __shfl_xor_sync(0xffffffffu, dacc, 1);
    if (!(t & 1)) dens[rgen] = dacc;
    __syncthreads();
    // epilogue: scale + elu, write to g_hcat
#pragma unroll
    for (int mt = 0; mt < 2; mt++) {
        int rl = wm * 32 + mt * 16 + (lane >> 2);
        float inv0 = 1.f / dens[rl], inv1 = 1.f / dens[rl + 8];
        float* d0 = g_hcat + (size_t)(i0 + rl) * HD + h * ND + wn * 64 + (lane & 3) * 2;
        float* d1 = d0 + (size_t)8 * HD;
#pragma unroll
        for (int nt = 0; nt < 8; nt++) {
            float z0 = acc[mt][nt][0] * inv0, z1 = acc[mt][nt][1] * inv0;
            float z2 = acc[mt][nt][2] * inv1, z3 = acc[mt][nt][3] * inv1;
            float2 o0, o1;
            o0.x = z0 > 0.f ? z0 : (__expf(z0) - 1.f);
            o0.y = z1 > 0.f ? z1 : (__expf(z1) - 1.f);
            o1.x = z2 > 0.f ? z2 : (__expf(z2) - 1.f);
            o1.y = z3 > 0.f ? z3 : (__expf(z3) - 1.f);
            *(float2*)(d0 + nt * 8) = o0;
            *(float2*)(d1 + nt * 8) = o1;
        }
    }
}

// ---------------- K5: Who = hcat @ Wo  (4096x1024x64) ----------------
__global__ __launch_bounds__(256) void k_who(const float* __restrict__ Wo) {
    __shared__ float As[16][36];
    __shared__ float Bs[16][64];
    int i0 = blockIdx.x * 32;
    int t = threadIdx.x, ty = t >> 4, tx = t & 15;
    float acc[2][4];
#pragma unroll
    for (int u = 0; u < 2; u++)
#pragma unroll
        for (int v = 0; v < 4; v++) acc[u][v] = 0.f;
    for (int f0 = 0; f0 < HD; f0 += 16) {
        if (t < 128) {
            int row = t >> 2, k4 = (t & 3) * 4;
            float4 v = *(const float4*)(g_hcat + (size_t)(i0 + row) * HD + f0 + k4);
            As[k4 + 0][row] = v.x; As[k4 + 1][row] = v.y;
            As[k4 + 2][row] = v.z; As[k4 + 3][row] = v.w;
        }
        {
            int kk = t >> 4, d4 = (t & 15) * 4;
            *(float4*)&Bs[kk][d4] = *(const float4*)(Wo + (size_t)(f0 + kk) * NC + d4);
        }
        __syncthreads();
#pragma unroll
        for (int k = 0; k < 16; k++) {
            float ra0 = As[k][ty * 2], ra1 = As[k][ty * 2 + 1];
            float rb[4];
            *(float4*)rb = *(float4*)&Bs[k][tx * 4];
#pragma unroll
            for (int v = 0; v < 4; v++) {
                acc[0][v] = fmaf(ra0, rb[v], acc[0][v]);
                acc[1][v] = fmaf(ra1, rb[v], acc[1][v]);
            }
        }
        __syncthreads();
    }
#pragma unroll
    for (int u = 0; u < 2; u++)
        *(float4*)(g_Who + (size_t)(i0 + ty * 2 + u) * NC + tx * 4) = *(float4*)&acc[u][0];
}

// ---------------- K6: g1,g2 = Who . ao1/ao2 ----------------
__global__ void k_g(const float* __restrict__ ao1, const float* __restrict__ ao2) {
    int warp = threadIdx.x >> 5, lane = threadIdx.x & 31;
    int n = blockIdx.x * 8 + warp;
    const float* r = g_Who + (size_t)n * NC;
    float s1 = fmaf(r[lane], ao1[lane], r[lane + 32] * ao1[lane + 32]);
    float s2 = fmaf(r[lane], ao2[lane], r[lane + 32] * ao2[lane + 32]);
#pragma unroll
    for (int o = 16; o; o >>= 1) {
        s1 += __shfl_xor_sync(0xffffffffu, s1, o);
        s2 += __shfl_xor_sync(0xffffffffu, s2, o);
    }
    if (lane == 0) { g_g1[n] = s1; g_g2[n] = s2; }
}

// ---------------- K7: output attention, j-split partials ----------------
__global__ __launch_bounds__(256, 2) void k_attn2() {
    __shared__ float ws[32][128];
    __shared__ float whs[32][64];
    __shared__ unsigned mrow[128];
    __shared__ float g2s[32];
    int jc = blockIdx.y, i0 = blockIdx.x * 128;
    int t = threadIdx.x, ty = t >> 4, tx = t & 15;
    int rgen = t >> 1, jh = (t & 1) * 16;
    float g1r = g_g1[i0 + rgen];
    float dacc = 0.f;
    float acc[8][4];
#pragma unroll
    for (int u = 0; u < 8; u++)
#pragma unroll
        for (int v = 0; v < 4; v++) acc[u][v] = 0.f;

    int jt0 = jc * (NW / JC);
    for (int jt = jt0; jt < jt0 + NW / JC; jt++) {
        int j0 = jt * 32;
        if (t < 32) g2s[t] = g_g2[j0 + t];
        if (t < 128) mrow[t] = g_mask[(size_t)(i0 + t) * NW + jt];
#pragma unroll
        for (int p = 0; p < 2; p++) {
            int idx = p * 256 + t;
            int jj = idx >> 4, d4 = (idx & 15) * 4;
            *(float4*)&whs[jj][d4] = *(const float4*)(g_Who + (size_t)(j0 + jj) * NC + d4);
        }
        __syncthreads();
        unsigned m = mrow[rgen];
        float dloc = 0.f;
#pragma unroll
        for (int q = 0; q < 16; q++) {
            int jj = jh + q;
            float w = ((m >> jj) & 1u) ? __expf(lrelu(g1r + g2s[jj])) : 0.f;
            ws[jj][rgen] = w;
            dloc += w;
        }
        dloc += __shfl_xor_sync(0xffffffffu, dloc, 1);
        if (!(t & 1)) dacc += dloc;
        __syncthreads();
#pragma unroll
        for (int jj = 0; jj < 32; jj++) {
            float rw[8], rb[4];
            *(float4*)(rw)     = *(float4*)&ws[jj][ty * 8];
            *(float4*)(rw + 4) = *(float4*)&ws[jj][ty * 8 + 4];
            *(float4*)rb = *(float4*)&whs[jj][tx * 4];
#pragma unroll
            for (int u = 0; u < 8; u++)
#pragma unroll
                for (int v = 0; v < 4; v++) acc[u][v] = fmaf(rw[u], rb[v], acc[u][v]);
        }
        __syncthreads();
    }
#pragma unroll
    for (int u = 0; u < 8; u++) {
        int r = ty * 8 + u;
        size_t base = ((size_t)jc * NN + i0 + r) * NC + tx * 4;
        *(float4*)(g_part + base) = *(float4*)&acc[u][0];
    }
    if (!(t & 1)) g_dpart[jc * NN + i0 + rgen] = dacc;
}

// ---------------- K8: combine partials + elu + log_softmax ----------------
__global__ void k_final(float* __restrict__ out) {
    int warp = threadIdx.x >> 5, lane = threadIdx.x & 31;
    int n = blockIdx.x * 8 + warp;
    float den = 0.f;
#pragma unroll
    for (int jc = 0; jc < JC; jc++) den += g_dpart[jc * NN + n];
    float inv = 1.f / den;
    float v0 = 0.f, v1 = 0.f;
#pragma unroll
    for (int jc = 0; jc < JC; jc++) {
        size_t base = ((size_t)jc * NN + n) * NC;
        v0 += g_part[base + lane];
        v1 += g_part[base + lane + 32];
    }
    v0 *= inv; v1 *= inv;
    v0 = v0 > 0.f ? v0 : (expf(v0) - 1.f);
    v1 = v1 > 0.f ? v1 : (expf(v1) - 1.f);
    float m = fmaxf(v0, v1);
#pragma unroll
    for (int o = 16; o; o >>= 1) m = fmaxf(m, __shfl_xor_sync(0xffffffffu, m, o));
    float s = expf(v0 - m) + expf(v1 - m);
#pragma unroll
    for (int o = 16; o; o >>= 1) s += __shfl_xor_sync(0xffffffffu, s, o);
    float lse = m + logf(s);
    out[(size_t)n * NC + lane] = v0 - lse;
    out[(size_t)n * NC + lane + 32] = v1 - lse;
}

// ---------------- launch ----------------
extern "C" void kernel_launch(void* const* d_in, const int* in_sizes, int n_in,
                              void* d_out, int out_size) {
    const float* x   = (const float*)d_in[0];
    const int*   adj = (const int*)d_in[1];
    const float* W   = (const float*)d_in[2];
    const float* a1  = (const float*)d_in[3];
    const float* a2  = (const float*)d_in[4];
    const float* Wo  = (const float*)d_in[5];
    const float* ao1 = (const float*)d_in[6];
    const float* ao2 = (const float*)d_in[7];
    float* out = (float*)d_out;

    cudaFuncSetAttribute(k_attn1, cudaFuncAttributeMaxDynamicSharedMemorySize, SMEM_TOT);

    k_pack <<<NN, 128>>>(adj);
    k_wh   <<<dim3(NN / 128, NH), 256>>>(x, W, a1, a2);
    k_attn1<<<dim3(NN / 128, NH), 256, SMEM_TOT>>>();
    k_who  <<<NN / 32, 256>>>(Wo);
    k_g    <<<NN / 8, 256>>>(ao1, ao2);
    k_attn2<<<dim3(NN / 128, JC), 256>>>();
    k_final<<<NN / 8, 256>>>(out);
}

// round 5
// speedup vs baseline: 1.5899x; 1.1537x over previous
#include <cuda_runtime.h>
#include <cuda_bf16.h>
#include <math.h>
#include <stdint.h>

#define NN 4096
#define NF 1024
#define NH 8
#define ND 128
#define NC 64
#define HD (NH*ND)      // 1024
#define NW (NN/32)      // 128 mask words per row
#define LALPHA 0.2f
#define JC 8            // j-split chunks for output attention layer
#define KC 4            // split-K chunks for k_who

// ---------------- scratch (static device globals; no allocs) ----------------
__device__ unsigned g_mask[(size_t)NN*NW];         // 2 MB packed adjacency
__device__ __nv_bfloat16 g_VhiT[(size_t)NH*ND*NN]; // 8 MB  Wh^T hi  [h][d][n]
__device__ __nv_bfloat16 g_VloT[(size_t)NH*ND*NN]; // 8 MB  Wh^T lo
__device__ __nv_bfloat16 g_xhi[(size_t)NN*NF];     // 8 MB  x hi
__device__ __nv_bfloat16 g_xlo[(size_t)NN*NF];     // 8 MB  x lo
__device__ __nv_bfloat16 g_WThi[(size_t)NH*ND*NF]; // 2 MB  W^T hi [h][d][f]
__device__ __nv_bfloat16 g_WTlo[(size_t)NH*ND*NF]; // 2 MB
__device__ float g_f1[NH*NN];
__device__ float g_f2[NH*NN];
__device__ float g_hcat[(size_t)NN*HD];            // 16 MB  elu(h) concat
__device__ float g_Who[(size_t)NN*NC];             // 1 MB
__device__ float g_g1[NN];
__device__ float g_g2[NN];
__device__ float g_part[(size_t)JC*NN*NC];         // 8 MB partials (who & attn2)
__device__ float g_dpart[JC*NN];                   // partial denominators

__device__ __forceinline__ float lrelu(float s) { return s > 0.f ? s : LALPHA * s; }

__device__ __forceinline__ uint32_t s2u(const void* p) {
    uint32_t a;
    asm("{ .reg .u64 t; cvta.to.shared.u64 t, %1; cvt.u32.u64 %0, t; }" : "=r"(a) : "l"(p));
    return a;
}

#define LDSM4(r, addr) \
    asm volatile("ldmatrix.sync.aligned.m8n8.x4.shared.b16 {%0,%1,%2,%3}, [%4];" \
        : "=r"((r)[0]), "=r"((r)[1]), "=r"((r)[2]), "=r"((r)[3]) : "r"(addr))

#define MMA_BF16(c, a, b0, b1) \
    asm volatile("mma.sync.aligned.m16n8k16.row.col.f32.bf16.bf16.f32 " \
        "{%0,%1,%2,%3}, {%4,%5,%6,%7}, {%8,%9}, {%0,%1,%2,%3};" \
        : "+f"((c)[0]), "+f"((c)[1]), "+f"((c)[2]), "+f"((c)[3]) \
        : "r"((a)[0]), "r"((a)[1]), "r"((a)[2]), "r"((a)[3]), "r"(b0), "r"(b1))

// ---------------- K1: pack adj -> bitmask ----------------
__global__ void k_pack(const int* __restrict__ adj) {
    int row = blockIdx.x;
    int warp = threadIdx.x >> 5, lane = threadIdx.x & 31;
    const int* ar = adj + (size_t)row * NN;
    for (int w = warp; w < NW; w += 4) {
        unsigned b = __ballot_sync(0xffffffffu, ar[w * 32 + lane] > 0);
        if (lane == 0) g_mask[(size_t)row * NW + w] = b;
    }
}

// ---------------- K1b: split x into bf16 hi/lo ----------------
__global__ void k_splitx(const float* __restrict__ x) {
    int i = blockIdx.x * 256 + threadIdx.x;   // one float4 each
    float4 v = *(const float4*)(x + (size_t)i * 4);
    __nv_bfloat16 h0 = __float2bfloat16(v.x), h1 = __float2bfloat16(v.y);
    __nv_bfloat16 h2 = __float2bfloat16(v.z), h3 = __float2bfloat16(v.w);
    __nv_bfloat16 l0 = __float2bfloat16(v.x - __bfloat162float(h0));
    __nv_bfloat16 l1 = __float2bfloat16(v.y - __bfloat162float(h1));
    __nv_bfloat16 l2 = __float2bfloat16(v.z - __bfloat162float(h2));
    __nv_bfloat16 l3 = __float2bfloat16(v.w - __bfloat162float(h3));
    __nv_bfloat162 hh0(h0, h1), hh1(h2, h3), ll0(l0, l1), ll1(l2, l3);
    uint2 ho, lo;
    ho.x = *(uint32_t*)&hh0; ho.y = *(uint32_t*)&hh1;
    lo.x = *(uint32_t*)&ll0; lo.y = *(uint32_t*)&ll1;
    *(uint2*)(g_xhi + (size_t)i * 4) = ho;
    *(uint2*)(g_xlo + (size_t)i * 4) = lo;
}

// ---------------- K1c: W -> W^T hi/lo  [h][f][d] -> [h][d][f] ----------------
__global__ void k_splitw(const float* __restrict__ W) {
    __shared__ float ts[32][33];
    int f0 = blockIdx.x * 32, d0 = blockIdx.y * 32, h = blockIdx.z;
    int t = threadIdx.x;
    int r = t >> 3, c4 = (t & 7) * 4;
#pragma unroll
    for (int p = 0; p < 32; p += 32) { }
    // load 32x32 tile: W[h][f0+r][d0+c]
#pragma unroll
    for (int q = 0; q < 1; q++) { }
    float4 v = *(const float4*)(W + ((size_t)h * NF + f0 + r) * ND + d0 + c4);
    ts[r][c4] = v.x; ts[r][c4 + 1] = v.y; ts[r][c4 + 2] = v.z; ts[r][c4 + 3] = v.w;
    __syncthreads();
    // write WT[h][d0+r][f0+c] hi/lo, 4 per thread
    int rr = t >> 3, cc = (t & 7) * 4;
    uint32_t hp[2], lp[2];
#pragma unroll
    for (int q = 0; q < 4; q += 2) {
        float w0 = ts[cc + q][rr], w1 = ts[cc + q + 1][rr];
        __nv_bfloat16 h0 = __float2bfloat16(w0), h1 = __float2bfloat16(w1);
        __nv_bfloat16 l0 = __float2bfloat16(w0 - __bfloat162float(h0));
        __nv_bfloat16 l1 = __float2bfloat16(w1 - __bfloat162float(h1));
        __nv_bfloat162 hh(h0, h1), ll(l0, l1);
        hp[q >> 1] = *(uint32_t*)&hh; lp[q >> 1] = *(uint32_t*)&ll;
    }
    size_t base = ((size_t)h * ND + d0 + rr) * NF + f0 + cc;
    *(uint2*)(g_WThi + base) = *(uint2*)hp;
    *(uint2*)(g_WTlo + base) = *(uint2*)lp;
}

// ---------------- K2: Wh = x @ W via HMMA hi/lo; epilogue f1/f2 + V^T -------
// grid (32 i-tiles, 8 heads), 256 thr. Tiles: A 128x64, B 128x64 bf16 hi/lo.
#define WSTR 144u           // bytes per smem row (72 bf16)
#define WTILE 18432u        // 128 * 144
#define SM_AHI 0u
#define SM_ALO 18432u
#define SM_BHI 36864u
#define SM_BLO 55296u
#define SM_A1  73728
#define SM_A2  74240
#define CSTR 130            // fp32 staging stride
#define SMEM_WH 74752
__global__ __launch_bounds__(256) void k_wh(const float* __restrict__ a1,
                                            const float* __restrict__ a2) {
    extern __shared__ char smem[];
    uint32_t sb = s2u(smem);
    int t = threadIdx.x, lane = t & 31, wid = t >> 5;
    int h = blockIdx.y, i0 = blockIdx.x * 128;
    int wm = wid & 3, wn = wid >> 2;
    float* a1s = (float*)(smem + SM_A1);
    float* a2s = (float*)(smem + SM_A2);
    if (t < ND) { a1s[t] = a1[h * ND + t]; a2s[t] = a2[h * ND + t]; }

    float acc[2][8][4];
#pragma unroll
    for (int mt = 0; mt < 2; mt++)
#pragma unroll
        for (int nt = 0; nt < 8; nt++)
#pragma unroll
            for (int q = 0; q < 4; q++) acc[mt][nt][q] = 0.f;

    uint32_t aAddr0 = sb + SM_AHI + (uint32_t)(wm * 32 + (lane & 15)) * WSTR + (uint32_t)(lane >> 4) * 16u;
    int brow = ((lane >> 4) << 3) + (lane & 7);
    uint32_t bAddr0 = sb + SM_BHI + (uint32_t)(wn * 64 + brow) * WSTR + (uint32_t)((lane >> 3) & 1) * 16u;

    for (int kt = 0; kt < 16; kt++) {
        int f0 = kt * 64;
        __syncthreads();
#pragma unroll
        for (int c = 0; c < 4; c++) {
            int idx = c * 256 + t;
            int row = idx >> 3, ch = (idx & 7) * 8;
            uint32_t o = (uint32_t)row * WSTR + (uint32_t)ch * 2u;
            size_t ga = (size_t)(i0 + row) * NF + f0 + ch;
            size_t gb = ((size_t)h * ND + row) * NF + f0 + ch;
            *(uint4*)(smem + SM_AHI + o) = *(const uint4*)(g_xhi + ga);
            *(uint4*)(smem + SM_ALO + o) = *(const uint4*)(g_xlo + ga);
            *(uint4*)(smem + SM_BHI + o) = *(const uint4*)(g_WThi + gb);
            *(uint4*)(smem + SM_BLO + o) = *(const uint4*)(g_WTlo + gb);
        }
        __syncthreads();
#pragma unroll
        for (int ks = 0; ks < 4; ks++) {
            uint32_t ahi[2][4], alo[2][4];
#pragma unroll
            for (int mt = 0; mt < 2; mt++) {
                uint32_t ao = aAddr0 + (uint32_t)mt * (16u * WSTR) + (uint32_t)ks * 32u;
                LDSM4(ahi[mt], ao);
                LDSM4(alo[mt], ao + WTILE);
            }
#pragma unroll
            for (int p = 0; p < 4; p++) {
                uint32_t bh[4], bl[4];
                uint32_t bo = bAddr0 + (uint32_t)p * (16u * WSTR) + (uint32_t)ks * 32u;
                LDSM4(bh, bo);
                LDSM4(bl, bo + WTILE);
#pragma unroll
                for (int mt = 0; mt < 2; mt++) {
                    MMA_BF16(acc[mt][2 * p],     ahi[mt], bh[0], bh[1]);
                    MMA_BF16(acc[mt][2 * p],     ahi[mt], bl[0], bl[1]);
                    MMA_BF16(acc[mt][2 * p],     alo[mt], bh[0], bh[1]);
                    MMA_BF16(acc[mt][2 * p + 1], ahi[mt], bh[2], bh[3]);
                    MMA_BF16(acc[mt][2 * p + 1], ahi[mt], bl[2], bl[3]);
                    MMA_BF16(acc[mt][2 * p + 1], alo[mt], bh[2], bh[3]);
                }
            }
        }
    }
    // stage C = Wh tile into fp32 smem [128][CSTR]
    __syncthreads();
    float* Cst = (float*)smem;
#pragma unroll
    for (int mt = 0; mt < 2; mt++) {
#pragma unroll
        for (int nt = 0; nt < 8; nt++) {
            int rl = wm * 32 + mt * 16 + (lane >> 2);
            int cl = wn * 64 + nt * 8 + (lane & 3) * 2;
            *(float2*)(Cst + rl * CSTR + cl)       = *(float2*)&acc[mt][nt][0];
            *(float2*)(Cst + (rl + 8) * CSTR + cl) = *(float2*)&acc[mt][nt][2];
        }
    }
    __syncthreads();
    // f1/f2 + transposed hi/lo stores
    {
        int r = t >> 1, half = (t & 1) * 64;
        float p1 = 0.f, p2 = 0.f;
#pragma unroll
        for (int d = 0; d < 64; d++) {
            float v = Cst[r * CSTR + half + d];
            p1 = fmaf(v, a1s[half + d], p1);
            p2 = fmaf(v, a2s[half + d], p2);
        }
        p1 += __shfl_xor_sync(0xffffffffu, p1, 1);
        p2 += __shfl_xor_sync(0xffffffffu, p2, 1);
        if (!(t & 1)) {
            g_f1[h * NN + i0 + r] = p1;
            g_f2[h * NN + i0 + r] = p2;
        }
    }
    {
        int d = t >> 1, n0 = (t & 1) * 64;
        size_t base = ((size_t)h * ND + d) * NN + i0 + n0;
#pragma unroll
        for (int c = 0; c < 8; c++) {
            uint32_t hp[4], lp[4];
#pragma unroll
            for (int q = 0; q < 8; q += 2) {
                int n = c * 8 + q;
                float w0 = Cst[(n0 + n) * CSTR + d], w1 = Cst[(n0 + n + 1) * CSTR + d];
                __nv_bfloat16 h0 = __float2bfloat16(w0), h1 = __float2bfloat16(w1);
                __nv_bfloat16 l0 = __float2bfloat16(w0 - __bfloat162float(h0));
                __nv_bfloat16 l1 = __float2bfloat16(w1 - __bfloat162float(h1));
                __nv_bfloat162 hh(h0, h1), ll(l0, l1);
                hp[q >> 1] = *(uint32_t*)&hh; lp[q >> 1] = *(uint32_t*)&ll;
            }
            *(uint4*)(g_VhiT + base + c * 8) = *(uint4*)hp;
            *(uint4*)(g_VloT + base + c * 8) = *(uint4*)lp;
        }
    }
}

// ---------------- K4: HMMA masked-softmax aggregation, layer 1 -------------
#define PSTR 272u            // bytes per smem row (136 bf16)
#define TILE_B 34816u        // 128 * 272
#define SMEM_TOT 143360
__global__ __launch_bounds__(256) void k_attn1() {
    extern __shared__ char smem[];
    uint32_t sb = s2u(smem);
    int t = threadIdx.x, lane = t & 31, wid = t >> 5;
    int h = blockIdx.y, i0 = blockIdx.x * 128;
    int wm = wid & 3, wn = wid >> 2;

    float* f2s = (float*)(smem);
    char* mw = smem + 512;
    float* dens = (float*)(smem + 2560);
    uint32_t PHI = sb + 4096, VHI = sb + 73728;

    int rgen = t >> 1, jh64 = (t & 1) * 64;
    float f1r = g_f1[h * NN + i0 + rgen];
    float dacc = 0.f;

    float acc[2][8][4];
#pragma unroll
    for (int mt = 0; mt < 2; mt++)
#pragma unroll
        for (int nt = 0; nt < 8; nt++)
#pragma unroll
            for (int q = 0; q < 4; q++) acc[mt][nt][q] = 0.f;

    uint32_t aAddr0 = PHI + (uint32_t)(wm * 32 + (lane & 15)) * PSTR + (uint32_t)(lane >> 4) * 16u;
    int brow = ((lane >> 4) << 3) + (lane & 7);
    uint32_t bAddr0 = VHI + (uint32_t)(wn * 64 + brow) * PSTR + (uint32_t)((lane >> 3) & 1) * 16u;

    for (int jt = 0; jt < 32; jt++) {
        int j0 = jt * 128;
        __syncthreads();
        if (t < 128) f2s[t] = g_f2[h * NN + j0 + t];
        *(uint2*)(mw + rgen * 16 + (t & 1) * 8) =
            *(const uint2*)(g_mask + (size_t)(i0 + rgen) * NW + jt * 4 + (t & 1) * 2);
#pragma unroll
        for (int c = 0; c < 8; c++) {
            int idx = c * 256 + t;
            int d = idx >> 4, jc = (idx & 15) * 8;
            uint32_t o = (uint32_t)d * PSTR + (uint32_t)jc * 2u;
            size_t g = (size_t)(h * ND + d) * NN + j0 + jc;
            *(float4*)(smem + 73728 + o)  = *(const float4*)(g_VhiT + g);
            *(float4*)(smem + 108544 + o) = *(const float4*)(g_VloT + g);
        }
        __syncthreads();
        uint64_t m64 = *(const uint64_t*)(mw + rgen * 16 + (t & 1) * 8);
#pragma unroll
        for (int g = 0; g < 8; g++) {
            uint32_t ph[4], pl[4];
#pragma unroll
            for (int q = 0; q < 8; q += 2) {
                int b = g * 8 + q;
                float w0 = 0.f, w1 = 0.f;
                if ((m64 >> b) & 1)       { float s = f1r + f2s[jh64 + b];     w0 = __expf(lrelu(s)); }
                if ((m64 >> (b + 1)) & 1) { float s = f1r + f2s[jh64 + b + 1]; w1 = __expf(lrelu(s)); }
                dacc += w0 + w1;
                __nv_bfloat16 h0 = __float2bfloat16(w0), h1 = __float2bfloat16(w1);
                __nv_bfloat16 l0 = __float2bfloat16(w0 - __bfloat162float(h0));
                __nv_bfloat16 l1 = __float2bfloat16(w1 - __bfloat162float(h1));
                __nv_bfloat162 hh(h0, h1), ll(l0, l1);
                ph[q >> 1] = *(uint32_t*)&hh; pl[q >> 1] = *(uint32_t*)&ll;
            }
            uint32_t o = (uint32_t)rgen * PSTR + (uint32_t)(jh64 + g * 8) * 2u;
            *(uint4*)(smem + 4096 + o)  = *(uint4*)ph;
            *(uint4*)(smem + 38912 + o) = *(uint4*)pl;
        }
        __syncthreads();
#pragma unroll
        for (int ks = 0; ks < 8; ks++) {
            uint32_t ahi[2][4], alo[2][4];
#pragma unroll
            for (int mt = 0; mt < 2; mt++) {
                uint32_t ao = aAddr0 + (uint32_t)mt * (16u * PSTR) + (uint32_t)ks * 32u;
                LDSM4(ahi[mt], ao);
                LDSM4(alo[mt], ao + TILE_B);
            }
#pragma unroll
            for (int p = 0; p < 4; p++) {
                uint32_t bh[4], bl[4];
                uint32_t bo = bAddr0 + (uint32_t)p * (16u * PSTR) + (uint32_t)ks * 32u;
                LDSM4(bh, bo);
                LDSM4(bl, bo + TILE_B);
#pragma unroll
                for (int mt = 0; mt < 2; mt++) {
                    MMA_BF16(acc[mt][2 * p],     ahi[mt], bh[0], bh[1]);
                    MMA_BF16(acc[mt][2 * p],     ahi[mt], bl[0], bl[1]);
                    MMA_BF16(acc[mt][2 * p],     alo[mt], bh[0], bh[1]);
                    MMA_BF16(acc[mt][2 * p + 1], ahi[mt], bh[2], bh[3]);
                    MMA_BF16(acc[mt][2 * p + 1], ahi[mt], bl[2], bl[3]);
                    MMA_BF16(acc[mt][2 * p + 1], alo[mt], bh[2], bh[3]);
                }
            }
        }
    }
    dacc += __shfl_xor_sync(0xffffffffu, dacc, 1);
    if (!(t & 1)) dens[rgen] = dacc;
    __syncthreads();
#pragma unroll
    for (int mt = 0; mt < 2; mt++) {
        int rl = wm * 32 + mt * 16 + (lane >> 2);
        float inv0 = 1.f / dens[rl], inv1 = 1.f / dens[rl + 8];
        float* d0 = g_hcat + (size_t)(i0 + rl) * HD + h * ND + wn * 64 + (lane & 3) * 2;
        float* d1 = d0 + (size_t)8 * HD;
#pragma unroll
        for (int nt = 0; nt < 8; nt++) {
            float z0 = acc[mt][nt][0] * inv0, z1 = acc[mt][nt][1] * inv0;
            float z2 = acc[mt][nt][2] * inv1, z3 = acc[mt][nt][3] * inv1;
            float2 o0, o1;
            o0.x = z0 > 0.f ? z0 : (__expf(z0) - 1.f);
            o0.y = z1 > 0.f ? z1 : (__expf(z1) - 1.f);
            o1.x = z2 > 0.f ? z2 : (__expf(z2) - 1.f);
            o1.y = z3 > 0.f ? z3 : (__expf(z3) - 1.f);
            *(float2*)(d0 + nt * 8) = o0;
            *(float2*)(d1 + nt * 8) = o1;
        }
    }
}

// ---------------- K5: Who partials, split-K (64x64 tiles, KC chunks) -------
__global__ __launch_bounds__(256) void k_who(const float* __restrict__ Wo) {
    __shared__ float As[16][68];
    __shared__ float Bs[16][64];
    int i0 = blockIdx.x * 64, kc = blockIdx.y;
    int t = threadIdx.x, ty = t >> 4, tx = t & 15;
    float acc[4][4];
#pragma unroll
    for (int u = 0; u < 4; u++)
#pragma unroll
        for (int v = 0; v < 4; v++) acc[u][v] = 0.f;
    int fbeg = kc * (HD / KC);
    for (int f0 = fbeg; f0 < fbeg + HD / KC; f0 += 16) {
        {
            int row = t >> 2, k4 = (t & 3) * 4;
            float4 v = *(const float4*)(g_hcat + (size_t)(i0 + row) * HD + f0 + k4);
            As[k4 + 0][row] = v.x; As[k4 + 1][row] = v.y;
            As[k4 + 2][row] = v.z; As[k4 + 3][row] = v.w;
        }
        {
            int kk = t >> 4, d4 = (t & 15) * 4;
            *(float4*)&Bs[kk][d4] = *(const float4*)(Wo + (size_t)(f0 + kk) * NC + d4);
        }
        __syncthreads();
#pragma unroll
        for (int k = 0; k < 16; k++) {
            float ra[4], rb[4];
            *(float4*)ra = *(float4*)&As[k][ty * 4];
            *(float4*)rb = *(float4*)&Bs[k][tx * 4];
#pragma unroll
            for (int u = 0; u < 4; u++)
#pragma unroll
                for (int v = 0; v < 4; v++) acc[u][v] = fmaf(ra[u], rb[v], acc[u][v]);
        }
        __syncthreads();
    }
#pragma unroll
    for (int u = 0; u < 4; u++)
        *(float4*)(g_part + ((size_t)kc * NN + i0 + ty * 4 + u) * NC + tx * 4) = *(float4*)&acc[u][0];
}

// ---------------- K6: combine Who partials; g1,g2 = Who . ao1/ao2 ----------
__global__ void k_g(const float* __restrict__ ao1, const float* __restrict__ ao2) {
    int warp = threadIdx.x >> 5, lane = threadIdx.x & 31;
    int n = blockIdx.x * 8 + warp;
    float v0 = 0.f, v1 = 0.f;
#pragma unroll
    for (int kc = 0; kc < KC; kc++) {
        size_t base = ((size_t)kc * NN + n) * NC;
        v0 += g_part[base + lane];
        v1 += g_part[base + lane + 32];
    }
    g_Who[(size_t)n * NC + lane] = v0;
    g_Who[(size_t)n * NC + lane + 32] = v1;
    float s1 = fmaf(v0, ao1[lane], v1 * ao1[lane + 32]);
    float s2 = fmaf(v0, ao2[lane], v1 * ao2[lane + 32]);
#pragma unroll
    for (int o = 16; o; o >>= 1) {
        s1 += __shfl_xor_sync(0xffffffffu, s1, o);
        s2 += __shfl_xor_sync(0xffffffffu, s2, o);
    }
    if (lane == 0) { g_g1[n] = s1; g_g2[n] = s2; }
}

// ---------------- K7: output attention, j-split partials ----------------
__global__ __launch_bounds__(256, 2) void k_attn2() {
    __shared__ float ws[32][128];
    __shared__ float whs[32][64];
    __shared__ unsigned mrow[128];
    __shared__ float g2s[32];
    int jc = blockIdx.y, i0 = blockIdx.x * 128;
    int t = threadIdx.x, ty = t >> 4, tx = t & 15;
    int rgen = t >> 1, jh = (t & 1) * 16;
    float g1r = g_g1[i0 + rgen];
    float dacc = 0.f;
    float acc[8][4];
#pragma unroll
    for (int u = 0; u < 8; u++)
#pragma unroll
        for (int v = 0; v < 4; v++) acc[u][v] = 0.f;

    int jt0 = jc * (NW / JC);
    for (int jt = jt0; jt < jt0 + NW / JC; jt++) {
        int j0 = jt * 32;
        if (t < 32) g2s[t] = g_g2[j0 + t];
        if (t < 128) mrow[t] = g_mask[(size_t)(i0 + t) * NW + jt];
#pragma unroll
        for (int p = 0; p < 2; p++) {
            int idx = p * 256 + t;
            int jj = idx >> 4, d4 = (idx & 15) * 4;
            *(float4*)&whs[jj][d4] = *(const float4*)(g_Who + (size_t)(j0 + jj) * NC + d4);
        }
        __syncthreads();
        unsigned m = mrow[rgen];
        float dloc = 0.f;
#pragma unroll
        for (int q = 0; q < 16; q++) {
            int jj = jh + q;
            float w = ((m >> jj) & 1u) ? __expf(lrelu(g1r + g2s[jj])) : 0.f;
            ws[jj][rgen] = w;
            dloc += w;
        }
        dloc += __shfl_xor_sync(0xffffffffu, dloc, 1);
        if (!(t & 1)) dacc += dloc;
        __syncthreads();
#pragma unroll
        for (int jj = 0; jj < 32; jj++) {
            float rw[8], rb[4];
            *(float4*)(rw)     = *(float4*)&ws[jj][ty * 8];
            *(float4*)(rw + 4) = *(float4*)&ws[jj][ty * 8 + 4];
            *(float4*)rb = *(float4*)&whs[jj][tx * 4];
#pragma unroll
            for (int u = 0; u < 8; u++)
#pragma unroll
                for (int v = 0; v < 4; v++) acc[u][v] = fmaf(rw[u], rb[v], acc[u][v]);
        }
        __syncthreads();
    }
#pragma unroll
    for (int u = 0; u < 8; u++) {
        int r = ty * 8 + u;
        size_t base = ((size_t)jc * NN + i0 + r) * NC + tx * 4;
        *(float4*)(g_part + base) = *(float4*)&acc[u][0];
    }
    if (!(t & 1)) g_dpart[jc * NN + i0 + rgen] = dacc;
}

// ---------------- K8: combine partials + elu + log_softmax ----------------
__global__ void k_final(float* __restrict__ out) {
    int warp = threadIdx.x >> 5, lane = threadIdx.x & 31;
    int n = blockIdx.x * 8 + warp;
    float den = 0.f;
#pragma unroll
    for (int jc = 0; jc < JC; jc++) den += g_dpart[jc * NN + n];
    float inv = 1.f / den;
    float v0 = 0.f, v1 = 0.f;
#pragma unroll
    for (int jc = 0; jc < JC; jc++) {
        size_t base = ((size_t)jc * NN + n) * NC;
        v0 += g_part[base + lane];
        v1 += g_part[base + lane + 32];
    }
    v0 *= inv; v1 *= inv;
    v0 = v0 > 0.f ? v0 : (expf(v0) - 1.f);
    v1 = v1 > 0.f ? v1 : (expf(v1) - 1.f);
    float m = fmaxf(v0, v1);
#pragma unroll
    for (int o = 16; o; o >>= 1) m = fmaxf(m, __shfl_xor_sync(0xffffffffu, m, o));
    float s = expf(v0 - m) + expf(v1 - m);
#pragma unroll
    for (int o = 16; o; o >>= 1) s += __shfl_xor_sync(0xffffffffu, s, o);
    float lse = m + logf(s);
    out[(size_t)n * NC + lane] = v0 - lse;
    out[(size_t)n * NC + lane + 32] = v1 - lse;
}

// ---------------- launch ----------------
extern "C" void kernel_launch(void* const* d_in, const int* in_sizes, int n_in,
                              void* d_out, int out_size) {
    const float* x   = (const float*)d_in[0];
    const int*   adj = (const int*)d_in[1];
    const float* W   = (const float*)d_in[2];
    const float* a1  = (const float*)d_in[3];
    const float* a2  = (const float*)d_in[4];
    const float* Wo  = (const float*)d_in[5];
    const float* ao1 = (const float*)d_in[6];
    const float* ao2 = (const float*)d_in[7];
    float* out = (float*)d_out;

    cudaFuncSetAttribute(k_attn1, cudaFuncAttributeMaxDynamicSharedMemorySize, SMEM_TOT);
    cudaFuncSetAttribute(k_wh, cudaFuncAttributeMaxDynamicSharedMemorySize, SMEM_WH);

    k_pack  <<<NN, 128>>>(adj);
    k_splitx<<<(NN * NF / 4) / 256, 256>>>(x);
    k_splitw<<<dim3(NF / 32, ND / 32, NH), 256>>>(W);
    k_wh    <<<dim3(NN / 128, NH), 256, SMEM_WH>>>(a1, a2);
    k_attn1 <<<dim3(NN / 128, NH), 256, SMEM_TOT>>>();
    k_who   <<<dim3(NN / 64, KC), 256>>>(Wo);
    k_g     <<<NN / 8, 256>>>(ao1, ao2);
    k_attn2 <<<dim3(NN / 128, JC), 256>>>();
    k_final <<<NN / 8, 256>>>(out);
}

// round 6
// speedup vs baseline: 2.7513x; 1.7305x over previous
#include <cuda_runtime.h>
#include <cuda_bf16.h>
#include <cuda_fp16.h>
#include <math.h>
#include <stdint.h>

#define NN 4096
#define NF 1024
#define NH 8
#define ND 128
#define NC 64
#define HD (NH*ND)      // 1024
#define NW (NN/32)      // 128 mask words per row
#define LALPHA 0.2f
#define KC 4            // split-K chunks for k_who
#define JCC 16          // j-split chunks for output attention layer

// ---------------- scratch (static device globals; no allocs) ----------------
__device__ unsigned g_mask[(size_t)NN*NW];         // 2 MB packed adjacency
__device__ __half g_VT[(size_t)NH*ND*NN];          // 8 MB  Wh^T fp16 [h][d][n]
__device__ __nv_bfloat16 g_xhi[(size_t)NN*NF];     // 8 MB  x hi (bf16, k_wh)
__device__ __nv_bfloat16 g_xlo[(size_t)NN*NF];     // 8 MB  x lo
__device__ __nv_bfloat16 g_WThi[(size_t)NH*ND*NF]; // 2 MB  W^T hi [h][d][f]
__device__ __nv_bfloat16 g_WTlo[(size_t)NH*ND*NF]; // 2 MB
__device__ float g_f1[NH*NN];
__device__ float g_f2[NH*NN];
__device__ float g_f2max[NH];
__device__ float g_hcat[(size_t)NN*HD];            // 16 MB  elu(h) concat
__device__ float g_Who[(size_t)NN*NC];             // 1 MB
__device__ __half g_WhoT[(size_t)NC*NN];           // 512 KB Who^T fp16 [c][n]
__device__ float g_g1[NN];
__device__ float g_g2[NN];
__device__ float g_gmax[1];
__device__ float g_part[(size_t)JCC*NN*NC];        // 16 MB partials (who & attn2)
__device__ float g_dpart[JCC*NN];                  // partial denominators

__device__ __forceinline__ float lrelu(float s) { return s > 0.f ? s : LALPHA * s; }

__device__ __forceinline__ uint32_t s2u(const void* p) {
    uint32_t a;
    asm("{ .reg .u64 t; cvta.to.shared.u64 t, %1; cvt.u32.u64 %0, t; }" : "=r"(a) : "l"(p));
    return a;
}

#define LDSM4(r, addr) \
    asm volatile("ldmatrix.sync.aligned.m8n8.x4.shared.b16 {%0,%1,%2,%3}, [%4];" \
        : "=r"((r)[0]), "=r"((r)[1]), "=r"((r)[2]), "=r"((r)[3]) : "r"(addr))

#define MMA_BF16(c, a, b0, b1) \
    asm volatile("mma.sync.aligned.m16n8k16.row.col.f32.bf16.bf16.f32 " \
        "{%0,%1,%2,%3}, {%4,%5,%6,%7}, {%8,%9}, {%0,%1,%2,%3};" \
        : "+f"((c)[0]), "+f"((c)[1]), "+f"((c)[2]), "+f"((c)[3]) \
        : "r"((a)[0]), "r"((a)[1]), "r"((a)[2]), "r"((a)[3]), "r"(b0), "r"(b1))

#define MMA_F16(c, a, b0, b1) \
    asm volatile("mma.sync.aligned.m16n8k16.row.col.f32.f16.f16.f32 " \
        "{%0,%1,%2,%3}, {%4,%5,%6,%7}, {%8,%9}, {%0,%1,%2,%3};" \
        : "+f"((c)[0]), "+f"((c)[1]), "+f"((c)[2]), "+f"((c)[3]) \
        : "r"((a)[0]), "r"((a)[1]), "r"((a)[2]), "r"((a)[3]), "r"(b0), "r"(b1))

#define CP16(dst, src) \
    asm volatile("cp.async.cg.shared.global [%0], [%1], 16;" :: "r"(dst), "l"(src))
#define CPWAITALL() asm volatile("cp.async.wait_all;" ::: "memory")

// ---------------- K1: pack adj -> bitmask ----------------
__global__ void k_pack(const int* __restrict__ adj) {
    int row = blockIdx.x;
    int warp = threadIdx.x >> 5, lane = threadIdx.x & 31;
    const int* ar = adj + (size_t)row * NN;
    for (int w = warp; w < NW; w += 4) {
        unsigned b = __ballot_sync(0xffffffffu, ar[w * 32 + lane] > 0);
        if (lane == 0) g_mask[(size_t)row * NW + w] = b;
    }
}

// ---------------- K1b: split x into bf16 hi/lo ----------------
__global__ void k_splitx(const float* __restrict__ x) {
    int i = blockIdx.x * 256 + threadIdx.x;
    float4 v = *(const float4*)(x + (size_t)i * 4);
    __nv_bfloat16 h0 = __float2bfloat16(v.x), h1 = __float2bfloat16(v.y);
    __nv_bfloat16 h2 = __float2bfloat16(v.z), h3 = __float2bfloat16(v.w);
    __nv_bfloat16 l0 = __float2bfloat16(v.x - __bfloat162float(h0));
    __nv_bfloat16 l1 = __float2bfloat16(v.y - __bfloat162float(h1));
    __nv_bfloat16 l2 = __float2bfloat16(v.z - __bfloat162float(h2));
    __nv_bfloat16 l3 = __float2bfloat16(v.w - __bfloat162float(h3));
    __nv_bfloat162 hh0(h0, h1), hh1(h2, h3), ll0(l0, l1), ll1(l2, l3);
    uint2 ho, lo;
    ho.x = *(uint32_t*)&hh0; ho.y = *(uint32_t*)&hh1;
    lo.x = *(uint32_t*)&ll0; lo.y = *(uint32_t*)&ll1;
    *(uint2*)(g_xhi + (size_t)i * 4) = ho;
    *(uint2*)(g_xlo + (size_t)i * 4) = lo;
}

// ---------------- K1c: W -> W^T hi/lo  [h][f][d] -> [h][d][f] ---------------
__global__ void k_splitw(const float* __restrict__ W) {
    __shared__ float ts[32][33];
    int f0 = blockIdx.x * 32, d0 = blockIdx.y * 32, h = blockIdx.z;
    int t = threadIdx.x;
    int r = t >> 3, c4 = (t & 7) * 4;
    float4 v = *(const float4*)(W + ((size_t)h * NF + f0 + r) * ND + d0 + c4);
    ts[r][c4] = v.x; ts[r][c4 + 1] = v.y; ts[r][c4 + 2] = v.z; ts[r][c4 + 3] = v.w;
    __syncthreads();
    int rr = t >> 3, cc = (t & 7) * 4;
    uint32_t hp[2], lp[2];
#pragma unroll
    for (int q = 0; q < 4; q += 2) {
        float w0 = ts[cc + q][rr], w1 = ts[cc + q + 1][rr];
        __nv_bfloat16 h0 = __float2bfloat16(w0), h1 = __float2bfloat16(w1);
        __nv_bfloat16 l0 = __float2bfloat16(w0 - __bfloat162float(h0));
        __nv_bfloat16 l1 = __float2bfloat16(w1 - __bfloat162float(h1));
        __nv_bfloat162 hh(h0, h1), ll(l0, l1);
        hp[q >> 1] = *(uint32_t*)&hh; lp[q >> 1] = *(uint32_t*)&ll;
    }
    size_t base = ((size_t)h * ND + d0 + rr) * NF + f0 + cc;
    *(uint2*)(g_WThi + base) = *(uint2*)hp;
    *(uint2*)(g_WTlo + base) = *(uint2*)lp;
}

// ---------------- K2: Wh = x @ W via HMMA bf16 3-prod; f1/f2 + V^T fp16 -----
#define WSTR 144u
#define WTILE 18432u
#define SM_AHI 0u
#define SM_ALO 18432u
#define SM_BHI 36864u
#define SM_BLO 55296u
#define SM_A1  73728
#define SM_A2  74240
#define CSTR 130
#define SMEM_WH 74752
__global__ __launch_bounds__(256) void k_wh(const float* __restrict__ a1,
                                            const float* __restrict__ a2) {
    extern __shared__ char smem[];
    uint32_t sb = s2u(smem);
    int t = threadIdx.x, lane = t & 31, wid = t >> 5;
    int h = blockIdx.y, i0 = blockIdx.x * 128;
    int wm = wid & 3, wn = wid >> 2;
    float* a1s = (float*)(smem + SM_A1);
    float* a2s = (float*)(smem + SM_A2);
    if (t < ND) { a1s[t] = a1[h * ND + t]; a2s[t] = a2[h * ND + t]; }

    float acc[2][8][4];
#pragma unroll
    for (int mt = 0; mt < 2; mt++)
#pragma unroll
        for (int nt = 0; nt < 8; nt++)
#pragma unroll
            for (int q = 0; q < 4; q++) acc[mt][nt][q] = 0.f;

    uint32_t aAddr0 = sb + SM_AHI + (uint32_t)(wm * 32 + (lane & 15)) * WSTR + (uint32_t)(lane >> 4) * 16u;
    int brow = ((lane >> 4) << 3) + (lane & 7);
    uint32_t bAddr0 = sb + SM_BHI + (uint32_t)(wn * 64 + brow) * WSTR + (uint32_t)((lane >> 3) & 1) * 16u;

    for (int kt = 0; kt < 16; kt++) {
        int f0 = kt * 64;
        __syncthreads();
#pragma unroll
        for (int c = 0; c < 4; c++) {
            int idx = c * 256 + t;
            int row = idx >> 3, ch = (idx & 7) * 8;
            uint32_t o = (uint32_t)row * WSTR + (uint32_t)ch * 2u;
            size_t ga = (size_t)(i0 + row) * NF + f0 + ch;
            size_t gb = ((size_t)h * ND + row) * NF + f0 + ch;
            *(uint4*)(smem + SM_AHI + o) = *(const uint4*)(g_xhi + ga);
            *(uint4*)(smem + SM_ALO + o) = *(const uint4*)(g_xlo + ga);
            *(uint4*)(smem + SM_BHI + o) = *(const uint4*)(g_WThi + gb);
            *(uint4*)(smem + SM_BLO + o) = *(const uint4*)(g_WTlo + gb);
        }
        __syncthreads();
#pragma unroll
        for (int ks = 0; ks < 4; ks++) {
            uint32_t ahi[2][4], alo[2][4];
#pragma unroll
            for (int mt = 0; mt < 2; mt++) {
                uint32_t ao = aAddr0 + (uint32_t)mt * (16u * WSTR) + (uint32_t)ks * 32u;
                LDSM4(ahi[mt], ao);
                LDSM4(alo[mt], ao + WTILE);
            }
#pragma unroll
            for (int p = 0; p < 4; p++) {
                uint32_t bh[4], bl[4];
                uint32_t bo = bAddr0 + (uint32_t)p * (16u * WSTR) + (uint32_t)ks * 32u;
                LDSM4(bh, bo);
                LDSM4(bl, bo + WTILE);
#pragma unroll
                for (int mt = 0; mt < 2; mt++) {
                    MMA_BF16(acc[mt][2 * p],     ahi[mt], bh[0], bh[1]);
                    MMA_BF16(acc[mt][2 * p],     ahi[mt], bl[0], bl[1]);
                    MMA_BF16(acc[mt][2 * p],     alo[mt], bh[0], bh[1]);
                    MMA_BF16(acc[mt][2 * p + 1], ahi[mt], bh[2], bh[3]);
                    MMA_BF16(acc[mt][2 * p + 1], ahi[mt], bl[2], bl[3]);
                    MMA_BF16(acc[mt][2 * p + 1], alo[mt], bh[2], bh[3]);
                }
            }
        }
    }
    __syncthreads();
    float* Cst = (float*)smem;
#pragma unroll
    for (int mt = 0; mt < 2; mt++) {
#pragma unroll
        for (int nt = 0; nt < 8; nt++) {
            int rl = wm * 32 + mt * 16 + (lane >> 2);
            int cl = wn * 64 + nt * 8 + (lane & 3) * 2;
            *(float2*)(Cst + rl * CSTR + cl)       = *(float2*)&acc[mt][nt][0];
            *(float2*)(Cst + (rl + 8) * CSTR + cl) = *(float2*)&acc[mt][nt][2];
        }
    }
    __syncthreads();
    {
        int r = t >> 1, half = (t & 1) * 64;
        float p1 = 0.f, p2 = 0.f;
#pragma unroll
        for (int d = 0; d < 64; d++) {
            float v = Cst[r * CSTR + half + d];
            p1 = fmaf(v, a1s[half + d], p1);
            p2 = fmaf(v, a2s[half + d], p2);
        }
        p1 += __shfl_xor_sync(0xffffffffu, p1, 1);
        p2 += __shfl_xor_sync(0xffffffffu, p2, 1);
        if (!(t & 1)) {
            g_f1[h * NN + i0 + r] = p1;
            g_f2[h * NN + i0 + r] = p2;
        }
    }
    {
        int d = t >> 1, n0 = (t & 1) * 64;
        size_t base = ((size_t)h * ND + d) * NN + i0 + n0;
#pragma unroll
        for (int c = 0; c < 8; c++) {
            uint32_t hp[4];
#pragma unroll
            for (int q = 0; q < 8; q += 2) {
                int n = c * 8 + q;
                __half2 hh = __floats2half2_rn(Cst[(n0 + n) * CSTR + d],
                                               Cst[(n0 + n + 1) * CSTR + d]);
                hp[q >> 1] = *(uint32_t*)&hh;
            }
            *(uint4*)(g_VT + base + c * 8) = *(uint4*)hp;
        }
    }
}

// ---------------- K2b: per-head max of f2 ----------------
__global__ void k_fmax() {
    __shared__ float red[256];
    int h = blockIdx.x, t = threadIdx.x;
    float m = -1e30f;
    for (int i = t; i < NN; i += 256) m = fmaxf(m, g_f2[h * NN + i]);
    red[t] = m; __syncthreads();
    for (int s = 128; s; s >>= 1) { if (t < s) red[t] = fmaxf(red[t], red[t + s]); __syncthreads(); }
    if (t == 0) g_f2max[h] = red[0];
}

// ---------------- K4: fp16 2-product masked-softmax aggregation, layer 1 ---
// P = exp(lrelu(f1+f2)-shift) in (0,1]; split fp16 hi/lo; V single fp16.
// smem: dens[256f]@0, PHI@1024, PLO@35840, V@70656; total 105472. occ 2.
#define PSTR 272u
#define A1_PHI 1024u
#define A1_PLO 35840u
#define A1_V   70656u
#define SMEM_A1 105472
__global__ __launch_bounds__(256, 2) void k_attn1() {
    extern __shared__ char smem[];
    uint32_t sb = s2u(smem);
    int t = threadIdx.x, lane = t & 31, wid = t >> 5;
    int h = blockIdx.y, i0 = blockIdx.x * 128;
    int wm = wid & 3, wn = wid >> 2;
    float* dens = (float*)smem;

    int row = t & 127, jh64 = (t >> 7) * 64;
    float f1r = g_f1[h * NN + i0 + row];
    float sh = lrelu(f1r + g_f2max[h]);
    float dacc = 0.f;

    float acc[2][8][4];
#pragma unroll
    for (int mt = 0; mt < 2; mt++)
#pragma unroll
        for (int nt = 0; nt < 8; nt++)
#pragma unroll
            for (int q = 0; q < 4; q++) acc[mt][nt][q] = 0.f;

    uint32_t aAddrH = sb + A1_PHI + (uint32_t)(wm * 32 + (lane & 15)) * PSTR + (uint32_t)(lane >> 4) * 16u;
    uint32_t aAddrL = aAddrH + (A1_PLO - A1_PHI);
    int brow = ((lane >> 4) << 3) + (lane & 7);
    uint32_t bAddr0 = sb + A1_V + (uint32_t)(wn * 64 + brow) * PSTR + (uint32_t)((lane >> 3) & 1) * 16u;

    const float* f2p = g_f2 + h * NN;
    const unsigned* mrow = g_mask + (size_t)(i0 + row) * NW + (jh64 >> 5);
    float pv0 = f2p[jh64 + lane];
    float pv1 = f2p[jh64 + 32 + lane];
    uint2 pm = *(const uint2*)mrow;

    for (int jt = 0; jt < 32; jt++) {
        int j0 = jt * 128;
        __syncthreads();
        // stage V via cp.async (latency hidden under P-gen)
#pragma unroll
        for (int c = 0; c < 9; c++) {
            int idx = c * 256 + t;
            if (idx < 2176) {
                int r = idx / 17, ch = idx - r * 17;
                CP16(sb + A1_V + (uint32_t)r * PSTR + (uint32_t)ch * 16u,
                     g_VT + ((size_t)(h * ND + r)) * NN + j0 + ch * 8);
            }
        }
        float fv0 = pv0, fv1 = pv1;
        uint64_t m64 = ((uint64_t)pm.y << 32) | pm.x;
        // P-gen: 64 cols per thread (fp16 hi/lo)
#pragma unroll
        for (int g = 0; g < 8; g++) {
            uint32_t ph[4], pl[4];
#pragma unroll
            for (int q = 0; q < 8; q += 2) {
                int c = g * 8 + q;
                float a = __shfl_sync(0xffffffffu, (c < 32) ? fv0 : fv1, c & 31);
                float b = __shfl_sync(0xffffffffu, (c + 1 < 32) ? fv0 : fv1, (c + 1) & 31);
                float w0 = 0.f, w1 = 0.f;
                if ((m64 >> c) & 1)       w0 = __expf(lrelu(f1r + a) - sh);
                if ((m64 >> (c + 1)) & 1) w1 = __expf(lrelu(f1r + b) - sh);
                dacc += w0 + w1;
                __half h0 = __float2half_rn(w0), h1 = __float2half_rn(w1);
                __half l0 = __float2half_rn(w0 - __half2float(h0));
                __half l1 = __float2half_rn(w1 - __half2float(h1));
                __half2 hh = __halves2half2(h0, h1), ll = __halves2half2(l0, l1);
                ph[q >> 1] = *(uint32_t*)&hh; pl[q >> 1] = *(uint32_t*)&ll;
            }
            uint32_t o = (uint32_t)row * PSTR + (uint32_t)(jh64 + g * 8) * 2u;
            *(uint4*)(smem + A1_PHI + o) = *(uint4*)ph;
            *(uint4*)(smem + A1_PLO + o) = *(uint4*)pl;
        }
        // prefetch next tile's f2/mask
        if (jt < 31) {
            pv0 = f2p[j0 + 128 + jh64 + lane];
            pv1 = f2p[j0 + 128 + jh64 + 32 + lane];
            pm = *(const uint2*)(mrow + (jt + 1) * 4);
        }
        CPWAITALL();
        __syncthreads();
        // MMA: 2 products (Ph*V + Pl*V)
#pragma unroll
        for (int ks = 0; ks < 8; ks++) {
            uint32_t ah[2][4], al[2][4];
#pragma unroll
            for (int mt = 0; mt < 2; mt++) {
                uint32_t ao = (uint32_t)mt * (16u * PSTR) + (uint32_t)ks * 32u;
                LDSM4(ah[mt], aAddrH + ao);
                LDSM4(al[mt], aAddrL + ao);
            }
#pragma unroll
            for (int p = 0; p < 4; p++) {
                uint32_t bb[4];
                LDSM4(bb, bAddr0 + (uint32_t)p * (16u * PSTR) + (uint32_t)ks * 32u);
#pragma unroll
                for (int mt = 0; mt < 2; mt++) {
                    MMA_F16(acc[mt][2 * p],     ah[mt], bb[0], bb[1]);
                    MMA_F16(acc[mt][2 * p],     al[mt], bb[0], bb[1]);
                    MMA_F16(acc[mt][2 * p + 1], ah[mt], bb[2], bb[3]);
                    MMA_F16(acc[mt][2 * p + 1], al[mt], bb[2], bb[3]);
                }
            }
        }
    }
    dens[t] = dacc;
    __syncthreads();
#pragma unroll
    for (int mt = 0; mt < 2; mt++) {
        int rl = wm * 32 + mt * 16 + (lane >> 2);
        float inv0 = 1.f / (dens[rl] + dens[128 + rl]);
        float inv1 = 1.f / (dens[rl + 8] + dens[128 + rl + 8]);
        float* d0 = g_hcat + (size_t)(i0 + rl) * HD + h * ND + wn * 64 + (lane & 3) * 2;
        float* d1 = d0 + (size_t)8 * HD;
#pragma unroll
        for (int nt = 0; nt < 8; nt++) {
            float z0 = acc[mt][nt][0] * inv0, z1 = acc[mt][nt][1] * inv0;
            float z2 = acc[mt][nt][2] * inv1, z3 = acc[mt][nt][3] * inv1;
            float2 o0, o1;
            o0.x = z0 > 0.f ? z0 : (__expf(z0) - 1.f);
            o0.y = z1 > 0.f ? z1 : (__expf(z1) - 1.f);
            o1.x = z2 > 0.f ? z2 : (__expf(z2) - 1.f);
            o1.y = z3 > 0.f ? z3 : (__expf(z3) - 1.f);
            *(float2*)(d0 + nt * 8) = o0;
            *(float2*)(d1 + nt * 8) = o1;
        }
    }
}

// ---------------- K5: Who partials, split-K (64x64 tiles, KC chunks) -------
__global__ __launch_bounds__(256) void k_who(const float* __restrict__ Wo) {
    __shared__ float As[16][68];
    __shared__ float Bs[16][64];
    int i0 = blockIdx.x * 64, kc = blockIdx.y;
    int t = threadIdx.x, ty = t >> 4, tx = t & 15;
    float acc[4][4];
#pragma unroll
    for (int u = 0; u < 4; u++)
#pragma unroll
        for (int v = 0; v < 4; v++) acc[u][v] = 0.f;
    int fbeg = kc * (HD / KC);
    for (int f0 = fbeg; f0 < fbeg + HD / KC; f0 += 16) {
        {
            int r = t >> 2, k4 = (t & 3) * 4;
            float4 v = *(const float4*)(g_hcat + (size_t)(i0 + r) * HD + f0 + k4);
            As[k4 + 0][r] = v.x; As[k4 + 1][r] = v.y;
            As[k4 + 2][r] = v.z; As[k4 + 3][r] = v.w;
        }
        {
            int kk = t >> 4, d4 = (t & 15) * 4;
            *(float4*)&Bs[kk][d4] = *(const float4*)(Wo + (size_t)(f0 + kk) * NC + d4);
        }
        __syncthreads();
#pragma unroll
        for (int k = 0; k < 16; k++) {
            float ra[4], rb[4];
            *(float4*)ra = *(float4*)&As[k][ty * 4];
            *(float4*)rb = *(float4*)&Bs[k][tx * 4];
#pragma unroll
            for (int u = 0; u < 4; u++)
#pragma unroll
                for (int v = 0; v < 4; v++) acc[u][v] = fmaf(ra[u], rb[v], acc[u][v]);
        }
        __syncthreads();
    }
#pragma unroll
    for (int u = 0; u < 4; u++)
        *(float4*)(g_part + ((size_t)kc * NN + i0 + ty * 4 + u) * NC + tx * 4) = *(float4*)&acc[u][0];
}

// ---------------- K6: combine Who partials; g1,g2 ----------------
__global__ void k_g(const float* __restrict__ ao1, const float* __restrict__ ao2) {
    int warp = threadIdx.x >> 5, lane = threadIdx.x & 31;
    int n = blockIdx.x * 8 + warp;
    float v0 = 0.f, v1 = 0.f;
#pragma unroll
    for (int kc = 0; kc < KC; kc++) {
        size_t base = ((size_t)kc * NN + n) * NC;
        v0 += g_part[base + lane];
        v1 += g_part[base + lane + 32];
    }
    g_Who[(size_t)n * NC + lane] = v0;
    g_Who[(size_t)n * NC + lane + 32] = v1;
    float s1 = fmaf(v0, ao1[lane], v1 * ao1[lane + 32]);
    float s2 = fmaf(v0, ao2[lane], v1 * ao2[lane + 32]);
#pragma unroll
    for (int o = 16; o; o >>= 1) {
        s1 += __shfl_xor_sync(0xffffffffu, s1, o);
        s2 += __shfl_xor_sync(0xffffffffu, s2, o);
    }
    if (lane == 0) { g_g1[n] = s1; g_g2[n] = s2; }
}

// ---------------- K6b: global max of g2 ----------------
__global__ void k_gmax() {
    __shared__ float red[256];
    int t = threadIdx.x;
    float m = -1e30f;
    for (int i = t; i < NN; i += 256) m = fmaxf(m, g_g2[i]);
    red[t] = m; __syncthreads();
    for (int s = 128; s; s >>= 1) { if (t < s) red[t] = fmaxf(red[t], red[t + s]); __syncthreads(); }
    if (t == 0) g_gmax[0] = red[0];
}

// ---------------- K6c: Who -> Who^T fp16 [c][n] ----------------
__global__ void k_whoT() {
    __shared__ float ts[64][65];
    int n0 = blockIdx.x * 64, t = threadIdx.x;
#pragma unroll
    for (int k = 0; k < 16; k++) {
        int idx = k * 256 + t;
        int r = idx >> 6, c = idx & 63;
        ts[r][c] = g_Who[(size_t)(n0 + r) * NC + c];
    }
    __syncthreads();
    int c = t >> 2, nq = (t & 3) * 16;
    uint32_t hp[8];
#pragma unroll
    for (int q = 0; q < 16; q += 2) {
        __half2 hh = __floats2half2_rn(ts[nq + q][c], ts[nq + q + 1][c]);
        hp[q >> 1] = *(uint32_t*)&hh;
    }
    *(uint4*)(g_WhoT + (size_t)c * NN + n0 + nq)     = *(uint4*)hp;
    *(uint4*)(g_WhoT + (size_t)c * NN + n0 + nq + 8) = *(uint4*)(hp + 4);
}

// ---------------- K7: output attention via fp16 HMMA, j-split --------------
// grid (32, JCC); CTA: 128 i-rows x 64 cols, j-chunk = 256 (2 tiles of 128).
// smem: dens@0[1024], PHI@1024, PLO@35840, B@70656[64*272]; total 88064. occ 2.
#define A2_PHI 1024u
#define A2_PLO 35840u
#define A2_B   70656u
#define SMEM_A2 88064
__global__ __launch_bounds__(256, 2) void k_attn2() {
    extern __shared__ char smem[];
    uint32_t sb = s2u(smem);
    int t = threadIdx.x, lane = t & 31, wid = t >> 5;
    int jcc = blockIdx.y, i0 = blockIdx.x * 128;
    int wm = wid & 3, wn = wid >> 2;
    float* dens = (float*)smem;

    int row = t & 127, jh64 = (t >> 7) * 64;
    float g1r = g_g1[i0 + row];
    float sh = lrelu(g1r + g_gmax[0]);
    float dacc = 0.f;

    float acc[2][4][4];
#pragma unroll
    for (int mt = 0; mt < 2; mt++)
#pragma unroll
        for (int nt = 0; nt < 4; nt++)
#pragma unroll
            for (int q = 0; q < 4; q++) acc[mt][nt][q] = 0.f;

    uint32_t aAddrH = sb + A2_PHI + (uint32_t)(wm * 32 + (lane & 15)) * PSTR + (uint32_t)(lane >> 4) * 16u;
    uint32_t aAddrL = aAddrH + (A2_PLO - A2_PHI);
    int brow = ((lane >> 4) << 3) + (lane & 7);
    uint32_t bAddr0 = sb + A2_B + (uint32_t)(wn * 32 + brow) * PSTR + (uint32_t)((lane >> 3) & 1) * 16u;

    const unsigned* mrow = g_mask + (size_t)(i0 + row) * NW + (jh64 >> 5);

    for (int jj = 0; jj < 2; jj++) {
        int jt = jcc * 2 + jj, j0 = jt * 128;
        __syncthreads();
#pragma unroll
        for (int c = 0; c < 5; c++) {
            int idx = c * 256 + t;
            if (idx < 1088) {
                int r = idx / 17, ch = idx - r * 17;
                CP16(sb + A2_B + (uint32_t)r * PSTR + (uint32_t)ch * 16u,
                     g_WhoT + (size_t)r * NN + j0 + ch * 8);
            }
        }
        float fv0 = g_g2[j0 + jh64 + lane];
        float fv1 = g_g2[j0 + jh64 + 32 + lane];
        uint2 pm = *(const uint2*)(mrow + jt * 4);
        uint64_t m64 = ((uint64_t)pm.y << 32) | pm.x;
#pragma unroll
        for (int g = 0; g < 8; g++) {
            uint32_t ph[4], pl[4];
#pragma unroll
            for (int q = 0; q < 8; q += 2) {
                int c = g * 8 + q;
                float a = __shfl_sync(0xffffffffu, (c < 32) ? fv0 : fv1, c & 31);
                float b = __shfl_sync(0xffffffffu, (c + 1 < 32) ? fv0 : fv1, (c + 1) & 31);
                float w0 = 0.f, w1 = 0.f;
                if ((m64 >> c) & 1)       w0 = __expf(lrelu(g1r + a) - sh);
                if ((m64 >> (c + 1)) & 1) w1 = __expf(lrelu(g1r + b) - sh);
                dacc += w0 + w1;
                __half h0 = __float2half_rn(w0), h1 = __float2half_rn(w1);
                __half l0 = __float2half_rn(w0 - __half2float(h0));
                __half l1 = __float2half_rn(w1 - __half2float(h1));
                __half2 hh = __halves2half2(h0, h1), ll = __halves2half2(l0, l1);
                ph[q >> 1] = *(uint32_t*)&hh; pl[q >> 1] = *(uint32_t*)&ll;
            }
            uint32_t o = (uint32_t)row * PSTR + (uint32_t)(jh64 + g * 8) * 2u;
            *(uint4*)(smem + A2_PHI + o) = *(uint4*)ph;
            *(uint4*)(smem + A2_PLO + o) = *(uint4*)pl;
        }
        CPWAITALL();
        __syncthreads();
#pragma unroll
        for (int ks = 0; ks < 8; ks++) {
            uint32_t ah[2][4], al[2][4];
#pragma unroll
            for (int mt = 0; mt < 2; mt++) {
                uint32_t ao = (uint32_t)mt * (16u * PSTR) + (uint32_t)ks * 32u;
                LDSM4(ah[mt], aAddrH + ao);
                LDSM4(al[mt], aAddrL + ao);
            }
#pragma unroll
            for (int p = 0; p < 2; p++) {
                uint32_t bb[4];
                LDSM4(bb, bAddr0 + (uint32_t)p * (16u * PSTR) + (uint32_t)ks * 32u);
#pragma unroll
                for (int mt = 0; mt < 2; mt++) {
                    MMA_F16(acc[mt][2 * p],     ah[mt], bb[0], bb[1]);
                    MMA_F16(acc[mt][2 * p],     al[mt], bb[0], bb[1]);
                    MMA_F16(acc[mt][2 * p + 1], ah[mt], bb[2], bb[3]);
                    MMA_F16(acc[mt][2 * p + 1], al[mt], bb[2], bb[3]);
                }
            }
        }
    }
    dens[t] = dacc;
    __syncthreads();
#pragma unroll
    for (int mt = 0; mt < 2; mt++) {
        int rl = wm * 32 + mt * 16 + (lane >> 2);
        int cl = wn * 32 + (lane & 3) * 2;
#pragma unroll
        for (int nt = 0; nt < 4; nt++) {
            size_t b0 = ((size_t)jcc * NN + i0 + rl) * NC + cl + nt * 8;
            *(float2*)(g_part + b0)                    = *(float2*)&acc[mt][nt][0];
            *(float2*)(g_part + b0 + (size_t)8 * NC)   = *(float2*)&acc[mt][nt][2];
        }
    }
    if (t < 128) g_dpart[jcc * NN + i0 + t] = dens[t] + dens[128 + t];
}

// ---------------- K8: combine partials + elu + log_softmax ----------------
__global__ void k_final(float* __restrict__ out) {
    int warp = threadIdx.x >> 5, lane = threadIdx.x & 31;
    int n = blockIdx.x * 8 + warp;
    float den = 0.f;
#pragma unroll
    for (int jc = 0; jc < JCC; jc++) den += g_dpart[jc * NN + n];
    float inv = 1.f / den;
    float v0 = 0.f, v1 = 0.f;
#pragma unroll
    for (int jc = 0; jc < JCC; jc++) {
        size_t base = ((size_t)jc * NN + n) * NC;
        v0 += g_part[base + lane];
        v1 += g_part[base + lane + 32];
    }
    v0 *= inv; v1 *= inv;
    v0 = v0 > 0.f ? v0 : (expf(v0) - 1.f);
    v1 = v1 > 0.f ? v1 : (expf(v1) - 1.f);
    float m = fmaxf(v0, v1);
#pragma unroll
    for (int o = 16; o; o >>= 1) m = fmaxf(m, __shfl_xor_sync(0xffffffffu, m, o));
    float s = expf(v0 - m) + expf(v1 - m);
#pragma unroll
    for (int o = 16; o; o >>= 1) s += __shfl_xor_sync(0xffffffffu, s, o);
    float lse = m + logf(s);
    out[(size_t)n * NC + lane] = v0 - lse;
    out[(size_t)n * NC + lane + 32] = v1 - lse;
}

// ---------------- launch ----------------
extern "C" void kernel_launch(void* const* d_in, const int* in_sizes, int n_in,
                              void* d_out, int out_size) {
    const float* x   = (const float*)d_in[0];
    const int*   adj = (const int*)d_in[1];
    const float* W   = (const float*)d_in[2];
    const float* a1  = (const float*)d_in[3];
    const float* a2  = (const float*)d_in[4];
    const float* Wo  = (const float*)d_in[5];
    const float* ao1 = (const float*)d_in[6];
    const float* ao2 = (const float*)d_in[7];
    float* out = (float*)d_out;

    cudaFuncSetAttribute(k_wh, cudaFuncAttributeMaxDynamicSharedMemorySize, SMEM_WH);
    cudaFuncSetAttribute(k_attn1, cudaFuncAttributeMaxDynamicSharedMemorySize, SMEM_A1);
    cudaFuncSetAttribute(k_attn2, cudaFuncAttributeMaxDynamicSharedMemorySize, SMEM_A2);

    k_pack  <<<NN, 128>>>(adj);
    k_splitx<<<(NN * NF / 4) / 256, 256>>>(x);
    k_splitw<<<dim3(NF / 32, ND / 32, NH), 256>>>(W);
    k_wh    <<<dim3(NN / 128, NH), 256, SMEM_WH>>>(a1, a2);
    k_fmax  <<<NH, 256>>>();
    k_attn1 <<<dim3(NN / 128, NH), 256, SMEM_A1>>>();
    k_who   <<<dim3(NN / 64, KC), 256>>>(Wo);
    k_g     <<<NN / 8, 256>>>(ao1, ao2);
    k_gmax  <<<1, 256>>>();
    k_whoT  <<<NN / 64, 256>>>();
    k_attn2 <<<dim3(NN / 128, JCC), 256, SMEM_A2>>>();
    k_final <<<NN / 8, 256>>>(out);
}

// round 7
// speedup vs baseline: 3.3349x; 1.2121x over previous
#include <cuda_runtime.h>
#include <cuda_fp16.h>
#include <math.h>
#include <stdint.h>

#define NN 4096
#define NF 1024
#define NH 8
#define ND 128
#define NC 64
#define HD (NH*ND)      // 1024
#define NW (NN/32)      // 128 mask words per row
#define LALPHA 0.2f
#define KC 4            // split-K chunks for k_who
#define JCC 16          // j-split chunks for output attention layer

// ---------------- scratch (static device globals; no allocs) ----------------
__device__ unsigned g_mask[(size_t)NN*NW];         // 2 MB packed adjacency
__device__ __half g_VT[(size_t)NH*ND*NN];          // 8 MB  Wh^T fp16 [h][d][n]
__device__ __half g_xhi[(size_t)NN*NF];            // 8 MB  x hi fp16
__device__ __half g_xlo[(size_t)NN*NF];            // 8 MB  x lo fp16
__device__ __half g_WT[(size_t)NH*ND*NF];          // 2 MB  W^T fp16 [h][d][f]
__device__ float g_f1[NH*NN];
__device__ float g_f2[NH*NN];
__device__ float g_f2max[NH];
__device__ float g_hcat[(size_t)NN*HD];            // 16 MB  elu(h) concat
__device__ float g_Who[(size_t)NN*NC];             // 1 MB
__device__ __half g_WhoT[(size_t)NC*NN];           // 512 KB Who^T fp16 [c][n]
__device__ float g_g1[NN];
__device__ float g_g2[NN];
__device__ float g_gmax[1];
__device__ float g_part[(size_t)JCC*NN*NC];        // 16 MB partials (who & attn2)
__device__ float g_dpart[JCC*NN];                  // partial denominators

__device__ __forceinline__ float lrelu(float s) { return s > 0.f ? s : LALPHA * s; }

__device__ __forceinline__ uint32_t s2u(const void* p) {
    uint32_t a;
    asm("{ .reg .u64 t; cvta.to.shared.u64 t, %1; cvt.u32.u64 %0, t; }" : "=r"(a) : "l"(p));
    return a;
}

#define LDSM4(r, addr) \
    asm volatile("ldmatrix.sync.aligned.m8n8.x4.shared.b16 {%0,%1,%2,%3}, [%4];" \
        : "=r"((r)[0]), "=r"((r)[1]), "=r"((r)[2]), "=r"((r)[3]) : "r"(addr))

#define MMA_F16(c, a, b0, b1) \
    asm volatile("mma.sync.aligned.m16n8k16.row.col.f32.f16.f16.f32 " \
        "{%0,%1,%2,%3}, {%4,%5,%6,%7}, {%8,%9}, {%0,%1,%2,%3};" \
        : "+f"((c)[0]), "+f"((c)[1]), "+f"((c)[2]), "+f"((c)[3]) \
        : "r"((a)[0]), "r"((a)[1]), "r"((a)[2]), "r"((a)[3]), "r"(b0), "r"(b1))

#define CP16(dst, src) \
    asm volatile("cp.async.cg.shared.global [%0], [%1], 16;" :: "r"(dst), "l"(src))
#define CPWAITALL() asm volatile("cp.async.wait_all;" ::: "memory")

// pack two floats to half2: lo=w0, hi=w1
#define F16X2(d, w0, w1) \
    asm("cvt.rn.f16x2.f32 %0, %1, %2;" : "=r"(d) : "f"(w1), "f"(w0))

// ---------------- K1: pack adj -> bitmask ----------------
__global__ void k_pack(const int* __restrict__ adj) {
    int row = blockIdx.x;
    int warp = threadIdx.x >> 5, lane = threadIdx.x & 31;
    const int* ar = adj + (size_t)row * NN;
    for (int w = warp; w < NW; w += 4) {
        unsigned b = __ballot_sync(0xffffffffu, ar[w * 32 + lane] > 0);
        if (lane == 0) g_mask[(size_t)row * NW + w] = b;
    }
}

// ---------------- K1b: split x into fp16 hi/lo ----------------
__global__ void k_splitx(const float* __restrict__ x) {
    int i = blockIdx.x * 256 + threadIdx.x;
    float4 v = *(const float4*)(x + (size_t)i * 4);
    uint2 ho, lo;
    F16X2(ho.x, v.x, v.y);
    F16X2(ho.y, v.z, v.w);
    __half2 h0 = *(__half2*)&ho.x, h1 = *(__half2*)&ho.y;
    F16X2(lo.x, v.x - __low2float(h0), v.y - __high2float(h0));
    F16X2(lo.y, v.z - __low2float(h1), v.w - __high2float(h1));
    *(uint2*)(g_xhi + (size_t)i * 4) = ho;
    *(uint2*)(g_xlo + (size_t)i * 4) = lo;
}

// ---------------- K1c: W -> W^T fp16  [h][f][d] -> [h][d][f] ---------------
__global__ void k_splitw(const float* __restrict__ W) {
    __shared__ float ts[32][33];
    int f0 = blockIdx.x * 32, d0 = blockIdx.y * 32, h = blockIdx.z;
    int t = threadIdx.x;
    int r = t >> 3, c4 = (t & 7) * 4;
    float4 v = *(const float4*)(W + ((size_t)h * NF + f0 + r) * ND + d0 + c4);
    ts[r][c4] = v.x; ts[r][c4 + 1] = v.y; ts[r][c4 + 2] = v.z; ts[r][c4 + 3] = v.w;
    __syncthreads();
    int rr = t >> 3, cc = (t & 7) * 4;
    uint2 hp;
    F16X2(hp.x, ts[cc][rr], ts[cc + 1][rr]);
    F16X2(hp.y, ts[cc + 2][rr], ts[cc + 3][rr]);
    *(uint2*)(g_WT + ((size_t)h * ND + d0 + rr) * NF + f0 + cc) = hp;
}

// ---------------- K2: Wh = x @ W via fp16 HMMA 2-prod; f1/f2 + V^T ---------
#define WSTR 144u
#define WTILE 18432u
#define SM_AHI 0u
#define SM_ALO 18432u
#define SM_B   36864u
#define CSTR 130
#define SM_A1  66560
#define SM_A2  67072
#define SMEM_WH 67584
__global__ __launch_bounds__(256) void k_wh(const float* __restrict__ a1,
                                            const float* __restrict__ a2) {
    extern __shared__ char smem[];
    uint32_t sb = s2u(smem);
    int t = threadIdx.x, lane = t & 31, wid = t >> 5;
    int h = blockIdx.y, i0 = blockIdx.x * 128;
    int wm = wid & 3, wn = wid >> 2;
    float* a1s = (float*)(smem + SM_A1);
    float* a2s = (float*)(smem + SM_A2);
    if (t < ND) { a1s[t] = a1[h * ND + t]; a2s[t] = a2[h * ND + t]; }

    float acc[2][8][4];
#pragma unroll
    for (int mt = 0; mt < 2; mt++)
#pragma unroll
        for (int nt = 0; nt < 8; nt++)
#pragma unroll
            for (int q = 0; q < 4; q++) acc[mt][nt][q] = 0.f;

    uint32_t aAddr0 = sb + SM_AHI + (uint32_t)(wm * 32 + (lane & 15)) * WSTR + (uint32_t)(lane >> 4) * 16u;
    int brow = ((lane >> 4) << 3) + (lane & 7);
    uint32_t bAddr0 = sb + SM_B + (uint32_t)(wn * 64 + brow) * WSTR + (uint32_t)((lane >> 3) & 1) * 16u;

    for (int kt = 0; kt < 16; kt++) {
        int f0 = kt * 64;
        __syncthreads();
#pragma unroll
        for (int c = 0; c < 4; c++) {
            int idx = c * 256 + t;
            int row = idx >> 3, ch = (idx & 7) * 8;
            uint32_t o = (uint32_t)row * WSTR + (uint32_t)ch * 2u;
            size_t ga = (size_t)(i0 + row) * NF + f0 + ch;
            size_t gb = ((size_t)h * ND + row) * NF + f0 + ch;
            *(uint4*)(smem + SM_AHI + o) = *(const uint4*)(g_xhi + ga);
            *(uint4*)(smem + SM_ALO + o) = *(const uint4*)(g_xlo + ga);
            *(uint4*)(smem + SM_B + o)   = *(const uint4*)(g_WT + gb);
        }
        __syncthreads();
#pragma unroll
        for (int ks = 0; ks < 4; ks++) {
            uint32_t ah[2][4], al[2][4];
#pragma unroll
            for (int mt = 0; mt < 2; mt++) {
                uint32_t ao = aAddr0 + (uint32_t)mt * (16u * WSTR) + (uint32_t)ks * 32u;
                LDSM4(ah[mt], ao);
                LDSM4(al[mt], ao + WTILE);
            }
#pragma unroll
            for (int p = 0; p < 4; p++) {
                uint32_t bb[4];
                LDSM4(bb, bAddr0 + (uint32_t)p * (16u * WSTR) + (uint32_t)ks * 32u);
#pragma unroll
                for (int mt = 0; mt < 2; mt++) {
                    MMA_F16(acc[mt][2 * p],     ah[mt], bb[0], bb[1]);
                    MMA_F16(acc[mt][2 * p],     al[mt], bb[0], bb[1]);
                    MMA_F16(acc[mt][2 * p + 1], ah[mt], bb[2], bb[3]);
                    MMA_F16(acc[mt][2 * p + 1], al[mt], bb[2], bb[3]);
                }
            }
        }
    }
    __syncthreads();
    float* Cst = (float*)smem;
#pragma unroll
    for (int mt = 0; mt < 2; mt++) {
#pragma unroll
        for (int nt = 0; nt < 8; nt++) {
            int rl = wm * 32 + mt * 16 + (lane >> 2);
            int cl = wn * 64 + nt * 8 + (lane & 3) * 2;
            *(float2*)(Cst + rl * CSTR + cl)       = *(float2*)&acc[mt][nt][0];
            *(float2*)(Cst + (rl + 8) * CSTR + cl) = *(float2*)&acc[mt][nt][2];
        }
    }
    __syncthreads();
    {
        int r = t >> 1, half = (t & 1) * 64;
        float p1 = 0.f, p2 = 0.f;
#pragma unroll
        for (int d = 0; d < 64; d++) {
            float v = Cst[r * CSTR + half + d];
            p1 = fmaf(v, a1s[half + d], p1);
            p2 = fmaf(v, a2s[half + d], p2);
        }
        p1 += __shfl_xor_sync(0xffffffffu, p1, 1);
        p2 += __shfl_xor_sync(0xffffffffu, p2, 1);
        if (!(t & 1)) {
            g_f1[h * NN + i0 + r] = p1;
            g_f2[h * NN + i0 + r] = p2;
        }
    }
    {
        int d = t >> 1, n0 = (t & 1) * 64;
        size_t base = ((size_t)h * ND + d) * NN + i0 + n0;
#pragma unroll
        for (int c = 0; c < 8; c++) {
            uint32_t hp[4];
#pragma unroll
            for (int q = 0; q < 8; q += 2) {
                int n = c * 8 + q;
                F16X2(hp[q >> 1], Cst[(n0 + n) * CSTR + d], Cst[(n0 + n + 1) * CSTR + d]);
            }
            *(uint4*)(g_VT + base + c * 8) = *(uint4*)hp;
        }
    }
}

// ---------------- K2b: per-head max of f2 ----------------
__global__ void k_fmax() {
    __shared__ float red[256];
    int h = blockIdx.x, t = threadIdx.x;
    float m = -1e30f;
    for (int i = t; i < NN; i += 256) m = fmaxf(m, g_f2[h * NN + i]);
    red[t] = m; __syncthreads();
    for (int s = 128; s; s >>= 1) { if (t < s) red[t] = fmaxf(red[t], red[t + s]); __syncthreads(); }
    if (t == 0) g_f2max[h] = red[0];
}

// ---------------- K4: fp16 2-product aggregation, exp-factored P-gen -------
// P_ij = mask ? (s>0 ? A_i*B_j : C_i*D_j) : 0, with A=exp(f1-sh), B=exp(f2),
// C=exp(.2 f1-sh), D=exp(.2 f2). Per-tile (f2,B,D) float4 table in smem.
#define PSTR 272u
#define A1_FBD 1024u
#define A1_PHI 3072u
#define A1_PLO 37888u
#define A1_V   72704u
#define SMEM_A1 107520
__global__ __launch_bounds__(256, 2) void k_attn1() {
    extern __shared__ char smem[];
    uint32_t sb = s2u(smem);
    int t = threadIdx.x, lane = t & 31, wid = t >> 5;
    int h = blockIdx.y, i0 = blockIdx.x * 128;
    int wm = wid & 3, wn = wid >> 2;
    float* dens = (float*)smem;
    float4* fBD = (float4*)(smem + A1_FBD);

    int row = t & 127, jh64 = (t >> 7) * 64;
    float f1r = g_f1[h * NN + i0 + row];
    float sh = lrelu(f1r + g_f2max[h]);
    float Arow = __expf(f1r - sh);
    float Crow = __expf(LALPHA * f1r - sh);
    float dacc = 0.f;

    float acc[2][8][4];
#pragma unroll
    for (int mt = 0; mt < 2; mt++)
#pragma unroll
        for (int nt = 0; nt < 8; nt++)
#pragma unroll
            for (int q = 0; q < 4; q++) acc[mt][nt][q] = 0.f;

    uint32_t aAddrH = sb + A1_PHI + (uint32_t)(wm * 32 + (lane & 15)) * PSTR + (uint32_t)(lane >> 4) * 16u;
    uint32_t aAddrL = aAddrH + (A1_PLO - A1_PHI);
    int brow = ((lane >> 4) << 3) + (lane & 7);
    uint32_t bAddr0 = sb + A1_V + (uint32_t)(wn * 64 + brow) * PSTR + (uint32_t)((lane >> 3) & 1) * 16u;

    const float* f2p = g_f2 + h * NN;
    const unsigned* mrow = g_mask + (size_t)(i0 + row) * NW + (jh64 >> 5);
    float pv = (t < 128) ? f2p[t] : 0.f;     // f2 prefetch for fBD
    uint2 pm = *(const uint2*)mrow;

    for (int jt = 0; jt < 32; jt++) {
        int j0 = jt * 128;
        __syncthreads();                      // prev tile's smem reads done
        // stage V via cp.async
#pragma unroll
        for (int c = 0; c < 9; c++) {
            int idx = c * 256 + t;
            if (idx < 2176) {
                int r = idx / 17, ch = idx - r * 17;
                CP16(sb + A1_V + (uint32_t)r * PSTR + (uint32_t)ch * 16u,
                     g_VT + ((size_t)(h * ND + r)) * NN + j0 + ch * 8);
            }
        }
        if (t < 128) {
            float v = pv;
            fBD[t] = make_float4(v, __expf(v), __expf(LALPHA * v), 0.f);
        }
        __syncthreads();                      // fBD visible
        uint64_t m64 = ((uint64_t)pm.y << 32) | pm.x;
#pragma unroll
        for (int g = 0; g < 8; g++) {
            uint32_t ph[4], pl[4];
#pragma unroll
            for (int q = 0; q < 8; q += 2) {
                int c = g * 8 + q;
                float4 q0 = fBD[jh64 + c];
                float4 q1 = fBD[jh64 + c + 1];
                float s0 = f1r + q0.x, s1 = f1r + q1.x;
                float w0 = ((m64 >> c) & 1)       ? (s0 > 0.f ? Arow * q0.y : Crow * q0.z) : 0.f;
                float w1 = ((m64 >> (c + 1)) & 1) ? (s1 > 0.f ? Arow * q1.y : Crow * q1.z) : 0.f;
                dacc += w0 + w1;
                uint32_t hh, ll;
                F16X2(hh, w0, w1);
                __half2 hv = *(__half2*)&hh;
                F16X2(ll, w0 - __low2float(hv), w1 - __high2float(hv));
                ph[q >> 1] = hh; pl[q >> 1] = ll;
            }
            uint32_t o = (uint32_t)row * PSTR + (uint32_t)(jh64 + g * 8) * 2u;
            *(uint4*)(smem + A1_PHI + o) = *(uint4*)ph;
            *(uint4*)(smem + A1_PLO + o) = *(uint4*)pl;
        }
        if (jt < 31) {
            if (t < 128) pv = f2p[j0 + 128 + t];
            pm = *(const uint2*)(mrow + (jt + 1) * 4);
        }
        CPWAITALL();
        __syncthreads();                      // V + P visible
#pragma unroll
        for (int ks = 0; ks < 8; ks++) {
            uint32_t ah[2][4], al[2][4];
#pragma unroll
            for (int mt = 0; mt < 2; mt++) {
                uint32_t ao = (uint32_t)mt * (16u * PSTR) + (uint32_t)ks * 32u;
                LDSM4(ah[mt], aAddrH + ao);
                LDSM4(al[mt], aAddrL + ao);
            }
#pragma unroll
            for (int p = 0; p < 4; p++) {
                uint32_t bb[4];
                LDSM4(bb, bAddr0 + (uint32_t)p * (16u * PSTR) + (uint32_t)ks * 32u);
#pragma unroll
                for (int mt = 0; mt < 2; mt++) {
                    MMA_F16(acc[mt][2 * p],     ah[mt], bb[0], bb[1]);
                    MMA_F16(acc[mt][2 * p],     al[mt], bb[0], bb[1]);
                    MMA_F16(acc[mt][2 * p + 1], ah[mt], bb[2], bb[3]);
                    MMA_F16(acc[mt][2 * p + 1], al[mt], bb[2], bb[3]);
                }
            }
        }
    }
    dens[t] = dacc;
    __syncthreads();
#pragma unroll
    for (int mt = 0; mt < 2; mt++) {
        int rl = wm * 32 + mt * 16 + (lane >> 2);
        float inv0 = 1.f / (dens[rl] + dens[128 + rl]);
        float inv1 = 1.f / (dens[rl + 8] + dens[128 + rl + 8]);
        float* d0 = g_hcat + (size_t)(i0 + rl) * HD + h * ND + wn * 64 + (lane & 3) * 2;
        float* d1 = d0 + (size_t)8 * HD;
#pragma unroll
        for (int nt = 0; nt < 8; nt++) {
            float z0 = acc[mt][nt][0] * inv0, z1 = acc[mt][nt][1] * inv0;
            float z2 = acc[mt][nt][2] * inv1, z3 = acc[mt][nt][3] * inv1;
            float2 o0, o1;
            o0.x = z0 > 0.f ? z0 : (__expf(z0) - 1.f);
            o0.y = z1 > 0.f ? z1 : (__expf(z1) - 1.f);
            o1.x = z2 > 0.f ? z2 : (__expf(z2) - 1.f);
            o1.y = z3 > 0.f ? z3 : (__expf(z3) - 1.f);
            *(float2*)(d0 + nt * 8) = o0;
            *(float2*)(d1 + nt * 8) = o1;
        }
    }
}

// ---------------- K5: Who partials, split-K (64x64 tiles, KC chunks) -------
__global__ __launch_bounds__(256) void k_who(const float* __restrict__ Wo) {
    __shared__ float As[16][68];
    __shared__ float Bs[16][64];
    int i0 = blockIdx.x * 64, kc = blockIdx.y;
    int t = threadIdx.x, ty = t >> 4, tx = t & 15;
    float acc[4][4];
#pragma unroll
    for (int u = 0; u < 4; u++)
#pragma unroll
        for (int v = 0; v < 4; v++) acc[u][v] = 0.f;
    int fbeg = kc * (HD / KC);
    for (int f0 = fbeg; f0 < fbeg + HD / KC; f0 += 16) {
        {
            int r = t >> 2, k4 = (t & 3) * 4;
            float4 v = *(const float4*)(g_hcat + (size_t)(i0 + r) * HD + f0 + k4);
            As[k4 + 0][r] = v.x; As[k4 + 1][r] = v.y;
            As[k4 + 2][r] = v.z; As[k4 + 3][r] = v.w;
        }
        {
            int kk = t >> 4, d4 = (t & 15) * 4;
            *(float4*)&Bs[kk][d4] = *(const float4*)(Wo + (size_t)(f0 + kk) * NC + d4);
        }
        __syncthreads();
#pragma unroll
        for (int k = 0; k < 16; k++) {
            float ra[4], rb[4];
            *(float4*)ra = *(float4*)&As[k][ty * 4];
            *(float4*)rb = *(float4*)&Bs[k][tx * 4];
#pragma unroll
            for (int u = 0; u < 4; u++)
#pragma unroll
                for (int v = 0; v < 4; v++) acc[u][v] = fmaf(ra[u], rb[v], acc[u][v]);
        }
        __syncthreads();
    }
#pragma unroll
    for (int u = 0; u < 4; u++)
        *(float4*)(g_part + ((size_t)kc * NN + i0 + ty * 4 + u) * NC + tx * 4) = *(float4*)&acc[u][0];
}

// ---------------- K6: combine Who partials; g1,g2 ----------------
__global__ void k_g(const float* __restrict__ ao1, const float* __restrict__ ao2) {
    int warp = threadIdx.x >> 5, lane = threadIdx.x & 31;
    int n = blockIdx.x * 8 + warp;
    float v0 = 0.f, v1 = 0.f;
#pragma unroll
    for (int kc = 0; kc < KC; kc++) {
        size_t base = ((size_t)kc * NN + n) * NC;
        v0 += g_part[base + lane];
        v1 += g_part[base + lane + 32];
    }
    g_Who[(size_t)n * NC + lane] = v0;
    g_Who[(size_t)n * NC + lane + 32] = v1;
    float s1 = fmaf(v0, ao1[lane], v1 * ao1[lane + 32]);
    float s2 = fmaf(v0, ao2[lane], v1 * ao2[lane + 32]);
#pragma unroll
    for (int o = 16; o; o >>= 1) {
        s1 += __shfl_xor_sync(0xffffffffu, s1, o);
        s2 += __shfl_xor_sync(0xffffffffu, s2, o);
    }
    if (lane == 0) { g_g1[n] = s1; g_g2[n] = s2; }
}

// ---------------- K6b: global max of g2 ----------------
__global__ void k_gmax() {
    __shared__ float red[256];
    int t = threadIdx.x;
    float m = -1e30f;
    for (int i = t; i < NN; i += 256) m = fmaxf(m, g_g2[i]);
    red[t] = m; __syncthreads();
    for (int s = 128; s; s >>= 1) { if (t < s) red[t] = fmaxf(red[t], red[t + s]); __syncthreads(); }
    if (t == 0) g_gmax[0] = red[0];
}

// ---------------- K6c: Who -> Who^T fp16 [c][n] ----------------
__global__ void k_whoT() {
    __shared__ float ts[64][65];
    int n0 = blockIdx.x * 64, t = threadIdx.x;
#pragma unroll
    for (int k = 0; k < 16; k++) {
        int idx = k * 256 + t;
        int r = idx >> 6, c = idx & 63;
        ts[r][c] = g_Who[(size_t)(n0 + r) * NC + c];
    }
    __syncthreads();
    int c = t >> 2, nq = (t & 3) * 16;
    uint32_t hp[8];
#pragma unroll
    for (int q = 0; q < 16; q += 2)
        F16X2(hp[q >> 1], ts[nq + q][c], ts[nq + q + 1][c]);
    *(uint4*)(g_WhoT + (size_t)c * NN + n0 + nq)     = *(uint4*)hp;
    *(uint4*)(g_WhoT + (size_t)c * NN + n0 + nq + 8) = *(uint4*)(hp + 4);
}

// ---------------- K7: output attention, exp-factored, fp16 HMMA ------------
#define A2_FBD 1024u
#define A2_PHI 3072u
#define A2_PLO 37888u
#define A2_B   72704u
#define SMEM_A2 90112
__global__ __launch_bounds__(256, 2) void k_attn2() {
    extern __shared__ char smem[];
    uint32_t sb = s2u(smem);
    int t = threadIdx.x, lane = t & 31, wid = t >> 5;
    int jcc = blockIdx.y, i0 = blockIdx.x * 128;
    int wm = wid & 3, wn = wid >> 2;
    float* dens = (float*)smem;
    float4* fBD = (float4*)(smem + A2_FBD);

    int row = t & 127, jh64 = (t >> 7) * 64;
    float g1r = g_g1[i0 + row];
    float sh = lrelu(g1r + g_gmax[0]);
    float Arow = __expf(g1r - sh);
    float Crow = __expf(LALPHA * g1r - sh);
    float dacc = 0.f;

    float acc[2][4][4];
#pragma unroll
    for (int mt = 0; mt < 2; mt++)
#pragma unroll
        for (int nt = 0; nt < 4; nt++)
#pragma unroll
            for (int q = 0; q < 4; q++) acc[mt][nt][q] = 0.f;

    uint32_t aAddrH = sb + A2_PHI + (uint32_t)(wm * 32 + (lane & 15)) * PSTR + (uint32_t)(lane >> 4) * 16u;
    uint32_t aAddrL = aAddrH + (A2_PLO - A2_PHI);
    int brow = ((lane >> 4) << 3) + (lane & 7);
    uint32_t bAddr0 = sb + A2_B + (uint32_t)(wn * 32 + brow) * PSTR + (uint32_t)((lane >> 3) & 1) * 16u;

    const unsigned* mrow = g_mask + (size_t)(i0 + row) * NW + (jh64 >> 5);

    for (int jj = 0; jj < 2; jj++) {
        int jt = jcc * 2 + jj, j0 = jt * 128;
        __syncthreads();
#pragma unroll
        for (int c = 0; c < 5; c++) {
            int idx = c * 256 + t;
            if (idx < 1088) {
                int r = idx / 17, ch = idx - r * 17;
                CP16(sb + A2_B + (uint32_t)r * PSTR + (uint32_t)ch * 16u,
                     g_WhoT + (size_t)r * NN + j0 + ch * 8);
            }
        }
        if (t < 128) {
            float v = g_g2[j0 + t];
            fBD[t] = make_float4(v, __expf(v), __expf(LALPHA * v), 0.f);
        }
        __syncthreads();
        uint2 pm = *(const uint2*)(mrow + jt * 4);
        uint64_t m64 = ((uint64_t)pm.y << 32) | pm.x;
#pragma unroll
        for (int g = 0; g < 8; g++) {
            uint32_t ph[4], pl[4];
#pragma unroll
            for (int q = 0; q < 8; q += 2) {
                int c = g * 8 + q;
                float4 q0 = fBD[jh64 + c];
                float4 q1 = fBD[jh64 + c + 1];
                float s0 = g1r + q0.x, s1 = g1r + q1.x;
                float w0 = ((m64 >> c) & 1)       ? (s0 > 0.f ? Arow * q0.y : Crow * q0.z) : 0.f;
                float w1 = ((m64 >> (c + 1)) & 1) ? (s1 > 0.f ? Arow * q1.y : Crow * q1.z) : 0.f;
                dacc += w0 + w1;
                uint32_t hh, ll;
                F16X2(hh, w0, w1);
                __half2 hv = *(__half2*)&hh;
                F16X2(ll, w0 - __low2float(hv), w1 - __high2float(hv));
                ph[q >> 1] = hh; pl[q >> 1] = ll;
            }
            uint32_t o = (uint32_t)row * PSTR + (uint32_t)(jh64 + g * 8) * 2u;
            *(uint4*)(smem + A2_PHI + o) = *(uint4*)ph;
            *(uint4*)(smem + A2_PLO + o) = *(uint4*)pl;
        }
        CPWAITALL();
        __syncthreads();
#pragma unroll
        for (int ks = 0; ks < 8; ks++) {
            uint32_t ah[2][4], al[2][4];
#pragma unroll
            for (int mt = 0; mt < 2; mt++) {
                uint32_t ao = (uint32_t)mt * (16u * PSTR) + (uint32_t)ks * 32u;
                LDSM4(ah[mt], aAddrH + ao);
                LDSM4(al[mt], aAddrL + ao);
            }
#pragma unroll
            for (int p = 0; p < 2; p++) {
                uint32_t bb[4];
                LDSM4(bb, bAddr0 + (uint32_t)p * (16u * PSTR) + (uint32_t)ks * 32u);
#pragma unroll
                for (int mt = 0; mt < 2; mt++) {
                    MMA_F16(acc[mt][2 * p],     ah[mt], bb[0], bb[1]);
                    MMA_F16(acc[mt][2 * p],     al[mt], bb[0], bb[1]);
                    MMA_F16(acc[mt][2 * p + 1], ah[mt], bb[2], bb[3]);
                    MMA_F16(acc[mt][2 * p + 1], al[mt], bb[2], bb[3]);
                }
            }
        }
    }
    dens[t] = dacc;
    __syncthreads();
#pragma unroll
    for (int mt = 0; mt < 2; mt++) {
        int rl = wm * 32 + mt * 16 + (lane >> 2);
        int cl = wn * 32 + (lane & 3) * 2;
#pragma unroll
        for (int nt = 0; nt < 4; nt++) {
            size_t b0 = ((size_t)jcc * NN + i0 + rl) * NC + cl + nt * 8;
            *(float2*)(g_part + b0)                  = *(float2*)&acc[mt][nt][0];
            *(float2*)(g_part + b0 + (size_t)8 * NC) = *(float2*)&acc[mt][nt][2];
        }
    }
    if (t < 128) g_dpart[jcc * NN + i0 + t] = dens[t] + dens[128 + t];
}

// ---------------- K8: combine partials + elu + log_softmax ----------------
__global__ void k_final(float* __restrict__ out) {
    int warp = threadIdx.x >> 5, lane = threadIdx.x & 31;
    int n = blockIdx.x * 8 + warp;
    float den = 0.f;
#pragma unroll
    for (int jc = 0; jc < JCC; jc++) den += g_dpart[jc * NN + n];
    float inv = 1.f / den;
    float v0 = 0.f, v1 = 0.f;
#pragma unroll
    for (int jc = 0; jc < JCC; jc++) {
        size_t base = ((size_t)jc * NN + n) * NC;
        v0 += g_part[base + lane];
        v1 += g_part[base + lane + 32];
    }
    v0 *= inv; v1 *= inv;
    v0 = v0 > 0.f ? v0 : (expf(v0) - 1.f);
    v1 = v1 > 0.f ? v1 : (expf(v1) - 1.f);
    float m = fmaxf(v0, v1);
#pragma unroll
    for (int o = 16; o; o >>= 1) m = fmaxf(m, __shfl_xor_sync(0xffffffffu, m, o));
    float s = expf(v0 - m) + expf(v1 - m);
#pragma unroll
    for (int o = 16; o; o >>= 1) s += __shfl_xor_sync(0xffffffffu, s, o);
    float lse = m + logf(s);
    out[(size_t)n * NC + lane] = v0 - lse;
    out[(size_t)n * NC + lane + 32] = v1 - lse;
}

// ---------------- launch ----------------
extern "C" void kernel_launch(void* const* d_in, const int* in_sizes, int n_in,
                              void* d_out, int out_size) {
    const float* x   = (const float*)d_in[0];
    const int*   adj = (const int*)d_in[1];
    const float* W   = (const float*)d_in[2];
    const float* a1  = (const float*)d_in[3];
    const float* a2  = (const float*)d_in[4];
    const float* Wo  = (const float*)d_in[5];
    const float* ao1 = (const float*)d_in[6];
    const float* ao2 = (const float*)d_in[7];
    float* out = (float*)d_out;

    cudaFuncSetAttribute(k_wh, cudaFuncAttributeMaxDynamicSharedMemorySize, SMEM_WH);
    cudaFuncSetAttribute(k_attn1, cudaFuncAttributeMaxDynamicSharedMemorySize, SMEM_A1);
    cudaFuncSetAttribute(k_attn2, cudaFuncAttributeMaxDynamicSharedMemorySize, SMEM_A2);

    k_pack  <<<NN, 128>>>(adj);
    k_splitx<<<(NN * NF / 4) / 256, 256>>>(x);
    k_splitw<<<dim3(NF / 32, ND / 32, NH), 256>>>(W);
    k_wh    <<<dim3(NN / 128, NH), 256, SMEM_WH>>>(a1, a2);
    k_fmax  <<<NH, 256>>>();
    k_attn1 <<<dim3(NN / 128, NH), 256, SMEM_A1>>>();
    k_who   <<<dim3(NN / 64, KC), 256>>>(Wo);
    k_g     <<<NN / 8, 256>>>(ao1, ao2);
    k_gmax  <<<1, 256>>>();
    k_whoT  <<<NN / 64, 256>>>();
    k_attn2 <<<dim3(NN / 128, JCC), 256, SMEM_A2>>>();
    k_final <<<NN / 8, 256>>>(out);
}

// round 9
// speedup vs baseline: 4.4397x; 1.3313x over previous
#include <cuda_runtime.h>
#include <cuda_fp16.h>
#include <math.h>
#include <stdint.h>

#define NN 4096
#define NF 1024
#define NH 8
#define ND 128
#define NC 64
#define HD (NH*ND)      // 1024
#define NW (NN/32)      // 128 mask words per row
#define LALPHA 0.2f
#define KC 4            // split-K chunks for k_who
#define JCC 16          // j-split chunks for output attention layer

// ---------------- scratch (static device globals; no allocs) ----------------
__device__ unsigned g_mask[(size_t)NN*NW];         // 2 MB packed adjacency
__device__ __half g_VT[(size_t)NH*ND*NN];          // 8 MB  Wh^T fp16 [h][d][n]
__device__ __half g_xhi[(size_t)NN*NF];            // 8 MB  x hi fp16
__device__ __half g_xlo[(size_t)NN*NF];            // 8 MB  x lo fp16
__device__ __half g_WT[(size_t)NH*ND*NF];          // 2 MB  W^T fp16 [h][d][f]
__device__ float g_f1[NH*NN];
__device__ float g_f2[NH*NN];
__device__ float g_f2max[NH];
__device__ float g_hcat[(size_t)NN*HD];            // 16 MB  elu(h) concat
__device__ float g_Who[(size_t)NN*NC];             // 1 MB
__device__ __half g_WhoT[(size_t)NC*NN];           // 512 KB Who^T fp16 [c][n]
__device__ float g_g1[NN];
__device__ float g_g2[NN];
__device__ float g_gmax[1];
__device__ float g_part[(size_t)JCC*NN*NC];        // 16 MB partials (who & attn2)
__device__ float g_dpart[JCC*NN];                  // partial denominators

__device__ __forceinline__ float lrelu(float s) { return s > 0.f ? s : LALPHA * s; }

__device__ __forceinline__ uint32_t s2u(const void* p) {
    uint32_t a;
    asm("{ .reg .u64 t; cvta.to.shared.u64 t, %1; cvt.u32.u64 %0, t; }" : "=r"(a) : "l"(p));
    return a;
}

#define LDSM4(r, addr) \
    asm volatile("ldmatrix.sync.aligned.m8n8.x4.shared.b16 {%0,%1,%2,%3}, [%4];" \
        : "=r"((r)[0]), "=r"((r)[1]), "=r"((r)[2]), "=r"((r)[3]) : "r"(addr))

#define MMA_F16(c, a, b0, b1) \
    asm volatile("mma.sync.aligned.m16n8k16.row.col.f32.f16.f16.f32 " \
        "{%0,%1,%2,%3}, {%4,%5,%6,%7}, {%8,%9}, {%0,%1,%2,%3};" \
        : "+f"((c)[0]), "+f"((c)[1]), "+f"((c)[2]), "+f"((c)[3]) \
        : "r"((a)[0]), "r"((a)[1]), "r"((a)[2]), "r"((a)[3]), "r"(b0), "r"(b1))

#define CP16(dst, src) \
    asm volatile("cp.async.cg.shared.global [%0], [%1], 16;" :: "r"(dst), "l"(src))
#define CPCOMMIT() asm volatile("cp.async.commit_group;" ::: "memory")
#define CPWAITALL() asm volatile("cp.async.wait_all;" ::: "memory")

// pack two floats to half2: lo=w0, hi=w1
#define F16X2(d, w0, w1) \
    asm("cvt.rn.f16x2.f32 %0, %1, %2;" : "=r"(d) : "f"(w1), "f"(w0))

// ---------------- K1: pack adj -> bitmask ----------------
__global__ void k_pack(const int* __restrict__ adj) {
    int row = blockIdx.x;
    int warp = threadIdx.x >> 5, lane = threadIdx.x & 31;
    const int* ar = adj + (size_t)row * NN;
    for (int w = warp; w < NW; w += 4) {
        unsigned b = __ballot_sync(0xffffffffu, ar[w * 32 + lane] > 0);
        if (lane == 0) g_mask[(size_t)row * NW + w] = b;
    }
}

// ---------------- K1b: split x into fp16 hi/lo ----------------
__global__ void k_splitx(const float* __restrict__ x) {
    int i = blockIdx.x * 256 + threadIdx.x;
    float4 v = *(const float4*)(x + (size_t)i * 4);
    uint2 ho, lo;
    F16X2(ho.x, v.x, v.y);
    F16X2(ho.y, v.z, v.w);
    __half2 h0 = *(__half2*)&ho.x, h1 = *(__half2*)&ho.y;
    F16X2(lo.x, v.x - __low2float(h0), v.y - __high2float(h0));
    F16X2(lo.y, v.z - __low2float(h1), v.w - __high2float(h1));
    *(uint2*)(g_xhi + (size_t)i * 4) = ho;
    *(uint2*)(g_xlo + (size_t)i * 4) = lo;
}

// ---------------- K1c: W -> W^T fp16  [h][f][d] -> [h][d][f] ---------------
__global__ void k_splitw(const float* __restrict__ W) {
    __shared__ float ts[32][33];
    int f0 = blockIdx.x * 32, d0 = blockIdx.y * 32, h = blockIdx.z;
    int t = threadIdx.x;
    int r = t >> 3, c4 = (t & 7) * 4;
    float4 v = *(const float4*)(W + ((size_t)h * NF + f0 + r) * ND + d0 + c4);
    ts[r][c4] = v.x; ts[r][c4 + 1] = v.y; ts[r][c4 + 2] = v.z; ts[r][c4 + 3] = v.w;
    __syncthreads();
    int rr = t >> 3, cc = (t & 7) * 4;
    uint2 hp;
    F16X2(hp.x, ts[cc][rr], ts[cc + 1][rr]);
    F16X2(hp.y, ts[cc + 2][rr], ts[cc + 3][rr]);
    *(uint2*)(g_WT + ((size_t)h * ND + d0 + rr) * NF + f0 + cc) = hp;
}

// ---------------- K2: Wh = x @ W, fp16 2-prod, cp.async double-buffered ----
#define WSTR 144u
#define WTILE 18432u
#define STAGE 55296u         // AHI@0, ALO@18432, B@36864 (per stage)
#define CSTR 130
#define SM_A1  110592
#define SM_A2  111104
#define SMEM_WH 111616
__global__ __launch_bounds__(256) void k_wh(const float* __restrict__ a1,
                                            const float* __restrict__ a2) {
    extern __shared__ char smem[];
    uint32_t sb = s2u(smem);
    int t = threadIdx.x, lane = t & 31, wid = t >> 5;
    int h = blockIdx.y, i0 = blockIdx.x * 128;
    int wm = wid & 3, wn = wid >> 2;
    float* a1s = (float*)(smem + SM_A1);
    float* a2s = (float*)(smem + SM_A2);
    if (t < ND) { a1s[t] = a1[h * ND + t]; a2s[t] = a2[h * ND + t]; }

    float acc[2][8][4];
#pragma unroll
    for (int mt = 0; mt < 2; mt++)
#pragma unroll
        for (int nt = 0; nt < 8; nt++)
#pragma unroll
            for (int q = 0; q < 4; q++) acc[mt][nt][q] = 0.f;

    uint32_t aBase = sb + (uint32_t)(wm * 32 + (lane & 15)) * WSTR + (uint32_t)(lane >> 4) * 16u;
    int brow = ((lane >> 4) << 3) + (lane & 7);
    uint32_t bBase = sb + 36864u + (uint32_t)(wn * 64 + brow) * WSTR + (uint32_t)((lane >> 3) & 1) * 16u;

    int srow = t >> 3, sch = (t & 7) * 8;      // staging coords (c-loop adds 32 rows)
    uint32_t so0 = (uint32_t)srow * WSTR + (uint32_t)sch * 2u;

    // prologue: stage 0
    {
        uint32_t s0 = sb;
#pragma unroll
        for (int c = 0; c < 4; c++) {
            uint32_t o = so0 + (uint32_t)c * (32u * WSTR);
            size_t ga = (size_t)(i0 + c * 32 + srow) * NF + sch;
            size_t gb = ((size_t)h * ND + c * 32 + srow) * NF + sch;
            CP16(s0 + o,          g_xhi + ga);
            CP16(s0 + 18432u + o, g_xlo + ga);
            CP16(s0 + 36864u + o, g_WT + gb);
        }
        CPCOMMIT();
    }
    for (int kt = 0; kt < 16; kt++) {
        uint32_t buf = (uint32_t)(kt & 1) * STAGE;
        if (kt < 15) {
            uint32_t s0 = sb + (uint32_t)((kt + 1) & 1) * STAGE;
            int f0 = (kt + 1) * 64;
#pragma unroll
            for (int c = 0; c < 4; c++) {
                uint32_t o = so0 + (uint32_t)c * (32u * WSTR);
                size_t ga = (size_t)(i0 + c * 32 + srow) * NF + f0 + sch;
                size_t gb = ((size_t)h * ND + c * 32 + srow) * NF + f0 + sch;
                CP16(s0 + o,          g_xhi + ga);
                CP16(s0 + 18432u + o, g_xlo + ga);
                CP16(s0 + 36864u + o, g_WT + gb);
            }
            CPCOMMIT();
            asm volatile("cp.async.wait_group 1;" ::: "memory");
        } else {
            asm volatile("cp.async.wait_group 0;" ::: "memory");
        }
        __syncthreads();
#pragma unroll
        for (int ks = 0; ks < 4; ks++) {
            uint32_t ah[2][4], al[2][4];
#pragma unroll
            for (int mt = 0; mt < 2; mt++) {
                uint32_t ao = aBase + buf + (uint32_t)mt * (16u * WSTR) + (uint32_t)ks * 32u;
                LDSM4(ah[mt], ao);
                LDSM4(al[mt], ao + WTILE);
            }
#pragma unroll
            for (int p = 0; p < 4; p++) {
                uint32_t bb[4];
                LDSM4(bb, bBase + buf + (uint32_t)p * (16u * WSTR) + (uint32_t)ks * 32u);
#pragma unroll
                for (int mt = 0; mt < 2; mt++) {
                    MMA_F16(acc[mt][2 * p],     ah[mt], bb[0], bb[1]);
                    MMA_F16(acc[mt][2 * p],     al[mt], bb[0], bb[1]);
                    MMA_F16(acc[mt][2 * p + 1], ah[mt], bb[2], bb[3]);
                    MMA_F16(acc[mt][2 * p + 1], al[mt], bb[2], bb[3]);
                }
            }
        }
        __syncthreads();
    }
    float* Cst = (float*)smem;
#pragma unroll
    for (int mt = 0; mt < 2; mt++) {
#pragma unroll
        for (int nt = 0; nt < 8; nt++) {
            int rl = wm * 32 + mt * 16 + (lane >> 2);
            int cl = wn * 64 + nt * 8 + (lane & 3) * 2;
            *(float2*)(Cst + rl * CSTR + cl)       = *(float2*)&acc[mt][nt][0];
            *(float2*)(Cst + (rl + 8) * CSTR + cl) = *(float2*)&acc[mt][nt][2];
        }
    }
    __syncthreads();
    {
        int r = t >> 1, half = (t & 1) * 64;
        float p1 = 0.f, p2 = 0.f;
#pragma unroll
        for (int d = 0; d < 64; d++) {
            float v = Cst[r * CSTR + half + d];
            p1 = fmaf(v, a1s[half + d], p1);
            p2 = fmaf(v, a2s[half + d], p2);
        }
        p1 += __shfl_xor_sync(0xffffffffu, p1, 1);
        p2 += __shfl_xor_sync(0xffffffffu, p2, 1);
        if (!(t & 1)) {
            g_f1[h * NN + i0 + r] = p1;
            g_f2[h * NN + i0 + r] = p2;
        }
    }
    {
        int d = t >> 1, n0 = (t & 1) * 64;
        size_t base = ((size_t)h * ND + d) * NN + i0 + n0;
#pragma unroll
        for (int c = 0; c < 8; c++) {
            uint32_t hp[4];
#pragma unroll
            for (int q = 0; q < 8; q += 2) {
                int n = c * 8 + q;
                F16X2(hp[q >> 1], Cst[(n0 + n) * CSTR + d], Cst[(n0 + n + 1) * CSTR + d]);
            }
            *(uint4*)(g_VT + base + c * 8) = *(uint4*)hp;
        }
    }
}

// ---------------- K2b: per-head max of f2 ----------------
__global__ void k_fmax() {
    __shared__ float red[256];
    int h = blockIdx.x, t = threadIdx.x;
    float m = -1e30f;
    for (int i = t; i < NN; i += 256) m = fmaxf(m, g_f2[h * NN + i]);
    red[t] = m; __syncthreads();
    for (int s = 128; s; s >>= 1) { if (t < s) red[t] = fmaxf(red[t], red[t + s]); __syncthreads(); }
    if (t == 0) g_f2max[h] = red[0];
}

// ---------------- K4: single-product fp16 aggregation, exp-factored P-gen --
// P_ij = mask ? (s>0 ? A_i*B_j : C_i*D_j) : 0 (shifted softmax, P in (0,1]).
#define PSTR 272u
#define A1_FBD 1024u
#define A1_PHI 3072u
#define A1_V   37888u
#define SMEM_A1 72704
__global__ __launch_bounds__(256, 2) void k_attn1() {
    extern __shared__ char smem[];
    uint32_t sb = s2u(smem);
    int t = threadIdx.x, lane = t & 31, wid = t >> 5;
    int h = blockIdx.y, i0 = blockIdx.x * 128;
    int wm = wid & 3, wn = wid >> 2;
    float* dens = (float*)smem;
    float4* fBD = (float4*)(smem + A1_FBD);

    int row = t & 127, jh64 = (t >> 7) * 64;
    float f1r = g_f1[h * NN + i0 + row];
    float sh = lrelu(f1r + g_f2max[h]);
    float Arow = __expf(f1r - sh);
    float Crow = __expf(LALPHA * f1r - sh);
    float dacc = 0.f;

    float acc[2][8][4];
#pragma unroll
    for (int mt = 0; mt < 2; mt++)
#pragma unroll
        for (int nt = 0; nt < 8; nt++)
#pragma unroll
            for (int q = 0; q < 4; q++) acc[mt][nt][q] = 0.f;

    uint32_t aAddrH = sb + A1_PHI + (uint32_t)(wm * 32 + (lane & 15)) * PSTR + (uint32_t)(lane >> 4) * 16u;
    int brow = ((lane >> 4) << 3) + (lane & 7);
    uint32_t bAddr0 = sb + A1_V + (uint32_t)(wn * 64 + brow) * PSTR + (uint32_t)((lane >> 3) & 1) * 16u;

    const float* f2p = g_f2 + h * NN;
    const unsigned* mrow = g_mask + (size_t)(i0 + row) * NW + (jh64 >> 5);
    float pv = (t < 128) ? f2p[t] : 0.f;
    uint2 pm = *(const uint2*)mrow;

    for (int jt = 0; jt < 32; jt++) {
        int j0 = jt * 128;
        __syncthreads();
#pragma unroll
        for (int c = 0; c < 9; c++) {
            int idx = c * 256 + t;
            if (idx < 2176) {
                int r = idx / 17, ch = idx - r * 17;
                CP16(sb + A1_V + (uint32_t)r * PSTR + (uint32_t)ch * 16u,
                     g_VT + ((size_t)(h * ND + r)) * NN + j0 + ch * 8);
            }
        }
        if (t < 128) {
            float v = pv;
            fBD[t] = make_float4(v, __expf(v), __expf(LALPHA * v), 0.f);
        }
        __syncthreads();
        uint64_t m64 = ((uint64_t)pm.y << 32) | pm.x;
#pragma unroll
        for (int g = 0; g < 8; g++) {
            uint32_t ph[4];
#pragma unroll
            for (int q = 0; q < 8; q += 2) {
                int c = g * 8 + q;
                float4 q0 = fBD[jh64 + c];
                float4 q1 = fBD[jh64 + c + 1];
                float s0 = f1r + q0.x, s1 = f1r + q1.x;
                float w0 = ((m64 >> c) & 1)       ? (s0 > 0.f ? Arow * q0.y : Crow * q0.z) : 0.f;
                float w1 = ((m64 >> (c + 1)) & 1) ? (s1 > 0.f ? Arow * q1.y : Crow * q1.z) : 0.f;
                dacc += w0 + w1;
                F16X2(ph[q >> 1], w0, w1);
            }
            uint32_t o = (uint32_t)row * PSTR + (uint32_t)(jh64 + g * 8) * 2u;
            *(uint4*)(smem + A1_PHI + o) = *(uint4*)ph;
        }
        if (jt < 31) {
            if (t < 128) pv = f2p[j0 + 128 + t];
            pm = *(const uint2*)(mrow + (jt + 1) * 4);
        }
        CPWAITALL();
        __syncthreads();
#pragma unroll
        for (int ks = 0; ks < 8; ks++) {
            uint32_t ah[2][4];
#pragma unroll
            for (int mt = 0; mt < 2; mt++)
                LDSM4(ah[mt], aAddrH + (uint32_t)mt * (16u * PSTR) + (uint32_t)ks * 32u);
#pragma unroll
            for (int p = 0; p < 4; p++) {
                uint32_t bb[4];
                LDSM4(bb, bAddr0 + (uint32_t)p * (16u * PSTR) + (uint32_t)ks * 32u);
#pragma unroll
                for (int mt = 0; mt < 2; mt++) {
                    MMA_F16(acc[mt][2 * p],     ah[mt], bb[0], bb[1]);
                    MMA_F16(acc[mt][2 * p + 1], ah[mt], bb[2], bb[3]);
                }
            }
        }
    }
    dens[t] = dacc;
    __syncthreads();
#pragma unroll
    for (int mt = 0; mt < 2; mt++) {
        int rl = wm * 32 + mt * 16 + (lane >> 2);
        float inv0 = 1.f / (dens[rl] + dens[128 + rl]);
        float inv1 = 1.f / (dens[rl + 8] + dens[128 + rl + 8]);
        float* d0 = g_hcat + (size_t)(i0 + rl) * HD + h * ND + wn * 64 + (lane & 3) * 2;
        float* d1 = d0 + (size_t)8 * HD;
#pragma unroll
        for (int nt = 0; nt < 8; nt++) {
            float z0 = acc[mt][nt][0] * inv0, z1 = acc[mt][nt][1] * inv0;
            float z2 = acc[mt][nt][2] * inv1, z3 = acc[mt][nt][3] * inv1;
            float2 o0, o1;
            o0.x = z0 > 0.f ? z0 : (__expf(z0) - 1.f);
            o0.y = z1 > 0.f ? z1 : (__expf(z1) - 1.f);
            o1.x = z2 > 0.f ? z2 : (__expf(z2) - 1.f);
            o1.y = z3 > 0.f ? z3 : (__expf(z3) - 1.f);
            *(float2*)(d0 + nt * 8) = o0;
            *(float2*)(d1 + nt * 8) = o1;
        }
    }
}

// ---------------- K5: Who partials, split-K (64x64 tiles, KC chunks) -------
__global__ __launch_bounds__(256) void k_who(const float* __restrict__ Wo) {
    __shared__ float As[16][68];
    __shared__ float Bs[16][64];
    int i0 = blockIdx.x * 64, kc = blockIdx.y;
    int t = threadIdx.x, ty = t >> 4, tx = t & 15;
    float acc[4][4];
#pragma unroll
    for (int u = 0; u < 4; u++)
#pragma unroll
        for (int v = 0; v < 4; v++) acc[u][v] = 0.f;
    int fbeg = kc * (HD / KC);
    for (int f0 = fbeg; f0 < fbeg + HD / KC; f0 += 16) {
        {
            int r = t >> 2, k4 = (t & 3) * 4;
            float4 v = *(const float4*)(g_hcat + (size_t)(i0 + r) * HD + f0 + k4);
            As[k4 + 0][r] = v.x; As[k4 + 1][r] = v.y;
            As[k4 + 2][r] = v.z; As[k4 + 3][r] = v.w;
        }
        {
            int kk = t >> 4, d4 = (t & 15) * 4;
            *(float4*)&Bs[kk][d4] = *(const float4*)(Wo + (size_t)(f0 + kk) * NC + d4);
        }
        __syncthreads();
#pragma unroll
        for (int k = 0; k < 16; k++) {
            float ra[4], rb[4];
            *(float4*)ra = *(float4*)&As[k][ty * 4];
            *(float4*)rb = *(float4*)&Bs[k][tx * 4];
#pragma unroll
            for (int u = 0; u < 4; u++)
#pragma unroll
                for (int v = 0; v < 4; v++) acc[u][v] = fmaf(ra[u], rb[v], acc[u][v]);
        }
        __syncthreads();
    }
#pragma unroll
    for (int u = 0; u < 4; u++)
        *(float4*)(g_part + ((size_t)kc * NN + i0 + ty * 4 + u) * NC + tx * 4) = *(float4*)&acc[u][0];
}

// ---------------- K6: combine Who partials; g1,g2 ----------------
__global__ void k_g(const float* __restrict__ ao1, const float* __restrict__ ao2) {
    int warp = threadIdx.x >> 5, lane = threadIdx.x & 31;
    int n = blockIdx.x * 8 + warp;
    float v0 = 0.f, v1 = 0.f;
#pragma unroll
    for (int kc = 0; kc < KC; kc++) {
        size_t base = ((size_t)kc * NN + n) * NC;
        v0 += g_part[base + lane];
        v1 += g_part[base + lane + 32];
    }
    g_Who[(size_t)n * NC + lane] = v0;
    g_Who[(size_t)n * NC + lane + 32] = v1;
    float s1 = fmaf(v0, ao1[lane], v1 * ao1[lane + 32]);
    float s2 = fmaf(v0, ao2[lane], v1 * ao2[lane + 32]);
#pragma unroll
    for (int o = 16; o; o >>= 1) {
        s1 += __shfl_xor_sync(0xffffffffu, s1, o);
        s2 += __shfl_xor_sync(0xffffffffu, s2, o);
    }
    if (lane == 0) { g_g1[n] = s1; g_g2[n] = s2; }
}

// ---------------- K6b: global max of g2 ----------------
__global__ void k_gmax() {
    __shared__ float red[256];
    int t = threadIdx.x;
    float m = -1e30f;
    for (int i = t; i < NN; i += 256) m = fmaxf(m, g_g2[i]);
    red[t] = m; __syncthreads();
    for (int s = 128; s; s >>= 1) { if (t < s) red[t] = fmaxf(red[t], red[t + s]); __syncthreads(); }
    if (t == 0) g_gmax[0] = red[0];
}

// ---------------- K6c: Who -> Who^T fp16 [c][n] ----------------
__global__ void k_whoT() {
    __shared__ float ts[64][65];
    int n0 = blockIdx.x * 64, t = threadIdx.x;
#pragma unroll
    for (int k = 0; k < 16; k++) {
        int idx = k * 256 + t;
        int r = idx >> 6, c = idx & 63;
        ts[r][c] = g_Who[(size_t)(n0 + r) * NC + c];
    }
    __syncthreads();
    int c = t >> 2, nq = (t & 3) * 16;
    uint32_t hp[8];
#pragma unroll
    for (int q = 0; q < 16; q += 2)
        F16X2(hp[q >> 1], ts[nq + q][c], ts[nq + q + 1][c]);
    *(uint4*)(g_WhoT + (size_t)c * NN + n0 + nq)     = *(uint4*)hp;
    *(uint4*)(g_WhoT + (size_t)c * NN + n0 + nq + 8) = *(uint4*)(hp + 4);
}

// ---------------- K7: output attention, single-product fp16 HMMA -----------
#define A2_FBD 1024u
#define A2_PHI 3072u
#define A2_B   37888u
#define SMEM_A2 55296
__global__ __launch_bounds__(256, 2) void k_attn2() {
    extern __shared__ char smem[];
    uint32_t sb = s2u(smem);
    int t = threadIdx.x, lane = t & 31, wid = t >> 5;
    int jcc = blockIdx.y, i0 = blockIdx.x * 128;
    int wm = wid & 3, wn = wid >> 2;
    float* dens = (float*)smem;
    float4* fBD = (float4*)(smem + A2_FBD);

    int row = t & 127, jh64 = (t >> 7) * 64;
    float g1r = g_g1[i0 + row];
    float sh = lrelu(g1r + g_gmax[0]);
    float Arow = __expf(g1r - sh);
    float Crow = __expf(LALPHA * g1r - sh);
    float dacc = 0.f;

    float acc[2][4][4];
#pragma unroll
    for (int mt = 0; mt < 2; mt++)
#pragma unroll
        for (int nt = 0; nt < 4; nt++)
#pragma unroll
            for (int q = 0; q < 4; q++) acc[mt][nt][q] = 0.f;

    uint32_t aAddrH = sb + A2_PHI + (uint32_t)(wm * 32 + (lane & 15)) * PSTR + (uint32_t)(lane >> 4) * 16u;
    int brow = ((lane >> 4) << 3) + (lane & 7);
    uint32_t bAddr0 = sb + A2_B + (uint32_t)(wn * 32 + brow) * PSTR + (uint32_t)((lane >> 3) & 1) * 16u;

    const unsigned* mrow = g_mask + (size_t)(i0 + row) * NW + (jh64 >> 5);

    for (int jj = 0; jj < 2; jj++) {
        int jt = jcc * 2 + jj, j0 = jt * 128;
        __syncthreads();
#pragma unroll
        for (int c = 0; c < 5; c++) {
            int idx = c * 256 + t;
            if (idx < 1088) {
                int r = idx / 17, ch = idx - r * 17;
                CP16(sb + A2_B + (uint32_t)r * PSTR + (uint32_t)ch * 16u,
                     g_WhoT + (size_t)r * NN + j0 + ch * 8);
            }
        }
        if (t < 128) {
            float v = g_g2[j0 + t];
            fBD[t] = make_float4(v, __expf(v), __expf(LALPHA * v), 0.f);
        }
        __syncthreads();
        uint2 pm = *(const uint2*)(mrow + jt * 4);
        uint64_t m64 = ((uint64_t)pm.y << 32) | pm.x;
#pragma unroll
        for (int g = 0; g < 8; g++) {
            uint32_t ph[4];
#pragma unroll
            for (int q = 0; q < 8; q += 2) {
                int c = g * 8 + q;
                float4 q0 = fBD[jh64 + c];
                float4 q1 = fBD[jh64 + c + 1];
                float s0 = g1r + q0.x, s1 = g1r + q1.x;
                float w0 = ((m64 >> c) & 1)       ? (s0 > 0.f ? Arow * q0.y : Crow * q0.z) : 0.f;
                float w1 = ((m64 >> (c + 1)) & 1) ? (s1 > 0.f ? Arow * q1.y : Crow * q1.z) : 0.f;
                dacc += w0 + w1;
                F16X2(ph[q >> 1], w0, w1);
            }
            uint32_t o = (uint32_t)row * PSTR + (uint32_t)(jh64 + g * 8) * 2u;
            *(uint4*)(smem + A2_PHI + o) = *(uint4*)ph;
        }
        CPWAITALL();
        __syncthreads();
#pragma unroll
        for (int ks = 0; ks < 8; ks++) {
            uint32_t ah[2][4];
#pragma unroll
            for (int mt = 0; mt < 2; mt++)
                LDSM4(ah[mt], aAddrH + (uint32_t)mt * (16u * PSTR) + (uint32_t)ks * 32u);
#pragma unroll
            for (int p = 0; p < 2; p++) {
                uint32_t bb[4];
                LDSM4(bb, bAddr0 + (uint32_t)p * (16u * PSTR) + (uint32_t)ks * 32u);
#pragma unroll
                for (int mt = 0; mt < 2; mt++) {
                    MMA_F16(acc[mt][2 * p],     ah[mt], bb[0], bb[1]);
                    MMA_F16(acc[mt][2 * p + 1], ah[mt], bb[2], bb[3]);
                }
            }
        }
    }
    dens[t] = dacc;
    __syncthreads();
#pragma unroll
    for (int mt = 0; mt < 2; mt++) {
        int rl = wm * 32 + mt * 16 + (lane >> 2);
        int cl = wn * 32 + (lane & 3) * 2;
#pragma unroll
        for (int nt = 0; nt < 4; nt++) {
            size_t b0 = ((size_t)jcc * NN + i0 + rl) * NC + cl + nt * 8;
            *(float2*)(g_part + b0)                  = *(float2*)&acc[mt][nt][0];
            *(float2*)(g_part + b0 + (size_t)8 * NC) = *(float2*)&acc[mt][nt][2];
        }
    }
    if (t < 128) g_dpart[jcc * NN + i0 + t] = dens[t] + dens[128 + t];
}

// ---------------- K8: combine partials + elu + log_softmax ----------------
__global__ void k_final(float* __restrict__ out) {
    int warp = threadIdx.x >> 5, lane = threadIdx.x & 31;
    int n = blockIdx.x * 8 + warp;
    float den = 0.f;
#pragma unroll
    for (int jc = 0; jc < JCC; jc++) den += g_dpart[jc * NN + n];
    float inv = 1.f / den;
    float v0 = 0.f, v1 = 0.f;
#pragma unroll
    for (int jc = 0; jc < JCC; jc++) {
        size_t base = ((size_t)jc * NN + n) * NC;
        v0 += g_part[base + lane];
        v1 += g_part[base + lane + 32];
    }
    v0 *= inv; v1 *= inv;
    v0 = v0 > 0.f ? v0 : (expf(v0) - 1.f);
    v1 = v1 > 0.f ? v1 : (expf(v1) - 1.f);
    float m = fmaxf(v0, v1);
#pragma unroll
    for (int o = 16; o; o >>= 1) m = fmaxf(m, __shfl_xor_sync(0xffffffffu, m, o));
    float s = expf(v0 - m) + expf(v1 - m);
#pragma unroll
    for (int o = 16; o; o >>= 1) s += __shfl_xor_sync(0xffffffffu, s, o);
    float lse = m + logf(s);
    out[(size_t)n * NC + lane] = v0 - lse;
    out[(size_t)n * NC + lane + 32] = v1 - lse;
}

// ---------------- launch ----------------
extern "C" void kernel_launch(void* const* d_in, const int* in_sizes, int n_in,
                              void* d_out, int out_size) {
    const float* x   = (const float*)d_in[0];
    const int*   adj = (const int*)d_in[1];
    const float* W   = (const float*)d_in[2];
    const float* a1  = (const float*)d_in[3];
    const float* a2  = (const float*)d_in[4];
    const float* Wo  = (const float*)d_in[5];
    const float* ao1 = (const float*)d_in[6];
    const float* ao2 = (const float*)d_in[7];
    float* out = (float*)d_out;

    cudaFuncSetAttribute(k_wh, cudaFuncAttributeMaxDynamicSharedMemorySize, SMEM_WH);
    cudaFuncSetAttribute(k_attn1, cudaFuncAttributeMaxDynamicSharedMemorySize, SMEM_A1);
    cudaFuncSetAttribute(k_attn2, cudaFuncAttributeMaxDynamicSharedMemorySize, SMEM_A2);

    k_pack  <<<NN, 128>>>(adj);
    k_splitx<<<(NN * NF / 4) / 256, 256>>>(x);
    k_splitw<<<dim3(NF / 32, ND / 32, NH), 256>>>(W);
    k_wh    <<<dim3(NN / 128, NH), 256, SMEM_WH>>>(a1, a2);
    k_fmax  <<<NH, 256>>>();
    k_attn1 <<<dim3(NN / 128, NH), 256, SMEM_A1>>>();
    k_who   <<<dim3(NN / 64, KC), 256>>>(Wo);
    k_g     <<<NN / 8, 256>>>(ao1, ao2);
    k_gmax  <<<1, 256>>>();
    k_whoT  <<<NN / 64, 256>>>();
    k_attn2 <<<dim3(NN / 128, JCC), 256, SMEM_A2>>>();
    k_final <<<NN / 8, 256>>>(out);
}

// round 10
// speedup vs baseline: 5.0169x; 1.1300x over previous
#include <cuda_runtime.h>
#include <cuda_fp16.h>
#include <math.h>
#include <stdint.h>

#define NN 4096
#define NF 1024
#define NH 8
#define ND 128
#define NC 64
#define HD (NH*ND)      // 1024
#define NW (NN/32)      // 128 mask words per row
#define LALPHA 0.2f
#define KC 4            // split-K chunks for k_who
#define JCC 16          // j-split chunks for output attention layer

// ---------------- scratch (static device globals; no allocs) ----------------
__device__ unsigned g_mask[(size_t)NN*NW];         // 2 MB packed adjacency
__device__ __half g_VT[(size_t)NH*ND*NN];          // 8 MB  Wh^T fp16 [h][d][n]
__device__ __half g_xhi[(size_t)NN*NF];            // 8 MB  x fp16
__device__ __half g_WT[(size_t)NH*ND*NF];          // 2 MB  W^T fp16 [h][d][f]
__device__ float g_f1[NH*NN];
__device__ float g_f2[NH*NN];
__device__ unsigned g_f2maxU[NH];
__device__ float g_hcat[(size_t)NN*HD];            // 16 MB  elu(h) concat
__device__ float g_Who[(size_t)NN*NC];             // 1 MB
__device__ __half g_WhoT[(size_t)NC*NN];           // 512 KB Who^T fp16 [c][n]
__device__ float g_g1[NN];
__device__ float g_g2[NN];
__device__ unsigned g_gmaxU[1];
__device__ float g_part[(size_t)JCC*NN*NC];        // 16 MB partials (who & attn2)
__device__ float g_dpart[JCC*NN];                  // partial denominators

__device__ __forceinline__ float lrelu(float s) { return s > 0.f ? s : LALPHA * s; }

// monotone float<->uint for atomicMax over signed floats
__device__ __forceinline__ unsigned fenc(float f) {
    unsigned b = __float_as_uint(f);
    return (b & 0x80000000u) ? ~b : (b | 0x80000000u);
}
__device__ __forceinline__ float fdec(unsigned k) {
    unsigned b = (k & 0x80000000u) ? (k ^ 0x80000000u) : ~k;
    return __uint_as_float(b);
}

__device__ __forceinline__ uint32_t s2u(const void* p) {
    uint32_t a;
    asm("{ .reg .u64 t; cvta.to.shared.u64 t, %1; cvt.u32.u64 %0, t; }" : "=r"(a) : "l"(p));
    return a;
}

#define LDSM4(r, addr) \
    asm volatile("ldmatrix.sync.aligned.m8n8.x4.shared.b16 {%0,%1,%2,%3}, [%4];" \
        : "=r"((r)[0]), "=r"((r)[1]), "=r"((r)[2]), "=r"((r)[3]) : "r"(addr))

#define MMA_F16(c, a, b0, b1) \
    asm volatile("mma.sync.aligned.m16n8k16.row.col.f32.f16.f16.f32 " \
        "{%0,%1,%2,%3}, {%4,%5,%6,%7}, {%8,%9}, {%0,%1,%2,%3};" \
        : "+f"((c)[0]), "+f"((c)[1]), "+f"((c)[2]), "+f"((c)[3]) \
        : "r"((a)[0]), "r"((a)[1]), "r"((a)[2]), "r"((a)[3]), "r"(b0), "r"(b1))

#define CP16(dst, src) \
    asm volatile("cp.async.cg.shared.global [%0], [%1], 16;" :: "r"(dst), "l"(src))
#define CPCOMMIT() asm volatile("cp.async.commit_group;" ::: "memory")
#define CPWAITALL() asm volatile("cp.async.wait_all;" ::: "memory")

// pack two floats to half2: lo=w0, hi=w1
#define F16X2(d, w0, w1) \
    asm("cvt.rn.f16x2.f32 %0, %1, %2;" : "=r"(d) : "f"(w1), "f"(w0))

// ---------------- K1: pack adj -> bitmask (+ init atomic-max cells) --------
__global__ void k_pack(const int* __restrict__ adj) {
    int row = blockIdx.x;
    int warp = threadIdx.x >> 5, lane = threadIdx.x & 31;
    if (row == 0 && threadIdx.x < NH + 1) {
        if (threadIdx.x < NH) g_f2maxU[threadIdx.x] = 0u;
        else g_gmaxU[0] = 0u;
    }
    const int* ar = adj + (size_t)row * NN;
    for (int w = warp; w < NW; w += 4) {
        unsigned b = __ballot_sync(0xffffffffu, ar[w * 32 + lane] > 0);
        if (lane == 0) g_mask[(size_t)row * NW + w] = b;
    }
}

// ---------------- K1b: x -> fp16 ----------------
__global__ void k_splitx(const float* __restrict__ x) {
    int i = blockIdx.x * 256 + threadIdx.x;
    float4 v = *(const float4*)(x + (size_t)i * 4);
    uint2 ho;
    F16X2(ho.x, v.x, v.y);
    F16X2(ho.y, v.z, v.w);
    *(uint2*)(g_xhi + (size_t)i * 4) = ho;
}

// ---------------- K1c: W -> W^T fp16  [h][f][d] -> [h][d][f] ---------------
__global__ void k_splitw(const float* __restrict__ W) {
    __shared__ float ts[32][33];
    int f0 = blockIdx.x * 32, d0 = blockIdx.y * 32, h = blockIdx.z;
    int t = threadIdx.x;
    int r = t >> 3, c4 = (t & 7) * 4;
    float4 v = *(const float4*)(W + ((size_t)h * NF + f0 + r) * ND + d0 + c4);
    ts[r][c4] = v.x; ts[r][c4 + 1] = v.y; ts[r][c4 + 2] = v.z; ts[r][c4 + 3] = v.w;
    __syncthreads();
    int rr = t >> 3, cc = (t & 7) * 4;
    uint2 hp;
    F16X2(hp.x, ts[cc][rr], ts[cc + 1][rr]);
    F16X2(hp.y, ts[cc + 2][rr], ts[cc + 3][rr]);
    *(uint2*)(g_WT + ((size_t)h * ND + d0 + rr) * NF + f0 + cc) = hp;
}

// ---------------- K2: Wh = x @ W, fp16 1-prod, cp.async double-buffered ----
#define WSTR 144u
#define STAGE 36864u         // A@0, B@18432 (per stage)
#define CSTR 130
#define SM_A1  73728
#define SM_A2  74240
#define SM_RED 74752
#define SMEM_WH 74784
__global__ __launch_bounds__(256, 2) void k_wh(const float* __restrict__ a1,
                                               const float* __restrict__ a2) {
    extern __shared__ char smem[];
    uint32_t sb = s2u(smem);
    int t = threadIdx.x, lane = t & 31, wid = t >> 5;
    int h = blockIdx.y, i0 = blockIdx.x * 128;
    int wm = wid & 3, wn = wid >> 2;
    float* a1s = (float*)(smem + SM_A1);
    float* a2s = (float*)(smem + SM_A2);
    float* sred = (float*)(smem + SM_RED);
    if (t < ND) { a1s[t] = a1[h * ND + t]; a2s[t] = a2[h * ND + t]; }

    float acc[2][8][4];
#pragma unroll
    for (int mt = 0; mt < 2; mt++)
#pragma unroll
        for (int nt = 0; nt < 8; nt++)
#pragma unroll
            for (int q = 0; q < 4; q++) acc[mt][nt][q] = 0.f;

    uint32_t aBase = sb + (uint32_t)(wm * 32 + (lane & 15)) * WSTR + (uint32_t)(lane >> 4) * 16u;
    int brow = ((lane >> 4) << 3) + (lane & 7);
    uint32_t bBase = sb + 18432u + (uint32_t)(wn * 64 + brow) * WSTR + (uint32_t)((lane >> 3) & 1) * 16u;

    int srow = t >> 3, sch = (t & 7) * 8;
    uint32_t so0 = (uint32_t)srow * WSTR + (uint32_t)sch * 2u;

    // prologue: stage 0
    {
        uint32_t s0 = sb;
#pragma unroll
        for (int c = 0; c < 4; c++) {
            uint32_t o = so0 + (uint32_t)c * (32u * WSTR);
            size_t ga = (size_t)(i0 + c * 32 + srow) * NF + sch;
            size_t gb = ((size_t)h * ND + c * 32 + srow) * NF + sch;
            CP16(s0 + o,          g_xhi + ga);
            CP16(s0 + 18432u + o, g_WT + gb);
        }
        CPCOMMIT();
    }
    for (int kt = 0; kt < 16; kt++) {
        uint32_t buf = (uint32_t)(kt & 1) * STAGE;
        if (kt < 15) {
            uint32_t s0 = sb + (uint32_t)((kt + 1) & 1) * STAGE;
            int f0 = (kt + 1) * 64;
#pragma unroll
            for (int c = 0; c < 4; c++) {
                uint32_t o = so0 + (uint32_t)c * (32u * WSTR);
                size_t ga = (size_t)(i0 + c * 32 + srow) * NF + f0 + sch;
                size_t gb = ((size_t)h * ND + c * 32 + srow) * NF + f0 + sch;
                CP16(s0 + o,          g_xhi + ga);
                CP16(s0 + 18432u + o, g_WT + gb);
            }
            CPCOMMIT();
            asm volatile("cp.async.wait_group 1;" ::: "memory");
        } else {
            asm volatile("cp.async.wait_group 0;" ::: "memory");
        }
        __syncthreads();
#pragma unroll
        for (int ks = 0; ks < 4; ks++) {
            uint32_t ah[2][4];
#pragma unroll
            for (int mt = 0; mt < 2; mt++)
                LDSM4(ah[mt], aBase + buf + (uint32_t)mt * (16u * WSTR) + (uint32_t)ks * 32u);
#pragma unroll
            for (int p = 0; p < 4; p++) {
                uint32_t bb[4];
                LDSM4(bb, bBase + buf + (uint32_t)p * (16u * WSTR) + (uint32_t)ks * 32u);
#pragma unroll
                for (int mt = 0; mt < 2; mt++) {
                    MMA_F16(acc[mt][2 * p],     ah[mt], bb[0], bb[1]);
                    MMA_F16(acc[mt][2 * p + 1], ah[mt], bb[2], bb[3]);
                }
            }
        }
        __syncthreads();
    }
    float* Cst = (float*)smem;
#pragma unroll
    for (int mt = 0; mt < 2; mt++) {
#pragma unroll
        for (int nt = 0; nt < 8; nt++) {
            int rl = wm * 32 + mt * 16 + (lane >> 2);
            int cl = wn * 64 + nt * 8 + (lane & 3) * 2;
            *(float2*)(Cst + rl * CSTR + cl)       = *(float2*)&acc[mt][nt][0];
            *(float2*)(Cst + (rl + 8) * CSTR + cl) = *(float2*)&acc[mt][nt][2];
        }
    }
    __syncthreads();
    {
        int r = t >> 1, half = (t & 1) * 64;
        float p1 = 0.f, p2 = 0.f;
#pragma unroll
        for (int d = 0; d < 64; d++) {
            float v = Cst[r * CSTR + half + d];
            p1 = fmaf(v, a1s[half + d], p1);
            p2 = fmaf(v, a2s[half + d], p2);
        }
        p1 += __shfl_xor_sync(0xffffffffu, p1, 1);
        p2 += __shfl_xor_sync(0xffffffffu, p2, 1);
        if (!(t & 1)) {
            g_f1[h * NN + i0 + r] = p1;
            g_f2[h * NN + i0 + r] = p2;
        }
        // per-CTA f2 max -> single atomic
        float m = p2;
#pragma unroll
        for (int o = 16; o; o >>= 1) m = fmaxf(m, __shfl_xor_sync(0xffffffffu, m, o));
        if (lane == 0) sred[wid] = m;
    }
    __syncthreads();
    if (t == 0) {
        float mm = sred[0];
#pragma unroll
        for (int w = 1; w < 8; w++) mm = fmaxf(mm, sred[w]);
        atomicMax(&g_f2maxU[h], fenc(mm));
    }
    {
        int d = t >> 1, n0 = (t & 1) * 64;
        size_t base = ((size_t)h * ND + d) * NN + i0 + n0;
#pragma unroll
        for (int c = 0; c < 8; c++) {
            uint32_t hp[4];
#pragma unroll
            for (int q = 0; q < 8; q += 2) {
                int n = c * 8 + q;
                F16X2(hp[q >> 1], Cst[(n0 + n) * CSTR + d], Cst[(n0 + n + 1) * CSTR + d]);
            }
            *(uint4*)(g_VT + base + c * 8) = *(uint4*)hp;
        }
    }
}

// ---------------- K4: single-product fp16 aggregation, exp-factored P-gen --
#define PSTR 272u
#define A1_FBD 1024u
#define A1_PHI 3072u
#define A1_V   37888u
#define SMEM_A1 72704
__global__ __launch_bounds__(256, 2) void k_attn1() {
    extern __shared__ char smem[];
    uint32_t sb = s2u(smem);
    int t = threadIdx.x, lane = t & 31, wid = t >> 5;
    int h = blockIdx.y, i0 = blockIdx.x * 128;
    int wm = wid & 3, wn = wid >> 2;
    float* dens = (float*)smem;
    float4* fBD = (float4*)(smem + A1_FBD);

    int row = t & 127, jh64 = (t >> 7) * 64;
    float f1r = g_f1[h * NN + i0 + row];
    float sh = lrelu(f1r + fdec(g_f2maxU[h]));
    float Arow = __expf(f1r - sh);
    float Crow = __expf(LALPHA * f1r - sh);
    float dacc = 0.f;

    float acc[2][8][4];
#pragma unroll
    for (int mt = 0; mt < 2; mt++)
#pragma unroll
        for (int nt = 0; nt < 8; nt++)
#pragma unroll
            for (int q = 0; q < 4; q++) acc[mt][nt][q] = 0.f;

    uint32_t aAddrH = sb + A1_PHI + (uint32_t)(wm * 32 + (lane & 15)) * PSTR + (uint32_t)(lane >> 4) * 16u;
    int brow = ((lane >> 4) << 3) + (lane & 7);
    uint32_t bAddr0 = sb + A1_V + (uint32_t)(wn * 64 + brow) * PSTR + (uint32_t)((lane >> 3) & 1) * 16u;

    const float* f2p = g_f2 + h * NN;
    const unsigned* mrow = g_mask + (size_t)(i0 + row) * NW + (jh64 >> 5);
    float pv = (t < 128) ? f2p[t] : 0.f;
    uint2 pm = *(const uint2*)mrow;

    for (int jt = 0; jt < 32; jt++) {
        int j0 = jt * 128;
        __syncthreads();
#pragma unroll
        for (int c = 0; c < 9; c++) {
            int idx = c * 256 + t;
            if (idx < 2176) {
                int r = idx / 17, ch = idx - r * 17;
                CP16(sb + A1_V + (uint32_t)r * PSTR + (uint32_t)ch * 16u,
                     g_VT + ((size_t)(h * ND + r)) * NN + j0 + ch * 8);
            }
        }
        if (t < 128) {
            float v = pv;
            fBD[t] = make_float4(v, __expf(v), __expf(LALPHA * v), 0.f);
        }
        __syncthreads();
        uint64_t m64 = ((uint64_t)pm.y << 32) | pm.x;
#pragma unroll
        for (int g = 0; g < 8; g++) {
            uint32_t ph[4];
#pragma unroll
            for (int q = 0; q < 8; q += 2) {
                int c = g * 8 + q;
                float4 q0 = fBD[jh64 + c];
                float4 q1 = fBD[jh64 + c + 1];
                float s0 = f1r + q0.x, s1 = f1r + q1.x;
                float w0 = ((m64 >> c) & 1)       ? (s0 > 0.f ? Arow * q0.y : Crow * q0.z) : 0.f;
                float w1 = ((m64 >> (c + 1)) & 1) ? (s1 > 0.f ? Arow * q1.y : Crow * q1.z) : 0.f;
                dacc += w0 + w1;
                F16X2(ph[q >> 1], w0, w1);
            }
            uint32_t o = (uint32_t)row * PSTR + (uint32_t)(jh64 + g * 8) * 2u;
            *(uint4*)(smem + A1_PHI + o) = *(uint4*)ph;
        }
        if (jt < 31) {
            if (t < 128) pv = f2p[j0 + 128 + t];
            pm = *(const uint2*)(mrow + (jt + 1) * 4);
        }
        CPWAITALL();
        __syncthreads();
#pragma unroll
        for (int ks = 0; ks < 8; ks++) {
            uint32_t ah[2][4];
#pragma unroll
            for (int mt = 0; mt < 2; mt++)
                LDSM4(ah[mt], aAddrH + (uint32_t)mt * (16u * PSTR) + (uint32_t)ks * 32u);
#pragma unroll
            for (int p = 0; p < 4; p++) {
                uint32_t bb[4];
                LDSM4(bb, bAddr0 + (uint32_t)p * (16u * PSTR) + (uint32_t)ks * 32u);
#pragma unroll
                for (int mt = 0; mt < 2; mt++) {
                    MMA_F16(acc[mt][2 * p],     ah[mt], bb[0], bb[1]);
                    MMA_F16(acc[mt][2 * p + 1], ah[mt], bb[2], bb[3]);
                }
            }
        }
    }
    dens[t] = dacc;
    __syncthreads();
#pragma unroll
    for (int mt = 0; mt < 2; mt++) {
        int rl = wm * 32 + mt * 16 + (lane >> 2);
        float inv0 = 1.f / (dens[rl] + dens[128 + rl]);
        float inv1 = 1.f / (dens[rl + 8] + dens[128 + rl + 8]);
        float* d0 = g_hcat + (size_t)(i0 + rl) * HD + h * ND + wn * 64 + (lane & 3) * 2;
        float* d1 = d0 + (size_t)8 * HD;
#pragma unroll
        for (int nt = 0; nt < 8; nt++) {
            float z0 = acc[mt][nt][0] * inv0, z1 = acc[mt][nt][1] * inv0;
            float z2 = acc[mt][nt][2] * inv1, z3 = acc[mt][nt][3] * inv1;
            float2 o0, o1;
            o0.x = z0 > 0.f ? z0 : (__expf(z0) - 1.f);
            o0.y = z1 > 0.f ? z1 : (__expf(z1) - 1.f);
            o1.x = z2 > 0.f ? z2 : (__expf(z2) - 1.f);
            o1.y = z3 > 0.f ? z3 : (__expf(z3) - 1.f);
            *(float2*)(d0 + nt * 8) = o0;
            *(float2*)(d1 + nt * 8) = o1;
        }
    }
}

// ---------------- K5: Who partials, split-K (64x64 tiles, KC chunks) -------
__global__ __launch_bounds__(256) void k_who(const float* __restrict__ Wo) {
    __shared__ float As[16][68];
    __shared__ float Bs[16][64];
    int i0 = blockIdx.x * 64, kc = blockIdx.y;
    int t = threadIdx.x, ty = t >> 4, tx = t & 15;
    float acc[4][4];
#pragma unroll
    for (int u = 0; u < 4; u++)
#pragma unroll
        for (int v = 0; v < 4; v++) acc[u][v] = 0.f;
    int fbeg = kc * (HD / KC);
    for (int f0 = fbeg; f0 < fbeg + HD / KC; f0 += 16) {
        {
            int r = t >> 2, k4 = (t & 3) * 4;
            float4 v = *(const float4*)(g_hcat + (size_t)(i0 + r) * HD + f0 + k4);
            As[k4 + 0][r] = v.x; As[k4 + 1][r] = v.y;
            As[k4 + 2][r] = v.z; As[k4 + 3][r] = v.w;
        }
        {
            int kk = t >> 4, d4 = (t & 15) * 4;
            *(float4*)&Bs[kk][d4] = *(const float4*)(Wo + (size_t)(f0 + kk) * NC + d4);
        }
        __syncthreads();
#pragma unroll
        for (int k = 0; k < 16; k++) {
            float ra[4], rb[4];
            *(float4*)ra = *(float4*)&As[k][ty * 4];
            *(float4*)rb = *(float4*)&Bs[k][tx * 4];
#pragma unroll
            for (int u = 0; u < 4; u++)
#pragma unroll
                for (int v = 0; v < 4; v++) acc[u][v] = fmaf(ra[u], rb[v], acc[u][v]);
        }
        __syncthreads();
    }
#pragma unroll
    for (int u = 0; u < 4; u++)
        *(float4*)(g_part + ((size_t)kc * NN + i0 + ty * 4 + u) * NC + tx * 4) = *(float4*)&acc[u][0];
}

// ---------------- K6: combine Who partials; g1,g2 (+gmax atomic) ----------
__global__ void k_g(const float* __restrict__ ao1, const float* __restrict__ ao2) {
    __shared__ float red[8];
    int warp = threadIdx.x >> 5, lane = threadIdx.x & 31;
    int n = blockIdx.x * 8 + warp;
    float v0 = 0.f, v1 = 0.f;
#pragma unroll
    for (int kc = 0; kc < KC; kc++) {
        size_t base = ((size_t)kc * NN + n) * NC;
        v0 += g_part[base + lane];
        v1 += g_part[base + lane + 32];
    }
    g_Who[(size_t)n * NC + lane] = v0;
    g_Who[(size_t)n * NC + lane + 32] = v1;
    float s1 = fmaf(v0, ao1[lane], v1 * ao1[lane + 32]);
    float s2 = fmaf(v0, ao2[lane], v1 * ao2[lane + 32]);
#pragma unroll
    for (int o = 16; o; o >>= 1) {
        s1 += __shfl_xor_sync(0xffffffffu, s1, o);
        s2 += __shfl_xor_sync(0xffffffffu, s2, o);
    }
    if (lane == 0) { g_g1[n] = s1; g_g2[n] = s2; red[warp] = s2; }
    __syncthreads();
    if (threadIdx.x == 0) {
        float mm = red[0];
#pragma unroll
        for (int w = 1; w < 8; w++) mm = fmaxf(mm, red[w]);
        atomicMax(&g_gmaxU[0], fenc(mm));
    }
}

// ---------------- K6c: Who -> Who^T fp16 [c][n] ----------------
__global__ void k_whoT() {
    __shared__ float ts[64][65];
    int n0 = blockIdx.x * 64, t = threadIdx.x;
#pragma unroll
    for (int k = 0; k < 16; k++) {
        int idx = k * 256 + t;
        int r = idx >> 6, c = idx & 63;
        ts[r][c] = g_Who[(size_t)(n0 + r) * NC + c];
    }
    __syncthreads();
    int c = t >> 2, nq = (t & 3) * 16;
    uint32_t hp[8];
#pragma unroll
    for (int q = 0; q < 16; q += 2)
        F16X2(hp[q >> 1], ts[nq + q][c], ts[nq + q + 1][c]);
    *(uint4*)(g_WhoT + (size_t)c * NN + n0 + nq)     = *(uint4*)hp;
    *(uint4*)(g_WhoT + (size_t)c * NN + n0 + nq + 8) = *(uint4*)(hp + 4);
}

// ---------------- K7: output attention, single-product fp16 HMMA -----------
#define A2_FBD 1024u
#define A2_PHI 3072u
#define A2_B   37888u
#define SMEM_A2 55296
__global__ __launch_bounds__(256, 2) void k_attn2() {
    extern __shared__ char smem[];
    uint32_t sb = s2u(smem);
    int t = threadIdx.x, lane = t & 31, wid = t >> 5;
    int jcc = blockIdx.y, i0 = blockIdx.x * 128;
    int wm = wid & 3, wn = wid >> 2;
    float* dens = (float*)smem;
    float4* fBD = (float4*)(smem + A2_FBD);

    int row = t & 127, jh64 = (t >> 7) * 64;
    float g1r = g_g1[i0 + row];
    float sh = lrelu(g1r + fdec(g_gmaxU[0]));
    float Arow = __expf(g1r - sh);
    float Crow = __expf(LALPHA * g1r - sh);
    float dacc = 0.f;

    float acc[2][4][4];
#pragma unroll
    for (int mt = 0; mt < 2; mt++)
#pragma unroll
        for (int nt = 0; nt < 4; nt++)
#pragma unroll
            for (int q = 0; q < 4; q++) acc[mt][nt][q] = 0.f;

    uint32_t aAddrH = sb + A2_PHI + (uint32_t)(wm * 32 + (lane & 15)) * PSTR + (uint32_t)(lane >> 4) * 16u;
    int brow = ((lane >> 4) << 3) + (lane & 7);
    uint32_t bAddr0 = sb + A2_B + (uint32_t)(wn * 32 + brow) * PSTR + (uint32_t)((lane >> 3) & 1) * 16u;

    const unsigned* mrow = g_mask + (size_t)(i0 + row) * NW + (jh64 >> 5);

    for (int jj = 0; jj < 2; jj++) {
        int jt = jcc * 2 + jj, j0 = jt * 128;
        __syncthreads();
#pragma unroll
        for (int c = 0; c < 5; c++) {
            int idx = c * 256 + t;
            if (idx < 1088) {
                int r = idx / 17, ch = idx - r * 17;
                CP16(sb + A2_B + (uint32_t)r * PSTR + (uint32_t)ch * 16u,
                     g_WhoT + (size_t)r * NN + j0 + ch * 8);
            }
        }
        if (t < 128) {
            float v = g_g2[j0 + t];
            fBD[t] = make_float4(v, __expf(v), __expf(LALPHA * v), 0.f);
        }
        __syncthreads();
        uint2 pm = *(const uint2*)(mrow + jt * 4);
        uint64_t m64 = ((uint64_t)pm.y << 32) | pm.x;
#pragma unroll
        for (int g = 0; g < 8; g++) {
            uint32_t ph[4];
#pragma unroll
            for (int q = 0; q < 8; q += 2) {
                int c = g * 8 + q;
                float4 q0 = fBD[jh64 + c];
                float4 q1 = fBD[jh64 + c + 1];
                float s0 = g1r + q0.x, s1 = g1r + q1.x;
                float w0 = ((m64 >> c) & 1)       ? (s0 > 0.f ? Arow * q0.y : Crow * q0.z) : 0.f;
                float w1 = ((m64 >> (c + 1)) & 1) ? (s1 > 0.f ? Arow * q1.y : Crow * q1.z) : 0.f;
                dacc += w0 + w1;
                F16X2(ph[q >> 1], w0, w1);
            }
            uint32_t o = (uint32_t)row * PSTR + (uint32_t)(jh64 + g * 8) * 2u;
            *(uint4*)(smem + A2_PHI + o) = *(uint4*)ph;
        }
        CPWAITALL();
        __syncthreads();
#pragma unroll
        for (int ks = 0; ks < 8; ks++) {
            uint32_t ah[2][4];
#pragma unroll
            for (int mt = 0; mt < 2; mt++)
                LDSM4(ah[mt], aAddrH + (uint32_t)mt * (16u * PSTR) + (uint32_t)ks * 32u);
#pragma unroll
            for (int p = 0; p < 2; p++) {
                uint32_t bb[4];
                LDSM4(bb, bAddr0 + (uint32_t)p * (16u * PSTR) + (uint32_t)ks * 32u);
#pragma unroll
                for (int mt = 0; mt < 2; mt++) {
                    MMA_F16(acc[mt][2 * p],     ah[mt], bb[0], bb[1]);
                    MMA_F16(acc[mt][2 * p + 1], ah[mt], bb[2], bb[3]);
                }
            }
        }
    }
    dens[t] = dacc;
    __syncthreads();
#pragma unroll
    for (int mt = 0; mt < 2; mt++) {
        int rl = wm * 32 + mt * 16 + (lane >> 2);
        int cl = wn * 32 + (lane & 3) * 2;
#pragma unroll
        for (int nt = 0; nt < 4; nt++) {
            size_t b0 = ((size_t)jcc * NN + i0 + rl) * NC + cl + nt * 8;
            *(float2*)(g_part + b0)                  = *(float2*)&acc[mt][nt][0];
            *(float2*)(g_part + b0 + (size_t)8 * NC) = *(float2*)&acc[mt][nt][2];
        }
    }
    if (t < 128) g_dpart[jcc * NN + i0 + t] = dens[t] + dens[128 + t];
}

// ---------------- K8: combine partials + elu + log_softmax ----------------
__global__ void k_final(float* __restrict__ out) {
    int warp = threadIdx.x >> 5, lane = threadIdx.x & 31;
    int n = blockIdx.x * 8 + warp;
    float den = 0.f;
#pragma unroll
    for (int jc = 0; jc < JCC; jc++) den += g_dpart[jc * NN + n];
    float inv = 1.f / den;
    float v0 = 0.f, v1 = 0.f;
#pragma unroll
    for (int jc = 0; jc < JCC; jc++) {
        size_t base = ((size_t)jc * NN + n) * NC;
        v0 += g_part[base + lane];
        v1 += g_part[base + lane + 32];
    }
    v0 *= inv; v1 *= inv;
    v0 = v0 > 0.f ? v0 : (expf(v0) - 1.f);
    v1 = v1 > 0.f ? v1 : (expf(v1) - 1.f);
    float m = fmaxf(v0, v1);
#pragma unroll
    for (int o = 16; o; o >>= 1) m = fmaxf(m, __shfl_xor_sync(0xffffffffu, m, o));
    float s = expf(v0 - m) + expf(v1 - m);
#pragma unroll
    for (int o = 16; o; o >>= 1) s += __shfl_xor_sync(0xffffffffu, s, o);
    float lse = m + logf(s);
    out[(size_t)n * NC + lane] = v0 - lse;
    out[(size_t)n * NC + lane + 32] = v1 - lse;
}

// ---------------- launch ----------------
extern "C" void kernel_launch(void* const* d_in, const int* in_sizes, int n_in,
                              void* d_out, int out_size) {
    const float* x   = (const float*)d_in[0];
    const int*   adj = (const int*)d_in[1];
    const float* W   = (const float*)d_in[2];
    const float* a1  = (const float*)d_in[3];
    const float* a2  = (const float*)d_in[4];
    const float* Wo  = (const float*)d_in[5];
    const float* ao1 = (const float*)d_in[6];
    const float* ao2 = (const float*)d_in[7];
    float* out = (float*)d_out;

    cudaFuncSetAttribute(k_wh, cudaFuncAttributeMaxDynamicSharedMemorySize, SMEM_WH);
    cudaFuncSetAttribute(k_attn1, cudaFuncAttributeMaxDynamicSharedMemorySize, SMEM_A1);
    cudaFuncSetAttribute(k_attn2, cudaFuncAttributeMaxDynamicSharedMemorySize, SMEM_A2);

    k_pack  <<<NN, 128>>>(adj);
    k_splitx<<<(NN * NF / 4) / 256, 256>>>(x);
    k_splitw<<<dim3(NF / 32, ND / 32, NH), 256>>>(W);
    k_wh    <<<dim3(NN / 128, NH), 256, SMEM_WH>>>(a1, a2);
    k_attn1 <<<dim3(NN / 128, NH), 256, SMEM_A1>>>();
    k_who   <<<dim3(NN / 64, KC), 256>>>(Wo);
    k_g     <<<NN / 8, 256>>>(ao1, ao2);
    k_whoT  <<<NN / 64, 256>>>();
    k_attn2 <<<dim3(NN / 128, JCC), 256, SMEM_A2>>>();
    k_final <<<NN / 8, 256>>>(out);
}

// round 14
// speedup vs baseline: 5.1415x; 1.0248x over previous
#include <cuda_runtime.h>
#include <cuda_fp16.h>
#include <math.h>
#include <stdint.h>

#define NN 4096
#define NF 1024
#define NH 8
#define ND 128
#define NC 64
#define HD (NH*ND)      // 1024
#define NW (NN/32)      // 128 mask words per row
#define LALPHA 0.2f
#define KC 4            // split-K chunks for k_who
#define JCC 8           // j-split chunks for output attention layer

// ---------------- scratch (static device globals; no allocs) ----------------
__device__ unsigned g_mask[(size_t)NN*NW];         // 2 MB packed adjacency
__device__ __half g_VT[(size_t)NH*ND*NN];          // 8 MB  Wh^T fp16 [h][d][n]
__device__ __half g_xhi[(size_t)NN*NF];            // 8 MB  x fp16
__device__ __half g_WT[(size_t)NH*ND*NF];          // 2 MB  W^T fp16 [h][d][f]
__device__ float g_f1[NH*NN];
__device__ float g_f2[NH*NN];
__device__ unsigned g_f2maxU[NH];
__device__ __half g_hcat[(size_t)NN*HD];           // 8 MB  elu(h) concat, fp16
__device__ __half g_WhoT[(size_t)NC*NN];           // 512 KB Who^T fp16 [c][n]
__device__ float g_g1[NN];
__device__ float g_g2[NN];
__device__ unsigned g_gmaxU[1];
__device__ float g_part[(size_t)JCC*NN*NC];        // 8 MB partials (who & attn2)
__device__ float g_dpart[JCC*NN];                  // partial denominators

__device__ __forceinline__ float lrelu(float s) { return s > 0.f ? s : LALPHA * s; }

// monotone float<->uint for atomicMax over signed floats
__device__ __forceinline__ unsigned fenc(float f) {
    unsigned b = __float_as_uint(f);
    return (b & 0x80000000u) ? ~b : (b | 0x80000000u);
}
__device__ __forceinline__ float fdec(unsigned k) {
    unsigned b = (k & 0x80000000u) ? (k ^ 0x80000000u) : ~k;
    return __uint_as_float(b);
}

__device__ __forceinline__ uint32_t s2u(const void* p) {
    uint32_t a;
    asm("{ .reg .u64 t; cvta.to.shared.u64 t, %1; cvt.u32.u64 %0, t; }" : "=r"(a) : "l"(p));
    return a;
}

#define LDSM4(r, addr) \
    asm volatile("ldmatrix.sync.aligned.m8n8.x4.shared.b16 {%0,%1,%2,%3}, [%4];" \
        : "=r"((r)[0]), "=r"((r)[1]), "=r"((r)[2]), "=r"((r)[3]) : "r"(addr))

#define MMA_F16(c, a, b0, b1) \
    asm volatile("mma.sync.aligned.m16n8k16.row.col.f32.f16.f16.f32 " \
        "{%0,%1,%2,%3}, {%4,%5,%6,%7}, {%8,%9}, {%0,%1,%2,%3};" \
        : "+f"((c)[0]), "+f"((c)[1]), "+f"((c)[2]), "+f"((c)[3]) \
        : "r"((a)[0]), "r"((a)[1]), "r"((a)[2]), "r"((a)[3]), "r"(b0), "r"(b1))

#define CP16(dst, src) \
    asm volatile("cp.async.cg.shared.global [%0], [%1], 16;" :: "r"(dst), "l"(src))
#define CPCOMMIT() asm volatile("cp.async.commit_group;" ::: "memory")
#define CPWAITALL() asm volatile("cp.async.wait_all;" ::: "memory")

// pack two floats to half2: lo=w0, hi=w1
#define F16X2(d, w0, w1) \
    asm("cvt.rn.f16x2.f32 %0, %1, %2;" : "=r"(d) : "f"(w1), "f"(w0))

// ---------------- K1: pack adj -> bitmask (+ init atomic-max cells) --------
__global__ void k_pack(const int* __restrict__ adj) {
    int row = blockIdx.x;
    int warp = threadIdx.x >> 5, lane = threadIdx.x & 31;
    if (row == 0 && threadIdx.x < NH + 1) {
        if (threadIdx.x < NH) g_f2maxU[threadIdx.x] = 0u;
        else g_gmaxU[0] = 0u;
    }
    const int* ar = adj + (size_t)row * NN;
    for (int w = warp; w < NW; w += 4) {
        unsigned b = __ballot_sync(0xffffffffu, ar[w * 32 + lane] > 0);
        if (lane == 0) g_mask[(size_t)row * NW + w] = b;
    }
}

// ---------------- K1b: x -> fp16 ----------------
__global__ void k_splitx(const float* __restrict__ x) {
    int i = blockIdx.x * 256 + threadIdx.x;
    float4 v = *(const float4*)(x + (size_t)i * 4);
    uint2 ho;
    F16X2(ho.x, v.x, v.y);
    F16X2(ho.y, v.z, v.w);
    *(uint2*)(g_xhi + (size_t)i * 4) = ho;
}

// ---------------- K1c: W -> W^T fp16  [h][f][d] -> [h][d][f] ---------------
__global__ void k_splitw(const float* __restrict__ W) {
    __shared__ float ts[32][33];
    int f0 = blockIdx.x * 32, d0 = blockIdx.y * 32, h = blockIdx.z;
    int t = threadIdx.x;
    int r = t >> 3, c4 = (t & 7) * 4;
    float4 v = *(const float4*)(W + ((size_t)h * NF + f0 + r) * ND + d0 + c4);
    ts[r][c4] = v.x; ts[r][c4 + 1] = v.y; ts[r][c4 + 2] = v.z; ts[r][c4 + 3] = v.w;
    __syncthreads();
    int rr = t >> 3, cc = (t & 7) * 4;
    uint2 hp;
    F16X2(hp.x, ts[cc][rr], ts[cc + 1][rr]);
    F16X2(hp.y, ts[cc + 2][rr], ts[cc + 3][rr]);
    *(uint2*)(g_WT + ((size_t)h * ND + d0 + rr) * NF + f0 + cc) = hp;
}

// ---------------- K2: Wh = x @ W, fp16 1-prod, cp.async double-buffered ----
#define WSTR 144u
#define STAGE 36864u         // A@0, B@18432 (per stage)
#define CSTR 130
#define SM_A1  73728
#define SM_A2  74240
#define SM_RED 74752
#define SMEM_WH 74784
__global__ __launch_bounds__(256, 2) void k_wh(const float* __restrict__ a1,
                                               const float* __restrict__ a2) {
    extern __shared__ char smem[];
    uint32_t sb = s2u(smem);
    int t = threadIdx.x, lane = t & 31, wid = t >> 5;
    int h = blockIdx.y, i0 = blockIdx.x * 128;
    int wm = wid & 3, wn = wid >> 2;
    float* a1s = (float*)(smem + SM_A1);
    float* a2s = (float*)(smem + SM_A2);
    float* sred = (float*)(smem + SM_RED);
    if (t < ND) { a1s[t] = a1[h * ND + t]; a2s[t] = a2[h * ND + t]; }

    float acc[2][8][4];
#pragma unroll
    for (int mt = 0; mt < 2; mt++)
#pragma unroll
        for (int nt = 0; nt < 8; nt++)
#pragma unroll
            for (int q = 0; q < 4; q++) acc[mt][nt][q] = 0.f;

    uint32_t aBase = sb + (uint32_t)(wm * 32 + (lane & 15)) * WSTR + (uint32_t)(lane >> 4) * 16u;
    int brow = ((lane >> 4) << 3) + (lane & 7);
    uint32_t bBase = sb + 18432u + (uint32_t)(wn * 64 + brow) * WSTR + (uint32_t)((lane >> 3) & 1) * 16u;

    int srow = t >> 3, sch = (t & 7) * 8;
    uint32_t so0 = (uint32_t)srow * WSTR + (uint32_t)sch * 2u;

    {
        uint32_t s0 = sb;
#pragma unroll
        for (int c = 0; c < 4; c++) {
            uint32_t o = so0 + (uint32_t)c * (32u * WSTR);
            size_t ga = (size_t)(i0 + c * 32 + srow) * NF + sch;
            size_t gb = ((size_t)h * ND + c * 32 + srow) * NF + sch;
            CP16(s0 + o,          g_xhi + ga);
            CP16(s0 + 18432u + o, g_WT + gb);
        }
        CPCOMMIT();
    }
    for (int kt = 0; kt < 16; kt++) {
        uint32_t buf = (uint32_t)(kt & 1) * STAGE;
        if (kt < 15) {
            uint32_t s0 = sb + (uint32_t)((kt + 1) & 1) * STAGE;
            int f0 = (kt + 1) * 64;
#pragma unroll
            for (int c = 0; c < 4; c++) {
                uint32_t o = so0 + (uint32_t)c * (32u * WSTR);
                size_t ga = (size_t)(i0 + c * 32 + srow) * NF + f0 + sch;
                size_t gb = ((size_t)h * ND + c * 32 + srow) * NF + f0 + sch;
                CP16(s0 + o,          g_xhi + ga);
                CP16(s0 + 18432u + o, g_WT + gb);
            }
            CPCOMMIT();
            asm volatile("cp.async.wait_group 1;" ::: "memory");
        } else {
            asm volatile("cp.async.wait_group 0;" ::: "memory");
        }
        __syncthreads();
#pragma unroll
        for (int ks = 0; ks < 4; ks++) {
            uint32_t ah[2][4];
#pragma unroll
            for (int mt = 0; mt < 2; mt++)
                LDSM4(ah[mt], aBase + buf + (uint32_t)mt * (16u * WSTR) + (uint32_t)ks * 32u);
#pragma unroll
            for (int p = 0; p < 4; p++) {
                uint32_t bb[4];
                LDSM4(bb, bBase + buf + (uint32_t)p * (16u * WSTR) + (uint32_t)ks * 32u);
#pragma unroll
                for (int mt = 0; mt < 2; mt++) {
                    MMA_F16(acc[mt][2 * p],     ah[mt], bb[0], bb[1]);
                    MMA_F16(acc[mt][2 * p + 1], ah[mt], bb[2], bb[3]);
                }
            }
        }
        __syncthreads();
    }
    float* Cst = (float*)smem;
#pragma unroll
    for (int mt = 0; mt < 2; mt++) {
#pragma unroll
        for (int nt = 0; nt < 8; nt++) {
            int rl = wm * 32 + mt * 16 + (lane >> 2);
            int cl = wn * 64 + nt * 8 + (lane & 3) * 2;
            *(float2*)(Cst + rl * CSTR + cl)       = *(float2*)&acc[mt][nt][0];
            *(float2*)(Cst + (rl + 8) * CSTR + cl) = *(float2*)&acc[mt][nt][2];
        }
    }
    __syncthreads();
    {
        int r = t >> 1, half = (t & 1) * 64;
        float p1 = 0.f, p2 = 0.f;
#pragma unroll
        for (int d = 0; d < 64; d++) {
            float v = Cst[r * CSTR + half + d];
            p1 = fmaf(v, a1s[half + d], p1);
            p2 = fmaf(v, a2s[half + d], p2);
        }
        p1 += __shfl_xor_sync(0xffffffffu, p1, 1);
        p2 += __shfl_xor_sync(0xffffffffu, p2, 1);
        if (!(t & 1)) {
            g_f1[h * NN + i0 + r] = p1;
            g_f2[h * NN + i0 + r] = p2;
        }
        float m = p2;
#pragma unroll
        for (int o = 16; o; o >>= 1) m = fmaxf(m, __shfl_xor_sync(0xffffffffu, m, o));
        if (lane == 0) sred[wid] = m;
    }
    __syncthreads();
    if (t == 0) {
        float mm = sred[0];
#pragma unroll
        for (int w = 1; w < 8; w++) mm = fmaxf(mm, sred[w]);
        atomicMax(&g_f2maxU[h], fenc(mm));
    }
    {
        int d = t >> 1, n0 = (t & 1) * 64;
        size_t base = ((size_t)h * ND + d) * NN + i0 + n0;
#pragma unroll
        for (int c = 0; c < 8; c++) {
            uint32_t hp[4];
#pragma unroll
            for (int q = 0; q < 8; q += 2) {
                int n = c * 8 + q;
                F16X2(hp[q >> 1], Cst[(n0 + n) * CSTR + d], Cst[(n0 + n + 1) * CSTR + d]);
            }
            *(uint4*)(g_VT + base + c * 8) = *(uint4*)hp;
        }
    }
}

// ---------------- K4: single-product fp16 aggregation, 2 barriers/tile -----
#define PSTR 272u
#define A1_FBD 1024u         // float4[2][128] = 4096 B
#define A1_PHI 5120u
#define A1_V   39936u
#define SMEM_A1 74752
__global__ __launch_bounds__(256, 2) void k_attn1() {
    extern __shared__ char smem[];
    uint32_t sb = s2u(smem);
    int t = threadIdx.x, lane = t & 31, wid = t >> 5;
    int h = blockIdx.y, i0 = blockIdx.x * 128;
    int wm = wid & 3, wn = wid >> 2;
    float* dens = (float*)smem;
    float4* fBD = (float4*)(smem + A1_FBD);   // [2][128]

    int row = t & 127, jh64 = (t >> 7) * 64;
    float f1r = g_f1[h * NN + i0 + row];
    float sh = lrelu(f1r + fdec(g_f2maxU[h]));
    float Arow = __expf(f1r - sh);
    float Crow = __expf(LALPHA * f1r - sh);
    float dacc = 0.f;

    float acc[2][8][4];
#pragma unroll
    for (int mt = 0; mt < 2; mt++)
#pragma unroll
        for (int nt = 0; nt < 8; nt++)
#pragma unroll
            for (int q = 0; q < 4; q++) acc[mt][nt][q] = 0.f;

    uint32_t aAddrH = sb + A1_PHI + (uint32_t)(wm * 32 + (lane & 15)) * PSTR + (uint32_t)(lane >> 4) * 16u;
    int brow = ((lane >> 4) << 3) + (lane & 7);
    uint32_t bAddr0 = sb + A1_V + (uint32_t)(wn * 64 + brow) * PSTR + (uint32_t)((lane >> 3) & 1) * 16u;

    const float* f2p = g_f2 + h * NN;
    const unsigned* mrow = g_mask + (size_t)(i0 + row) * NW + (jh64 >> 5);
    if (t < 128) {
        float v = f2p[t];
        fBD[t] = make_float4(v, __expf(v), __expf(LALPHA * v), 0.f);
    }
    float pv2 = (t < 128) ? f2p[128 + t] : 0.f;   // f2 for tile jt+1
    uint2 pm = *(const uint2*)mrow;
    __syncthreads();

    for (int jt = 0; jt < 32; jt++) {
        int j0 = jt * 128;
        int cur = (jt & 1) * 128;
        // stage V via cp.async
#pragma unroll
        for (int c = 0; c < 9; c++) {
            int idx = c * 256 + t;
            if (idx < 2176) {
                int r = idx / 17, ch = idx - r * 17;
                CP16(sb + A1_V + (uint32_t)r * PSTR + (uint32_t)ch * 16u,
                     g_VT + ((size_t)(h * ND + r)) * NN + j0 + ch * 8);
            }
        }
        uint64_t m64 = ((uint64_t)pm.y << 32) | pm.x;
#pragma unroll
        for (int g = 0; g < 8; g++) {
            uint32_t ph[4];
#pragma unroll
            for (int q = 0; q < 8; q += 2) {
                int c = g * 8 + q;
                float4 q0 = fBD[cur + jh64 + c];
                float4 q1 = fBD[cur + jh64 + c + 1];
                float s0 = f1r + q0.x, s1 = f1r + q1.x;
                float w0 = ((m64 >> c) & 1)       ? (s0 > 0.f ? Arow * q0.y : Crow * q0.z) : 0.f;
                float w1 = ((m64 >> (c + 1)) & 1) ? (s1 > 0.f ? Arow * q1.y : Crow * q1.z) : 0.f;
                dacc += w0 + w1;
                F16X2(ph[q >> 1], w0, w1);
            }
            uint32_t o = (uint32_t)row * PSTR + (uint32_t)(jh64 + g * 8) * 2u;
            *(uint4*)(smem + A1_PHI + o) = *(uint4*)ph;
        }
        if (jt < 31) {
            if (t < 128)
                fBD[(cur ^ 128) + t] = make_float4(pv2, __expf(pv2), __expf(LALPHA * pv2), 0.f);
            if (jt < 30 && t < 128) pv2 = f2p[j0 + 256 + t];
            pm = *(const uint2*)(mrow + (jt + 1) * 4);
        }
        CPWAITALL();
        __syncthreads();
#pragma unroll
        for (int ks = 0; ks < 8; ks++) {
            uint32_t ah[2][4];
#pragma unroll
            for (int mt = 0; mt < 2; mt++)
                LDSM4(ah[mt], aAddrH + (uint32_t)mt * (16u * PSTR) + (uint32_t)ks * 32u);
#pragma unroll
            for (int p = 0; p < 4; p++) {
                uint32_t bb[4];
                LDSM4(bb, bAddr0 + (uint32_t)p * (16u * PSTR) + (uint32_t)ks * 32u);
#pragma unroll
                for (int mt = 0; mt < 2; mt++) {
                    MMA_F16(acc[mt][2 * p],     ah[mt], bb[0], bb[1]);
                    MMA_F16(acc[mt][2 * p + 1], ah[mt], bb[2], bb[3]);
                }
            }
        }
        __syncthreads();
    }
    dens[t] = dacc;
    __syncthreads();
#pragma unroll
    for (int mt = 0; mt < 2; mt++) {
        int rl = wm * 32 + mt * 16 + (lane >> 2);
        float inv0 = 1.f / (dens[rl] + dens[128 + rl]);
        float inv1 = 1.f / (dens[rl + 8] + dens[128 + rl + 8]);
        __half* d0 = g_hcat + (size_t)(i0 + rl) * HD + h * ND + wn * 64 + (lane & 3) * 2;
        __half* d1 = d0 + (size_t)8 * HD;
#pragma unroll
        for (int nt = 0; nt < 8; nt++) {
            float z0 = acc[mt][nt][0] * inv0, z1 = acc[mt][nt][1] * inv0;
            float z2 = acc[mt][nt][2] * inv1, z3 = acc[mt][nt][3] * inv1;
            z0 = z0 > 0.f ? z0 : (__expf(z0) - 1.f);
            z1 = z1 > 0.f ? z1 : (__expf(z1) - 1.f);
            z2 = z2 > 0.f ? z2 : (__expf(z2) - 1.f);
            z3 = z3 > 0.f ? z3 : (__expf(z3) - 1.f);
            uint32_t u0, u1;
            F16X2(u0, z0, z1);
            F16X2(u1, z2, z3);
            *(uint32_t*)(d0 + nt * 8) = u0;
            *(uint32_t*)(d1 + nt * 8) = u1;
        }
    }
}

// ---------------- K5: Who partials, split-K (64x64 tiles, KC chunks) -------
__global__ __launch_bounds__(256) void k_who(const float* __restrict__ Wo) {
    __shared__ float As[16][68];
    __shared__ float Bs[16][64];
    int i0 = blockIdx.x * 64, kc = blockIdx.y;
    int t = threadIdx.x, ty = t >> 4, tx = t & 15;
    float acc[4][4];
#pragma unroll
    for (int u = 0; u < 4; u++)
#pragma unroll
        for (int v = 0; v < 4; v++) acc[u][v] = 0.f;
    int fbeg = kc * (HD / KC);
    for (int f0 = fbeg; f0 < fbeg + HD / KC; f0 += 16) {
        {
            int r = t >> 2, k4 = (t & 3) * 4;
            uint2 u = *(const uint2*)(g_hcat + (size_t)(i0 + r) * HD + f0 + k4);
            __half2 p01 = *(__half2*)&u.x, p23 = *(__half2*)&u.y;
            As[k4 + 0][r] = __low2float(p01); As[k4 + 1][r] = __high2float(p01);
            As[k4 + 2][r] = __low2float(p23); As[k4 + 3][r] = __high2float(p23);
        }
        {
            int kk = t >> 4, d4 = (t & 15) * 4;
            *(float4*)&Bs[kk][d4] = *(const float4*)(Wo + (size_t)(f0 + kk) * NC + d4);
        }
        __syncthreads();
#pragma unroll
        for (int k = 0; k < 16; k++) {
            float ra[4], rb[4];
            *(float4*)ra = *(float4*)&As[k][ty * 4];
            *(float4*)rb = *(float4*)&Bs[k][tx * 4];
#pragma unroll
            for (int u = 0; u < 4; u++)
#pragma unroll
                for (int v = 0; v < 4; v++) acc[u][v] = fmaf(ra[u], rb[v], acc[u][v]);
        }
        __syncthreads();
    }
#pragma unroll
    for (int u = 0; u < 4; u++)
        *(float4*)(g_part + ((size_t)kc * NN + i0 + ty * 4 + u) * NC + tx * 4) = *(float4*)&acc[u][0];
}

// ---------------- K6: combine Who partials; g1,g2; Who^T fp16; gmax --------
__global__ void k_g(const float* __restrict__ ao1, const float* __restrict__ ao2) {
    __shared__ float red[8];
    __shared__ float sw[8][64];
    int warp = threadIdx.x >> 5, lane = threadIdx.x & 31;
    int n0 = blockIdx.x * 8;
    int n = n0 + warp;
    float v0 = 0.f, v1 = 0.f;
#pragma unroll
    for (int kc = 0; kc < KC; kc++) {
        size_t base = ((size_t)kc * NN + n) * NC;
        v0 += g_part[base + lane];
        v1 += g_part[base + lane + 32];
    }
    sw[warp][lane] = v0;
    sw[warp][lane + 32] = v1;
    float s1 = fmaf(v0, ao1[lane], v1 * ao1[lane + 32]);
    float s2 = fmaf(v0, ao2[lane], v1 * ao2[lane + 32]);
#pragma unroll
    for (int o = 16; o; o >>= 1) {
        s1 += __shfl_xor_sync(0xffffffffu, s1, o);
        s2 += __shfl_xor_sync(0xffffffffu, s2, o);
    }
    if (lane == 0) { g_g1[n] = s1; g_g2[n] = s2; red[warp] = s2; }
    __syncthreads();
    if (threadIdx.x < 64) {
        int c = threadIdx.x;
        uint32_t hp[4];
#pragma unroll
        for (int q = 0; q < 8; q += 2)
            F16X2(hp[q >> 1], sw[q][c], sw[q + 1][c]);
        *(uint4*)(g_WhoT + (size_t)c * NN + n0) = *(uint4*)hp;
    }
    if (threadIdx.x == 0) {
        float mm = red[0];
#pragma unroll
        for (int w = 1; w < 8; w++) mm = fmaxf(mm, red[w]);
        atomicMax(&g_gmaxU[0], fenc(mm));
    }
}

// ---------------- K7: output attention, single-product fp16 HMMA -----------
#define A2_FBD 1024u         // float4[2][128]
#define A2_PHI 5120u
#define A2_B   39936u
#define SMEM_A2 57344
__global__ __launch_bounds__(256, 2) void k_attn2() {
    extern __shared__ char smem[];
    uint32_t sb = s2u(smem);
    int t = threadIdx.x, lane = t & 31, wid = t >> 5;
    int jcc = blockIdx.y, i0 = blockIdx.x * 128;
    int wm = wid & 3, wn = wid >> 2;
    float* dens = (float*)smem;
    float4* fBD = (float4*)(smem + A2_FBD);

    int row = t & 127, jh64 = (t >> 7) * 64;
    float g1r = g_g1[i0 + row];
    float sh = lrelu(g1r + fdec(g_gmaxU[0]));
    float Arow = __expf(g1r - sh);
    float Crow = __expf(LALPHA * g1r - sh);
    float dacc = 0.f;

    float acc[2][4][4];
#pragma unroll
    for (int mt = 0; mt < 2; mt++)
#pragma unroll
        for (int nt = 0; nt < 4; nt++)
#pragma unroll
            for (int q = 0; q < 4; q++) acc[mt][nt][q] = 0.f;

    uint32_t aAddrH = sb + A2_PHI + (uint32_t)(wm * 32 + (lane & 15)) * PSTR + (uint32_t)(lane >> 4) * 16u;
    int brow = ((lane >> 4) << 3) + (lane & 7);
    uint32_t bAddr0 = sb + A2_B + (uint32_t)(wn * 32 + brow) * PSTR + (uint32_t)((lane >> 3) & 1) * 16u;

    const unsigned* mrow = g_mask + (size_t)(i0 + row) * NW + (jh64 >> 5);
    int jt0 = jcc * 4;
    if (t < 128) {
        float v = g_g2[jt0 * 128 + t];
        fBD[t] = make_float4(v, __expf(v), __expf(LALPHA * v), 0.f);
    }
    float pv2 = (t < 128) ? g_g2[jt0 * 128 + 128 + t] : 0.f;
    uint2 pm = *(const uint2*)(mrow + jt0 * 4);
    __syncthreads();

    for (int jj = 0; jj < 4; jj++) {
        int jt = jt0 + jj, j0 = jt * 128;
        int cur = (jj & 1) * 128;
#pragma unroll
        for (int c = 0; c < 5; c++) {
            int idx = c * 256 + t;
            if (idx < 1088) {
                int r = idx / 17, ch = idx - r * 17;
                CP16(sb + A2_B + (uint32_t)r * PSTR + (uint32_t)ch * 16u,
                     g_WhoT + (size_t)r * NN + j0 + ch * 8);
            }
        }
        uint64_t m64 = ((uint64_t)pm.y << 32) | pm.x;
#pragma unroll
        for (int g = 0; g < 8; g++) {
            uint32_t ph[4];
#pragma unroll
            for (int q = 0; q < 8; q += 2) {
                int c = g * 8 + q;
                float4 q0 = fBD[cur + jh64 + c];
                float4 q1 = fBD[cur + jh64 + c + 1];
                float s0 = g1r + q0.x, s1 = g1r + q1.x;
                float w0 = ((m64 >> c) & 1)       ? (s0 > 0.f ? Arow * q0.y : Crow * q0.z) : 0.f;
                float w1 = ((m64 >> (c + 1)) & 1) ? (s1 > 0.f ? Arow * q1.y : Crow * q1.z) : 0.f;
                dacc += w0 + w1;
                F16X2(ph[q >> 1], w0, w1);
            }
            uint32_t o = (uint32_t)row * PSTR + (uint32_t)(jh64 + g * 8) * 2u;
            *(uint4*)(smem + A2_PHI + o) = *(uint4*)ph;
        }
        if (jj < 3) {
            if (t < 128)
                fBD[(cur ^ 128) + t] = make_float4(pv2, __expf(pv2), __expf(LALPHA * pv2), 0.f);
            if (jj < 2 && t < 128) pv2 = g_g2[j0 + 256 + t];
            pm = *(const uint2*)(mrow + (jt + 1) * 4);
        }
        CPWAITALL();
        __syncthreads();
#pragma unroll
        for (int ks = 0; ks < 8; ks++) {
            uint32_t ah[2][4];
#pragma unroll
            for (int mt = 0; mt < 2; mt++)
                LDSM4(ah[mt], aAddrH + (uint32_t)mt * (16u * PSTR) + (uint32_t)ks * 32u);
#pragma unroll
            for (int p = 0; p < 2; p++) {
                uint32_t bb[4];
                LDSM4(bb, bAddr0 + (uint32_t)p * (16u * PSTR) + (uint32_t)ks * 32u);
#pragma unroll
                for (int mt = 0; mt < 2; mt++) {
                    MMA_F16(acc[mt][2 * p],     ah[mt], bb[0], bb[1]);
                    MMA_F16(acc[mt][2 * p + 1], ah[mt], bb[2], bb[3]);
                }
            }
        }
        __syncthreads();
    }
    dens[t] = dacc;
    __syncthreads();
#pragma unroll
    for (int mt = 0; mt < 2; mt++) {
        int rl = wm * 32 + mt * 16 + (lane >> 2);
        int cl = wn * 32 + (lane & 3) * 2;
#pragma unroll
        for (int nt = 0; nt < 4; nt++) {
            size_t b0 = ((size_t)jcc * NN + i0 + rl) * NC + cl + nt * 8;
            *(float2*)(g_part + b0)                  = *(float2*)&acc[mt][nt][0];
            *(float2*)(g_part + b0 + (size_t)8 * NC) = *(float2*)&acc[mt][nt][2];
        }
    }
    if (t < 128) g_dpart[jcc * NN + i0 + t] = dens[t] + dens[128 + t];
}

// ---------------- K8: combine partials + elu + log_softmax ----------------
__global__ void k_final(float* __restrict__ out) {
    int warp = threadIdx.x >> 5, lane = threadIdx.x & 31;
    int n = blockIdx.x * 8 + warp;
    float den = 0.f;
#pragma unroll
    for (int jc = 0; jc < JCC; jc++) den += g_dpart[jc * NN + n];
    float inv = 1.f / den;
    float v0 = 0.f, v1 = 0.f;
#pragma unroll
    for (int jc = 0; jc < JCC; jc++) {
        size_t base = ((size_t)jc * NN + n) * NC;
        v0 += g_part[base + lane];
        v1 += g_part[base + lane + 32];
    }
    v0 *= inv; v1 *= inv;
    v0 = v0 > 0.f ? v0 : (expf(v0) - 1.f);
    v1 = v1 > 0.f ? v1 : (expf(v1) - 1.f);
    float m = fmaxf(v0, v1);
#pragma unroll
    for (int o = 16; o; o >>= 1) m = fmaxf(m, __shfl_xor_sync(0xffffffffu, m, o));
    float s = expf(v0 - m) + expf(v1 - m);
#pragma unroll
    for (int o = 16; o; o >>= 1) s += __shfl_xor_sync(0xffffffffu, s, o);
    float lse = m + logf(s);
    out[(size_t)n * NC + lane] = v0 - lse;
    out[(size_t)n * NC + lane + 32] = v1 - lse;
}

// ---------------- launch ----------------
extern "C" void kernel_launch(void* const* d_in, const int* in_sizes, int n_in,
                              void* d_out, int out_size) {
    const float* x   = (const float*)d_in[0];
    const int*   adj = (const int*)d_in[1];
    const float* W   = (const float*)d_in[2];
    const float* a1  = (const float*)d_in[3];
    const float* a2  = (const float*)d_in[4];
    const float* Wo  = (const float*)d_in[5];
    const float* ao1 = (const float*)d_in[6];
    const float* ao2 = (const float*)d_in[7];
    float* out = (float*)d_out;

    cudaFuncSetAttribute(k_wh, cudaFuncAttributeMaxDynamicSharedMemorySize, SMEM_WH);
    cudaFuncSetAttribute(k_attn1, cudaFuncAttributeMaxDynamicSharedMemorySize, SMEM_A1);
    cudaFuncSetAttribute(k_attn2, cudaFuncAttributeMaxDynamicSharedMemorySize, SMEM_A2);

    k_pack  <<<NN, 128>>>(adj);
    k_splitx<<<(NN * NF / 4) / 256, 256>>>(x);
    k_splitw<<<dim3(NF / 32, ND / 32, NH), 256>>>(W);
    k_wh    <<<dim3(NN / 128, NH), 256, SMEM_WH>>>(a1, a2);
    k_attn1 <<<dim3(NN / 128, NH), 256, SMEM_A1>>>();
    k_who   <<<dim3(NN / 64, KC), 256>>>(Wo);
    k_g     <<<NN / 8, 256>>>(ao1, ao2);
    k_attn2 <<<dim3(NN / 128, JCC), 256, SMEM_A2>>>();
    k_final <<<NN / 8, 256>>>(out);
}

// round 16
// speedup vs baseline: 5.1492x; 1.0015x over previous
#include <cuda_runtime.h>
#include <cuda_fp16.h>
#include <math.h>
#include <stdint.h>

#define NN 4096
#define NF 1024
#define NH 8
#define ND 128
#define NC 64
#define HD (NH*ND)      // 1024
#define NW (NN/32)      // 128 mask words per row
#define LALPHA 0.2f
#define KC 4            // split-K chunks for k_who
#define JCC 8           // j-split chunks for output attention layer

// ---------------- scratch (static device globals; no allocs) ----------------
__device__ unsigned g_mask[(size_t)NN*NW];         // 2 MB packed adjacency
__device__ __half g_VT[(size_t)NH*ND*NN];          // 8 MB  Wh^T fp16 [h][d][n]
__device__ __half g_xhi[(size_t)NN*NF];            // 8 MB  x fp16
__device__ __half g_WT[(size_t)NH*ND*NF];          // 2 MB  W^T fp16 [h][d][f]
__device__ float g_f1[NH*NN];
__device__ float g_f2[NH*NN];
__device__ unsigned g_f2maxU[NH];
__device__ __half g_hcat[(size_t)NN*HD];           // 8 MB  elu(h) concat, fp16
__device__ __half g_WhoT[(size_t)NC*NN];           // 512 KB Who^T fp16 [c][n]
__device__ float g_g1[NN];
__device__ float g_g2[NN];
__device__ unsigned g_gmaxU[1];
__device__ float g_part[(size_t)JCC*NN*NC];        // 8 MB partials (who & attn2)
__device__ float g_dpart[JCC*NN];                  // partial denominators

__device__ __forceinline__ float lrelu(float s) { return s > 0.f ? s : LALPHA * s; }

// monotone float<->uint for atomicMax over signed floats
__device__ __forceinline__ unsigned fenc(float f) {
    unsigned b = __float_as_uint(f);
    return (b & 0x80000000u) ? ~b : (b | 0x80000000u);
}
__device__ __forceinline__ float fdec(unsigned k) {
    unsigned b = (k & 0x80000000u) ? (k ^ 0x80000000u) : ~k;
    return __uint_as_float(b);
}

__device__ __forceinline__ uint32_t s2u(const void* p) {
    uint32_t a;
    asm("{ .reg .u64 t; cvta.to.shared.u64 t, %1; cvt.u32.u64 %0, t; }" : "=r"(a) : "l"(p));
    return a;
}

#define LDSM4(r, addr) \
    asm volatile("ldmatrix.sync.aligned.m8n8.x4.shared.b16 {%0,%1,%2,%3}, [%4];" \
        : "=r"((r)[0]), "=r"((r)[1]), "=r"((r)[2]), "=r"((r)[3]) : "r"(addr))

#define MMA_F16(c, a, b0, b1) \
    asm volatile("mma.sync.aligned.m16n8k16.row.col.f32.f16.f16.f32 " \
        "{%0,%1,%2,%3}, {%4,%5,%6,%7}, {%8,%9}, {%0,%1,%2,%3};" \
        : "+f"((c)[0]), "+f"((c)[1]), "+f"((c)[2]), "+f"((c)[3]) \
        : "r"((a)[0]), "r"((a)[1]), "r"((a)[2]), "r"((a)[3]), "r"(b0), "r"(b1))

#define CP16(dst, src) \
    asm volatile("cp.async.cg.shared.global [%0], [%1], 16;" :: "r"(dst), "l"(src))
#define CPCOMMIT() asm volatile("cp.async.commit_group;" ::: "memory")
#define CPWAITALL() asm volatile("cp.async.wait_all;" ::: "memory")

// pack two floats to half2: lo=w0, hi=w1
#define F16X2(d, w0, w1) \
    asm("cvt.rn.f16x2.f32 %0, %1, %2;" : "=r"(d) : "f"(w1), "f"(w0))

// ---------------- K1: fused prep: pack adj / x->fp16 / W->W^T fp16 ---------
__global__ void k_prep(const int* __restrict__ adj, const float* __restrict__ x,
                       const float* __restrict__ W) {
    __shared__ float ts[32][33];
    int b = blockIdx.x, t = threadIdx.x;
    if (b < NN) {
        // pack row b (+ init atomic-max cells)
        int warp = t >> 5, lane = t & 31;
        if (b == 0 && t < NH + 1) {
            if (t < NH) g_f2maxU[t] = 0u;
            else g_gmaxU[0] = 0u;
        }
        const int* ar = adj + (size_t)b * NN;
        for (int w = warp; w < NW; w += 8) {
            unsigned bb = __ballot_sync(0xffffffffu, ar[w * 32 + lane] > 0);
            if (lane == 0) g_mask[(size_t)b * NW + w] = bb;
        }
    } else if (b < 2 * NN) {
        // x -> fp16, one float4 per thread
        int i = (b - NN) * 256 + t;
        float4 v = *(const float4*)(x + (size_t)i * 4);
        uint2 ho;
        F16X2(ho.x, v.x, v.y);
        F16X2(ho.y, v.z, v.w);
        *(uint2*)(g_xhi + (size_t)i * 4) = ho;
    } else {
        // W -> W^T fp16, 32x32 tile
        int idx = b - 2 * NN;
        int f0 = (idx & 31) * 32;
        int d0 = ((idx >> 5) & 3) * 32;
        int h = idx >> 7;
        int r = t >> 3, c4 = (t & 7) * 4;
        float4 v = *(const float4*)(W + ((size_t)h * NF + f0 + r) * ND + d0 + c4);
        ts[r][c4] = v.x; ts[r][c4 + 1] = v.y; ts[r][c4 + 2] = v.z; ts[r][c4 + 3] = v.w;
        __syncthreads();
        int rr = t >> 3, cc = (t & 7) * 4;
        uint2 hp;
        F16X2(hp.x, ts[cc][rr], ts[cc + 1][rr]);
        F16X2(hp.y, ts[cc + 2][rr], ts[cc + 3][rr]);
        *(uint2*)(g_WT + ((size_t)h * ND + d0 + rr) * NF + f0 + cc) = hp;
    }
}

// ---------------- K2: Wh = x @ W, fp16 1-prod, cp.async double-buffered ----
#define WSTR 144u
#define STAGE 36864u         // A@0, B@18432 (per stage)
#define CSTR 130
#define SM_A1  73728
#define SM_A2  74240
#define SM_RED 74752
#define SMEM_WH 74784
__global__ __launch_bounds__(256, 2) void k_wh(const float* __restrict__ a1,
                                               const float* __restrict__ a2) {
    extern __shared__ char smem[];
    uint32_t sb = s2u(smem);
    int t = threadIdx.x, lane = t & 31, wid = t >> 5;
    int h = blockIdx.y, i0 = blockIdx.x * 128;
    int wm = wid & 3, wn = wid >> 2;
    float* a1s = (float*)(smem + SM_A1);
    float* a2s = (float*)(smem + SM_A2);
    float* sred = (float*)(smem + SM_RED);
    if (t < ND) { a1s[t] = a1[h * ND + t]; a2s[t] = a2[h * ND + t]; }

    float acc[2][8][4];
#pragma unroll
    for (int mt = 0; mt < 2; mt++)
#pragma unroll
        for (int nt = 0; nt < 8; nt++)
#pragma unroll
            for (int q = 0; q < 4; q++) acc[mt][nt][q] = 0.f;

    uint32_t aBase = sb + (uint32_t)(wm * 32 + (lane & 15)) * WSTR + (uint32_t)(lane >> 4) * 16u;
    int brow = ((lane >> 4) << 3) + (lane & 7);
    uint32_t bBase = sb + 18432u + (uint32_t)(wn * 64 + brow) * WSTR + (uint32_t)((lane >> 3) & 1) * 16u;

    int srow = t >> 3, sch = (t & 7) * 8;
    uint32_t so0 = (uint32_t)srow * WSTR + (uint32_t)sch * 2u;

    {
        uint32_t s0 = sb;
#pragma unroll
        for (int c = 0; c < 4; c++) {
            uint32_t o = so0 + (uint32_t)c * (32u * WSTR);
            size_t ga = (size_t)(i0 + c * 32 + srow) * NF + sch;
            size_t gb = ((size_t)h * ND + c * 32 + srow) * NF + sch;
            CP16(s0 + o,          g_xhi + ga);
            CP16(s0 + 18432u + o, g_WT + gb);
        }
        CPCOMMIT();
    }
    for (int kt = 0; kt < 16; kt++) {
        uint32_t buf = (uint32_t)(kt & 1) * STAGE;
        if (kt < 15) {
            uint32_t s0 = sb + (uint32_t)((kt + 1) & 1) * STAGE;
            int f0 = (kt + 1) * 64;
#pragma unroll
            for (int c = 0; c < 4; c++) {
                uint32_t o = so0 + (uint32_t)c * (32u * WSTR);
                size_t ga = (size_t)(i0 + c * 32 + srow) * NF + f0 + sch;
                size_t gb = ((size_t)h * ND + c * 32 + srow) * NF + f0 + sch;
                CP16(s0 + o,          g_xhi + ga);
                CP16(s0 + 18432u + o, g_WT + gb);
            }
            CPCOMMIT();
            asm volatile("cp.async.wait_group 1;" ::: "memory");
        } else {
            asm volatile("cp.async.wait_group 0;" ::: "memory");
        }
        __syncthreads();
#pragma unroll
        for (int ks = 0; ks < 4; ks++) {
            uint32_t ah[2][4];
#pragma unroll
            for (int mt = 0; mt < 2; mt++)
                LDSM4(ah[mt], aBase + buf + (uint32_t)mt * (16u * WSTR) + (uint32_t)ks * 32u);
#pragma unroll
            for (int p = 0; p < 4; p++) {
                uint32_t bb[4];
                LDSM4(bb, bBase + buf + (uint32_t)p * (16u * WSTR) + (uint32_t)ks * 32u);
#pragma unroll
                for (int mt = 0; mt < 2; mt++) {
                    MMA_F16(acc[mt][2 * p],     ah[mt], bb[0], bb[1]);
                    MMA_F16(acc[mt][2 * p + 1], ah[mt], bb[2], bb[3]);
                }
            }
        }
        __syncthreads();
    }
    float* Cst = (float*)smem;
#pragma unroll
    for (int mt = 0; mt < 2; mt++) {
#pragma unroll
        for (int nt = 0; nt < 8; nt++) {
            int rl = wm * 32 + mt * 16 + (lane >> 2);
            int cl = wn * 64 + nt * 8 + (lane & 3) * 2;
            *(float2*)(Cst + rl * CSTR + cl)       = *(float2*)&acc[mt][nt][0];
            *(float2*)(Cst + (rl + 8) * CSTR + cl) = *(float2*)&acc[mt][nt][2];
        }
    }
    __syncthreads();
    {
        int r = t >> 1, half = (t & 1) * 64;
        float p1 = 0.f, p2 = 0.f;
#pragma unroll
        for (int d = 0; d < 64; d++) {
            float v = Cst[r * CSTR + half + d];
            p1 = fmaf(v, a1s[half + d], p1);
            p2 = fmaf(v, a2s[half + d], p2);
        }
        p1 += __shfl_xor_sync(0xffffffffu, p1, 1);
        p2 += __shfl_xor_sync(0xffffffffu, p2, 1);
        if (!(t & 1)) {
            g_f1[h * NN + i0 + r] = p1;
            g_f2[h * NN + i0 + r] = p2;
        }
        float m = p2;
#pragma unroll
        for (int o = 16; o; o >>= 1) m = fmaxf(m, __shfl_xor_sync(0xffffffffu, m, o));
        if (lane == 0) sred[wid] = m;
    }
    __syncthreads();
    if (t == 0) {
        float mm = sred[0];
#pragma unroll
        for (int w = 1; w < 8; w++) mm = fmaxf(mm, sred[w]);
        atomicMax(&g_f2maxU[h], fenc(mm));
    }
    {
        int d = t >> 1, n0 = (t & 1) * 64;
        size_t base = ((size_t)h * ND + d) * NN + i0 + n0;
#pragma unroll
        for (int c = 0; c < 8; c++) {
            uint32_t hp[4];
#pragma unroll
            for (int q = 0; q < 8; q += 2) {
                int n = c * 8 + q;
                F16X2(hp[q >> 1], Cst[(n0 + n) * CSTR + d], Cst[(n0 + n + 1) * CSTR + d]);
            }
            *(uint4*)(g_VT + base + c * 8) = *(uint4*)hp;
        }
    }
}

// ---------------- K4: fp16 aggregation; P = mask & max(A*B, C*D) -----------
// lrelu(s) = max(s, alpha*s); exp monotone => exp(lrelu(f1+f2)-sh) =
// max(exp(f1-sh)*exp(f2), exp(a*f1-sh)*exp(a*f2)). fBD holds (B,D) pairs.
#define PSTR 272u
#define A1_FBD 1024u         // float4[2][64] = 2048 B
#define A1_PHI 3072u
#define A1_V   37888u
#define SMEM_A1 72704
__global__ __launch_bounds__(256, 2) void k_attn1() {
    extern __shared__ char smem[];
    uint32_t sb = s2u(smem);
    int t = threadIdx.x, lane = t & 31, wid = t >> 5;
    int h = blockIdx.y, i0 = blockIdx.x * 128;
    int wm = wid & 3, wn = wid >> 2;
    float* dens = (float*)smem;
    float4* fBD = (float4*)(smem + A1_FBD);   // [2][64] of {B0,D0,B1,D1}

    int row = t & 127, jh64 = (t >> 7) * 64;
    float f1r = g_f1[h * NN + i0 + row];
    float sh = lrelu(f1r + fdec(g_f2maxU[h]));
    float Arow = __expf(f1r - sh);
    float Crow = __expf(LALPHA * f1r - sh);
    float dacc = 0.f;

    float acc[2][8][4];
#pragma unroll
    for (int mt = 0; mt < 2; mt++)
#pragma unroll
        for (int nt = 0; nt < 8; nt++)
#pragma unroll
            for (int q = 0; q < 4; q++) acc[mt][nt][q] = 0.f;

    uint32_t aAddrH = sb + A1_PHI + (uint32_t)(wm * 32 + (lane & 15)) * PSTR + (uint32_t)(lane >> 4) * 16u;
    int brow = ((lane >> 4) << 3) + (lane & 7);
    uint32_t bAddr0 = sb + A1_V + (uint32_t)(wn * 64 + brow) * PSTR + (uint32_t)((lane >> 3) & 1) * 16u;

    const float* f2p = g_f2 + h * NN;
    const unsigned* mrow = g_mask + (size_t)(i0 + row) * NW + (jh64 >> 5);
    if (t < 64) {
        float2 v = *(const float2*)(f2p + 2 * t);
        fBD[t] = make_float4(__expf(v.x), __expf(LALPHA * v.x),
                             __expf(v.y), __expf(LALPHA * v.y));
    }
    float2 pv2 = make_float2(0.f, 0.f);
    if (t < 64) pv2 = *(const float2*)(f2p + 128 + 2 * t);
    uint2 pm = *(const uint2*)mrow;
    __syncthreads();

    for (int jt = 0; jt < 32; jt++) {
        int j0 = jt * 128;
        int cur = (jt & 1) * 64;
        // stage V via cp.async
#pragma unroll
        for (int c = 0; c < 9; c++) {
            int idx = c * 256 + t;
            if (idx < 2176) {
                int r = idx / 17, ch = idx - r * 17;
                CP16(sb + A1_V + (uint32_t)r * PSTR + (uint32_t)ch * 16u,
                     g_VT + ((size_t)(h * ND + r)) * NN + j0 + ch * 8);
            }
        }
        int fb = cur + (jh64 >> 1);
#pragma unroll
        for (int g = 0; g < 8; g++) {
            uint32_t ph[4];
#pragma unroll
            for (int q = 0; q < 8; q += 2) {
                int c = g * 8 + q;
                float4 q01 = fBD[fb + (c >> 1)];
                float w0 = fmaxf(Arow * q01.x, Crow * q01.y);
                float w1 = fmaxf(Arow * q01.z, Crow * q01.w);
                uint32_t mword = (c < 32) ? pm.x : pm.y;
                uint32_t s0 = (uint32_t)((int)(mword << (31 - (c & 31))) >> 31);
                uint32_t s1 = (uint32_t)((int)(mword << (30 - (c & 31))) >> 31);
                w0 = __uint_as_float(__float_as_uint(w0) & s0);
                w1 = __uint_as_float(__float_as_uint(w1) & s1);
                dacc += w0 + w1;
                F16X2(ph[q >> 1], w0, w1);
            }
            uint32_t o = (uint32_t)row * PSTR + (uint32_t)(jh64 + g * 8) * 2u;
            *(uint4*)(smem + A1_PHI + o) = *(uint4*)ph;
        }
        if (jt < 31) {
            if (t < 64)
                fBD[(cur ^ 64) + t] = make_float4(__expf(pv2.x), __expf(LALPHA * pv2.x),
                                                  __expf(pv2.y), __expf(LALPHA * pv2.y));
            if (jt < 30 && t < 64) pv2 = *(const float2*)(f2p + j0 + 256 + 2 * t);
            pm = *(const uint2*)(mrow + (jt + 1) * 4);
        }
        CPWAITALL();
        __syncthreads();
#pragma unroll
        for (int ks = 0; ks < 8; ks++) {
            uint32_t ah[2][4];
#pragma unroll
            for (int mt = 0; mt < 2; mt++)
                LDSM4(ah[mt], aAddrH + (uint32_t)mt * (16u * PSTR) + (uint32_t)ks * 32u);
#pragma unroll
            for (int p = 0; p < 4; p++) {
                uint32_t bb[4];
                LDSM4(bb, bAddr0 + (uint32_t)p * (16u * PSTR) + (uint32_t)ks * 32u);
#pragma unroll
                for (int mt = 0; mt < 2; mt++) {
                    MMA_F16(acc[mt][2 * p],     ah[mt], bb[0], bb[1]);
                    MMA_F16(acc[mt][2 * p + 1], ah[mt], bb[2], bb[3]);
                }
            }
        }
        __syncthreads();
    }
    dens[t] = dacc;
    __syncthreads();
#pragma unroll
    for (int mt = 0; mt < 2; mt++) {
        int rl = wm * 32 + mt * 16 + (lane >> 2);
        float inv0 = 1.f / (dens[rl] + dens[128 + rl]);
        float inv1 = 1.f / (dens[rl + 8] + dens[128 + rl + 8]);
        __half* d0 = g_hcat + (size_t)(i0 + rl) * HD + h * ND + wn * 64 + (lane & 3) * 2;
        __half* d1 = d0 + (size_t)8 * HD;
#pragma unroll
        for (int nt = 0; nt < 8; nt++) {
            float z0 = acc[mt][nt][0] * inv0, z1 = acc[mt][nt][1] * inv0;
            float z2 = acc[mt][nt][2] * inv1, z3 = acc[mt][nt][3] * inv1;
            z0 = z0 > 0.f ? z0 : (__expf(z0) - 1.f);
            z1 = z1 > 0.f ? z1 : (__expf(z1) - 1.f);
            z2 = z2 > 0.f ? z2 : (__expf(z2) - 1.f);
            z3 = z3 > 0.f ? z3 : (__expf(z3) - 1.f);
            uint32_t u0, u1;
            F16X2(u0, z0, z1);
            F16X2(u1, z2, z3);
            *(uint32_t*)(d0 + nt * 8) = u0;
            *(uint32_t*)(d1 + nt * 8) = u1;
        }
    }
}

// ---------------- K5: Who partials, split-K (64x64 tiles, KC chunks) -------
__global__ __launch_bounds__(256) void k_who(const float* __restrict__ Wo) {
    __shared__ float As[16][68];
    __shared__ float Bs[16][64];
    int i0 = blockIdx.x * 64, kc = blockIdx.y;
    int t = threadIdx.x, ty = t >> 4, tx = t & 15;
    float acc[4][4];
#pragma unroll
    for (int u = 0; u < 4; u++)
#pragma unroll
        for (int v = 0; v < 4; v++) acc[u][v] = 0.f;
    int fbeg = kc * (HD / KC);
    for (int f0 = fbeg; f0 < fbeg + HD / KC; f0 += 16) {
        {
            int r = t >> 2, k4 = (t & 3) * 4;
            uint2 u = *(const uint2*)(g_hcat + (size_t)(i0 + r) * HD + f0 + k4);
            __half2 p01 = *(__half2*)&u.x, p23 = *(__half2*)&u.y;
            As[k4 + 0][r] = __low2float(p01); As[k4 + 1][r] = __high2float(p01);
            As[k4 + 2][r] = __low2float(p23); As[k4 + 3][r] = __high2float(p23);
        }
        {
            int kk = t >> 4, d4 = (t & 15) * 4;
            *(float4*)&Bs[kk][d4] = *(const float4*)(Wo + (size_t)(f0 + kk) * NC + d4);
        }
        __syncthreads();
#pragma unroll
        for (int k = 0; k < 16; k++) {
            float ra[4], rb[4];
            *(float4*)ra = *(float4*)&As[k][ty * 4];
            *(float4*)rb = *(float4*)&Bs[k][tx * 4];
#pragma unroll
            for (int u = 0; u < 4; u++)
#pragma unroll
                for (int v = 0; v < 4; v++) acc[u][v] = fmaf(ra[u], rb[v], acc[u][v]);
        }
        __syncthreads();
    }
#pragma unroll
    for (int u = 0; u < 4; u++)
        *(float4*)(g_part + ((size_t)kc * NN + i0 + ty * 4 + u) * NC + tx * 4) = *(float4*)&acc[u][0];
}

// ---------------- K6: combine Who partials; g1,g2; Who^T fp16; gmax --------
__global__ void k_g(const float* __restrict__ ao1, const float* __restrict__ ao2) {
    __shared__ float red[8];
    __shared__ float sw[8][64];
    int warp = threadIdx.x >> 5, lane = threadIdx.x & 31;
    int n0 = blockIdx.x * 8;
    int n = n0 + warp;
    float v0 = 0.f, v1 = 0.f;
#pragma unroll
    for (int kc = 0; kc < KC; kc++) {
        size_t base = ((size_t)kc * NN + n) * NC;
        v0 += g_part[base + lane];
        v1 += g_part[base + lane + 32];
    }
    sw[warp][lane] = v0;
    sw[warp][lane + 32] = v1;
    float s1 = fmaf(v0, ao1[lane], v1 * ao1[lane + 32]);
    float s2 = fmaf(v0, ao2[lane], v1 * ao2[lane + 32]);
#pragma unroll
    for (int o = 16; o; o >>= 1) {
        s1 += __shfl_xor_sync(0xffffffffu, s1, o);
        s2 += __shfl_xor_sync(0xffffffffu, s2, o);
    }
    if (lane == 0) { g_g1[n] = s1; g_g2[n] = s2; red[warp] = s2; }
    __syncthreads();
    if (threadIdx.x < 64) {
        int c = threadIdx.x;
        uint32_t hp[4];
#pragma unroll
        for (int q = 0; q < 8; q += 2)
            F16X2(hp[q >> 1], sw[q][c], sw[q + 1][c]);
        *(uint4*)(g_WhoT + (size_t)c * NN + n0) = *(uint4*)hp;
    }
    if (threadIdx.x == 0) {
        float mm = red[0];
#pragma unroll
        for (int w = 1; w < 8; w++) mm = fmaxf(mm, red[w]);
        atomicMax(&g_gmaxU[0], fenc(mm));
    }
}

// ---------------- K7: output attention, max-form P-gen, fp16 HMMA ----------
#define A2_FBD 1024u         // float4[2][64]
#define A2_PHI 3072u
#define A2_B   37888u
#define SMEM_A2 55296
__global__ __launch_bounds__(256, 2) void k_attn2() {
    extern __shared__ char smem[];
    uint32_t sb = s2u(smem);
    int t = threadIdx.x, lane = t & 31, wid = t >> 5;
    int jcc = blockIdx.y, i0 = blockIdx.x * 128;
    int wm = wid & 3, wn = wid >> 2;
    float* dens = (float*)smem;
    float4* fBD = (float4*)(smem + A2_FBD);

    int row = t & 127, jh64 = (t >> 7) * 64;
    float g1r = g_g1[i0 + row];
    float sh = lrelu(g1r + fdec(g_gmaxU[0]));
    float Arow = __expf(g1r - sh);
    float Crow = __expf(LALPHA * g1r - sh);
    float dacc = 0.f;

    float acc[2][4][4];
#pragma unroll
    for (int mt = 0; mt < 2; mt++)
#pragma unroll
        for (int nt = 0; nt < 4; nt++)
#pragma unroll
            for (int q = 0; q < 4; q++) acc[mt][nt][q] = 0.f;

    uint32_t aAddrH = sb + A2_PHI + (uint32_t)(wm * 32 + (lane & 15)) * PSTR + (uint32_t)(lane >> 4) * 16u;
    int brow = ((lane >> 4) << 3) + (lane & 7);
    uint32_t bAddr0 = sb + A2_B + (uint32_t)(wn * 32 + brow) * PSTR + (uint32_t)((lane >> 3) & 1) * 16u;

    const unsigned* mrow = g_mask + (size_t)(i0 + row) * NW + (jh64 >> 5);
    int jt0 = jcc * 4;
    if (t < 64) {
        float2 v = *(const float2*)(g_g2 + jt0 * 128 + 2 * t);
        fBD[t] = make_float4(__expf(v.x), __expf(LALPHA * v.x),
                             __expf(v.y), __expf(LALPHA * v.y));
    }
    float2 pv2 = make_float2(0.f, 0.f);
    if (t < 64) pv2 = *(const float2*)(g_g2 + jt0 * 128 + 128 + 2 * t);
    uint2 pm = *(const uint2*)(mrow + jt0 * 4);
    __syncthreads();

    for (int jj = 0; jj < 4; jj++) {
        int jt = jt0 + jj, j0 = jt * 128;
        int cur = (jj & 1) * 64;
#pragma unroll
        for (int c = 0; c < 5; c++) {
            int idx = c * 256 + t;
            if (idx < 1088) {
                int r = idx / 17, ch = idx - r * 17;
                CP16(sb + A2_B + (uint32_t)r * PSTR + (uint32_t)ch * 16u,
                     g_WhoT + (size_t)r * NN + j0 + ch * 8);
            }
        }
        int fb = cur + (jh64 >> 1);
        uint64_t unused = 0; (void)unused;
#pragma unroll
        for (int g = 0; g < 8; g++) {
            uint32_t ph[4];
#pragma unroll
            for (int q = 0; q < 8; q += 2) {
                int c = g * 8 + q;
                float4 q01 = fBD[fb + (c >> 1)];
                float w0 = fmaxf(Arow * q01.x, Crow * q01.y);
                float w1 = fmaxf(Arow * q01.z, Crow * q01.w);
                uint32_t mword = (c < 32) ? pm.x : pm.y;
                uint32_t s0 = (uint32_t)((int)(mword << (31 - (c & 31))) >> 31);
                uint32_t s1 = (uint32_t)((int)(mword << (30 - (c & 31))) >> 31);
                w0 = __uint_as_float(__float_as_uint(w0) & s0);
                w1 = __uint_as_float(__float_as_uint(w1) & s1);
                dacc += w0 + w1;
                F16X2(ph[q >> 1], w0, w1);
            }
            uint32_t o = (uint32_t)row * PSTR + (uint32_t)(jh64 + g * 8) * 2u;
            *(uint4*)(smem + A2_PHI + o) = *(uint4*)ph;
        }
        if (jj < 3) {
            if (t < 64)
                fBD[(cur ^ 64) + t] = make_float4(__expf(pv2.x), __expf(LALPHA * pv2.x),
                                                  __expf(pv2.y), __expf(LALPHA * pv2.y));
            if (jj < 2 && t < 64) pv2 = *(const float2*)(g_g2 + j0 + 256 + 2 * t);
            pm = *(const uint2*)(mrow + (jt + 1) * 4);
        }
        CPWAITALL();
        __syncthreads();
#pragma unroll
        for (int ks = 0; ks < 8; ks++) {
            uint32_t ah[2][4];
#pragma unroll
            for (int mt = 0; mt < 2; mt++)
                LDSM4(ah[mt], aAddrH + (uint32_t)mt * (16u * PSTR) + (uint32_t)ks * 32u);
#pragma unroll
            for (int p = 0; p < 2; p++) {
                uint32_t bb[4];
                LDSM4(bb, bAddr0 + (uint32_t)p * (16u * PSTR) + (uint32_t)ks * 32u);
#pragma unroll
                for (int mt = 0; mt < 2; mt++) {
                    MMA_F16(acc[mt][2 * p],     ah[mt], bb[0], bb[1]);
                    MMA_F16(acc[mt][2 * p + 1], ah[mt], bb[2], bb[3]);
                }
            }
        }
        __syncthreads();
    }
    dens[t] = dacc;
    __syncthreads();
#pragma unroll
    for (int mt = 0; mt < 2; mt++) {
        int rl = wm * 32 + mt * 16 + (lane >> 2);
        int cl = wn * 32 + (lane & 3) * 2;
#pragma unroll
        for (int nt = 0; nt < 4; nt++) {
            size_t b0 = ((size_t)jcc * NN + i0 + rl) * NC + cl + nt * 8;
            *(float2*)(g_part + b0)                  = *(float2*)&acc[mt][nt][0];
            *(float2*)(g_part + b0 + (size_t)8 * NC) = *(float2*)&acc[mt][nt][2];
        }
    }
    if (t < 128) g_dpart[jcc * NN + i0 + t] = dens[t] + dens[128 + t];
}

// ---------------- K8: combine partials + elu + log_softmax ----------------
__global__ void k_final(float* __restrict__ out) {
    int warp = threadIdx.x >> 5, lane = threadIdx.x & 31;
    int n = blockIdx.x * 8 + warp;
    float den = 0.f;
#pragma unroll
    for (int jc = 0; jc < JCC; jc++) den += g_dpart[jc * NN + n];
    float inv = 1.f / den;
    float v0 = 0.f, v1 = 0.f;
#pragma unroll
    for (int jc = 0; jc < JCC; jc++) {
        size_t base = ((size_t)jc * NN + n) * NC;
        v0 += g_part[base + lane];
        v1 += g_part[base + lane + 32];
    }
    v0 *= inv; v1 *= inv;
    v0 = v0 > 0.f ? v0 : (expf(v0) - 1.f);
    v1 = v1 > 0.f ? v1 : (expf(v1) - 1.f);
    float m = fmaxf(v0, v1);
#pragma unroll
    for (int o = 16; o; o >>= 1) m = fmaxf(m, __shfl_xor_sync(0xffffffffu, m, o));
    float s = expf(v0 - m) + expf(v1 - m);
#pragma unroll
    for (int o = 16; o; o >>= 1) s += __shfl_xor_sync(0xffffffffu, s, o);
    float lse = m + logf(s);
    out[(size_t)n * NC + lane] = v0 - lse;
    out[(size_t)n * NC + lane + 32] = v1 - lse;
}

// ---------------- launch ----------------
extern "C" void kernel_launch(void* const* d_in, const int* in_sizes, int n_in,
                              void* d_out, int out_size) {
    const float* x   = (const float*)d_in[0];
    const int*   adj = (const int*)d_in[1];
    const float* W   = (const float*)d_in[2];
    const float* a1  = (const float*)d_in[3];
    const float* a2  = (const float*)d_in[4];
    const float* Wo  = (const float*)d_in[5];
    const float* ao1 = (const float*)d_in[6];
    const float* ao2 = (const float*)d_in[7];
    float* out = (float*)d_out;

    cudaFuncSetAttribute(k_wh, cudaFuncAttributeMaxDynamicSharedMemorySize, SMEM_WH);
    cudaFuncSetAttribute(k_attn1, cudaFuncAttributeMaxDynamicSharedMemorySize, SMEM_A1);
    cudaFuncSetAttribute(k_attn2, cudaFuncAttributeMaxDynamicSharedMemorySize, SMEM_A2);

    k_prep  <<<2 * NN + 1024, 256>>>(adj, x, W);
    k_wh    <<<dim3(NN / 128, NH), 256, SMEM_WH>>>(a1, a2);
    k_attn1 <<<dim3(NN / 128, NH), 256, SMEM_A1>>>();
    k_who   <<<dim3(NN / 64, KC), 256>>>(Wo);
    k_g     <<<NN / 8, 256>>>(ao1, ao2);
    k_attn2 <<<dim3(NN / 128, JCC), 256, SMEM_A2>>>();
    k_final <<<NN / 8, 256>>>(out);
}